// round 8
// baseline (speedup 1.0000x reference)
#include <cuda_runtime.h>
#include <cuda_bf16.h>
#include <math.h>
#include <stdint.h>

#define IN_F   256
#define OUT_F  256
#define N_E    10000
#define N_KC   2000
#define ALPHA  0.2f

#define MT      32            // rows per attention block tile
#define KC      32            // j per K-chunk
#define NKC_PAD 2048
#define NCHUNK_RUN 63         // chunk 63 (j 2016..2047) is all padding -> skipped
#define RSTRIDE 80            // bytes per smem tile row (64B data + 16B pad)

typedef __nv_bfloat16 bf16;

// ---------------- scratch (static __device__, no allocation) ----------------
__device__ float g_kcWh[N_KC * OUT_F];
__device__ float g_exEh[N_E * OUT_F];
__device__ float g_e1[N_E];
__device__ float g_v1[IN_F];
__device__ float g_v2[IN_F];
__device__ bf16 g_kcWhT_hi[OUT_F * NKC_PAD];   // ((chunk*256 + n)*KC + j%KC)
__device__ bf16 g_kcWhT_lo[OUT_F * NKC_PAD];
__device__ float g_colmean[OUT_F];
__device__ float g_mkcp[8][IN_F];
__device__ float g_Ae[N_E];
__device__ float g_Ce[N_E];
__device__ float g_Bf[NKC_PAD];
__device__ float g_Df[NKC_PAD];
__device__ float g_e2p[NKC_PAD];
__device__ bf16 g_exhi[N_E * IN_F];
__device__ bf16 g_exlo[N_E * IN_F];
__device__ bf16 g_kchi[N_KC * IN_F];
__device__ bf16 g_kclo[N_KC * IN_F];
__device__ bf16 g_W1Thi[OUT_F * IN_F];
__device__ bf16 g_W1Tlo[OUT_F * IN_F];
__device__ bf16 g_EThi[OUT_F * IN_F];
__device__ bf16 g_ETlo[OUT_F * IN_F];
__device__ bf16 g_rdwhi[OUT_F * 2 * OUT_F];
__device__ bf16 g_rdwlo[OUT_F * 2 * OUT_F];
__device__ bf16 g_feathi[N_E * 2 * OUT_F];
__device__ bf16 g_featlo[N_E * 2 * OUT_F];

// ---------------- helpers ----------------
static __device__ __forceinline__ uint32_t smem_u32(const void* p) {
    uint32_t a;
    asm("{ .reg .u64 t; cvta.to.shared.u64 t, %1; cvt.u32.u64 %0, t; }" : "=r"(a) : "l"(p));
    return a;
}
#define LDSM_X4(R0,R1,R2,R3,ADDR) \
    asm volatile("ldmatrix.sync.aligned.m8n8.x4.shared.b16 {%0,%1,%2,%3}, [%4];" \
                 : "=r"(R0),"=r"(R1),"=r"(R2),"=r"(R3) : "r"(ADDR))

static __device__ __forceinline__ void mma_bf16(float* c, const uint32_t* a, const uint32_t* b) {
    asm volatile(
        "mma.sync.aligned.m16n8k16.row.col.f32.bf16.bf16.f32 "
        "{%0,%1,%2,%3}, {%4,%5,%6,%7}, {%8,%9}, {%0,%1,%2,%3};"
        : "+f"(c[0]), "+f"(c[1]), "+f"(c[2]), "+f"(c[3])
        : "r"(a[0]), "r"(a[1]), "r"(a[2]), "r"(a[3]), "r"(b[0]), "r"(b[1]));
}
static __device__ __forceinline__ void fsplit(float v, bf16& h, bf16& l) {
    h = __float2bfloat16(v);
    l = __float2bfloat16(v - __bfloat162float(h));
}
static __device__ __forceinline__ uint32_t pack2(bf16 a, bf16 b) {
    __nv_bfloat162 t = __halves2bfloat162(a, b);
    return *(uint32_t*)&t;
}
static __device__ __forceinline__ void split4_store(const float4 v, bf16* hi, bf16* lo) {
    bf16 h0, l0, h1, l1, h2, l2, h3, l3;
    fsplit(v.x, h0, l0); fsplit(v.y, h1, l1);
    fsplit(v.z, h2, l2); fsplit(v.w, h3, l3);
    *(uint32_t*)(hi)     = pack2(h0, h1);
    *(uint32_t*)(hi + 2) = pack2(h2, h3);
    *(uint32_t*)(lo)     = pack2(l0, l1);
    *(uint32_t*)(lo + 2) = pack2(l2, l3);
}

// ---------------- mega kernel: prep + all splits + kc col-sum partials ----------------
#define MB_EX   1
#define MB_KC   2501
#define MB_RDW  3001
#define MB_TW1  3129
#define MB_TE   3193
#define MB_MKC  3257
#define MB_TOT  3265
__global__ void mega_kernel(const float* __restrict__ ex, const float* __restrict__ kc,
                            const float* __restrict__ rdw, const float* __restrict__ W1,
                            const float* __restrict__ E, const float* __restrict__ a)
{
    int b = blockIdx.x, tid = threadIdx.x;
    if (b < MB_EX) {
        int k = tid;
        float s1 = 0.f, s2 = 0.f;
        #pragma unroll 8
        for (int j = 0; j < OUT_F; j++) {
            float w = W1[k * OUT_F + j];
            s1 += w * a[j];
            s2 += w * a[OUT_F + j];
        }
        g_v1[k] = s1;
        g_v2[k] = s2;
    } else if (b < MB_KC) {
        size_t i = ((size_t)(b - MB_EX) * 256 + tid) * 4;
        split4_store(*(const float4*)(ex + i), g_exhi + i, g_exlo + i);
    } else if (b < MB_RDW) {
        size_t i = ((size_t)(b - MB_KC) * 256 + tid) * 4;
        split4_store(*(const float4*)(kc + i), g_kchi + i, g_kclo + i);
    } else if (b < MB_TW1) {
        size_t i = ((size_t)(b - MB_RDW) * 256 + tid) * 4;
        split4_store(*(const float4*)(rdw + i), g_rdwhi + i, g_rdwlo + i);
    } else if (b < MB_MKC) {
        bool isW1 = b < MB_TE;
        int bb = b - (isW1 ? MB_TW1 : MB_TE);
        const float* src = isW1 ? W1 : E;
        bf16* hi = isW1 ? g_W1Thi : g_EThi;
        bf16* lo = isW1 ? g_W1Tlo : g_ETlo;
        __shared__ float t[32][33];
        int kb = (bb & 7) * 32, nb = (bb >> 3) * 32;
        int tx = tid & 31, ty = tid >> 5;
        #pragma unroll
        for (int rr = 0; rr < 32; rr += 8)
            t[ty + rr][tx] = src[(size_t)(kb + ty + rr) * OUT_F + nb + tx];
        __syncthreads();
        #pragma unroll
        for (int rr = 0; rr < 32; rr += 8) {
            int n = nb + ty + rr;
            bf16 h, l;
            fsplit(t[tx][ty + rr], h, l);
            hi[(size_t)n * IN_F + kb + tx] = h;
            lo[(size_t)n * IN_F + kb + tx] = l;
        }
    } else {
        int p = b - MB_MKC;
        float s = 0.f;
        for (int j = p * 250; j < (p + 1) * 250; j++)
            s += kc[(size_t)j * IN_F + tid];
        g_mkcp[p][tid] = s;
    }
}

// ---------------- rowdot_both + colmean ----------------
#define RB_E2  1250
#define RB_CM  1506
#define RB_TOT 1507
__global__ void rowdot_both_kernel(const float* __restrict__ ex, const float* __restrict__ kc,
                                   const float* __restrict__ W1)
{
    int b = blockIdx.x, tid = threadIdx.x;
    int lane = tid & 31, warp = tid >> 5;
    if (b < RB_E2) {
        int i = b * 8 + warp;
        if (i >= N_E) return;
        const float* row = ex + (size_t)i * IN_F;
        float s = 0.f;
        #pragma unroll
        for (int k = lane; k < IN_F; k += 32) s += row[k] * g_v1[k];
        #pragma unroll
        for (int o = 16; o; o >>= 1) s += __shfl_xor_sync(0xFFFFFFFFu, s, o);
        if (lane == 0) {
            g_e1[i] = s;
            g_Ae[i] = __expf(s);
            g_Ce[i] = __expf(ALPHA * s);
        }
    } else if (b < RB_CM) {
        int j = (b - RB_E2) * 8 + warp;
        if (j >= NKC_PAD) return;
        float s = 0.f;
        if (j < N_KC) {
            const float* row = kc + (size_t)j * IN_F;
            #pragma unroll
            for (int k = lane; k < IN_F; k += 32) s += row[k] * g_v2[k];
            #pragma unroll
            for (int o = 16; o; o >>= 1) s += __shfl_xor_sync(0xFFFFFFFFu, s, o);
            if (lane == 0) {
                g_e2p[j] = s;
                g_Bf[j] = __expf(s);
                g_Df[j] = __expf(ALPHA * s);
            }
        } else if (lane == 0) {
            g_e2p[j] = 0.f;
            g_Bf[j] = 0.f;
            g_Df[j] = 0.f;
        }
    } else {
        __shared__ float S[IN_F];
        float s = 0.f;
        #pragma unroll
        for (int p = 0; p < 8; p++) s += g_mkcp[p][tid];
        S[tid] = s;
        __syncthreads();
        float c = 0.f;
        #pragma unroll 8
        for (int k = 0; k < IN_F; k++)
            c += S[k] * W1[(size_t)k * OUT_F + tid];
        g_colmean[tid] = c * (1.0f / N_KC);
    }
}

// ---------------- transpose+convert kcWh -> chunk-blocked bf16 hi/lo ----------------
__global__ void conv_kernel(const float* __restrict__ kcWh)
{
    __shared__ float t[32][33];
    int jb = blockIdx.x * 32, nb = blockIdx.y * 32;
    int tx = threadIdx.x & 31, ty = threadIdx.x >> 5;
    #pragma unroll
    for (int rr = 0; rr < 32; rr += 8) {
        int j = jb + ty + rr, n = nb + tx;
        t[ty + rr][tx] = (j < N_KC) ? kcWh[(size_t)j * OUT_F + n] : 0.f;
    }
    __syncthreads();
    #pragma unroll
    for (int rr = 0; rr < 32; rr += 8) {
        int n = nb + ty + rr;
        bf16 h, l;
        fsplit(t[tx][ty + rr], h, l);
        size_t di = ((size_t)(jb >> 5) * 256 + n) * KC + tx;
        g_kcWhT_hi[di] = h;
        g_kcWhT_lo[di] = l;
    }
}

// ---------------- bf16 hi/lo tensor-core GEMM ----------------
// C[M][N] = A @ B^T. Block 64x128, 8 warps (2M x 4N), warp tile 32x32.
#define HOF_AH 0
#define HOF_AL 5120
#define HOF_BH 10240
#define HOF_BL 20480
__global__ __launch_bounds__(256, 2) void hgemm_kernel(
    const bf16* __restrict__ Ahi, const bf16* __restrict__ Alo,
    const bf16* __restrict__ Bhi, const bf16* __restrict__ Blo,
    float* __restrict__ C, int M, int N, int K,
    const float* __restrict__ bias, int epi)
{
    __shared__ char smem[30720];
    uint32_t sb = smem_u32(smem);
    int tid = threadIdx.x, lane = tid & 31, wid = tid >> 5;
    int bm = blockIdx.y * 64, bn = blockIdx.x * 128;
    int wm = wid & 1, wn = wid >> 1;

    float acc[2][4][4];
    #pragma unroll
    for (int mt = 0; mt < 2; mt++)
        #pragma unroll
        for (int nb = 0; nb < 4; nb++)
            #pragma unroll
            for (int k = 0; k < 4; k++) acc[mt][nb][k] = 0.f;

    int arow_c = tid >> 2, ahalf = tid & 3;   // A: 4 threads/row, 16B each
    int brow_c = tid >> 1, bhalf = tid & 1;   // B: 2 threads/row, 32B each
    bool arow_ok = (bm + arow_c) < M;
    const uint4 zero4 = make_uint4(0, 0, 0, 0);

    for (int k0 = 0; k0 < K; k0 += 32) {
        {
            char* dh = smem + HOF_AH + arow_c * RSTRIDE + ahalf * 16;
            char* dl = smem + HOF_AL + arow_c * RSTRIDE + ahalf * 16;
            if (arow_ok) {
                *(uint4*)dh = *(const uint4*)(Ahi + (size_t)(bm + arow_c) * K + k0 + ahalf * 8);
                *(uint4*)dl = *(const uint4*)(Alo + (size_t)(bm + arow_c) * K + k0 + ahalf * 8);
            } else {
                *(uint4*)dh = zero4;
                *(uint4*)dl = zero4;
            }
        }
        {
            const uint4* sh = (const uint4*)(Bhi + (size_t)(bn + brow_c) * K + k0 + bhalf * 16);
            const uint4* sl = (const uint4*)(Blo + (size_t)(bn + brow_c) * K + k0 + bhalf * 16);
            char* dh = smem + HOF_BH + brow_c * RSTRIDE + bhalf * 32;
            char* dl = smem + HOF_BL + brow_c * RSTRIDE + bhalf * 32;
            ((uint4*)dh)[0] = sh[0]; ((uint4*)dh)[1] = sh[1];
            ((uint4*)dl)[0] = sl[0]; ((uint4*)dl)[1] = sl[1];
        }
        __syncthreads();

        #pragma unroll
        for (int ks = 0; ks < 2; ks++) {
            uint32_t ahi[2][4], alo[2][4], bfrag[4][2];
            int arowi = lane & 15;
            int akoff = (ks * 16 + ((lane >> 4) & 1) * 8) * 2;
            #pragma unroll
            for (int mt = 0; mt < 2; mt++) {
                uint32_t ad = sb + HOF_AH + (wm * 32 + mt * 16 + arowi) * RSTRIDE + akoff;
                LDSM_X4(ahi[mt][0], ahi[mt][1], ahi[mt][2], ahi[mt][3], ad);
                ad += (HOF_AL - HOF_AH);
                LDSM_X4(alo[mt][0], alo[mt][1], alo[mt][2], alo[mt][3], ad);
            }
            int bnrow = (lane & 7) + ((lane >> 4) << 3);
            int bkoff = (ks * 16 + ((lane >> 3) & 1) * 8) * 2;
            #pragma unroll
            for (int nq = 0; nq < 2; nq++) {
                uint32_t bd = sb + HOF_BH + (wn * 32 + nq * 16 + bnrow) * RSTRIDE + bkoff;
                LDSM_X4(bfrag[2 * nq][0], bfrag[2 * nq][1],
                        bfrag[2 * nq + 1][0], bfrag[2 * nq + 1][1], bd);
            }
            #pragma unroll
            for (int mt = 0; mt < 2; mt++)
                #pragma unroll
                for (int nb = 0; nb < 4; nb++)
                    mma_bf16(acc[mt][nb], ahi[mt], bfrag[nb]);
            #pragma unroll
            for (int mt = 0; mt < 2; mt++)
                #pragma unroll
                for (int nb = 0; nb < 4; nb++)
                    mma_bf16(acc[mt][nb], alo[mt], bfrag[nb]);
            #pragma unroll
            for (int nq = 0; nq < 2; nq++) {
                uint32_t bd = sb + HOF_BL + (wn * 32 + nq * 16 + bnrow) * RSTRIDE + bkoff;
                LDSM_X4(bfrag[2 * nq][0], bfrag[2 * nq][1],
                        bfrag[2 * nq + 1][0], bfrag[2 * nq + 1][1], bd);
            }
            #pragma unroll
            for (int mt = 0; mt < 2; mt++)
                #pragma unroll
                for (int nb = 0; nb < 4; nb++)
                    mma_bf16(acc[mt][nb], ahi[mt], bfrag[nb]);
        }
        __syncthreads();
    }

    #pragma unroll
    for (int mt = 0; mt < 2; mt++) {
        #pragma unroll
        for (int nb = 0; nb < 4; nb++) {
            int row0 = wm * 32 + mt * 16 + (lane >> 2);
            int col = bn + wn * 32 + nb * 8 + (lane & 3) * 2;
            #pragma unroll
            for (int h = 0; h < 2; h++) {
                int r = bm + row0 + h * 8;
                if (r >= M) continue;
                float v0 = acc[mt][nb][2 * h];
                float v1 = acc[mt][nb][2 * h + 1];
                if (epi == 1) {
                    v0 += bias[col];
                    v1 += bias[col + 1];
                    v0 = v0 > 0.f ? v0 : expm1f(v0);
                    v1 = v1 > 0.f ? v1 : expm1f(v1);
                }
                C[(size_t)r * N + col]     = v0;
                C[(size_t)r * N + col + 1] = v1;
            }
        }
    }
}

// ---------------- attention: P-gen + warp-level bf16 hi/lo mma.sync ----------------
// MT=32: 8 warps (2M x 4N), warp tile 16x64.
#define OFF_BHI 0
#define OFF_BLO 20480
#define OFF_AHI 40960
#define OFF_ALO 43520
#define OFF_E2  46080
#define OFF_BF  54272
#define OFF_DF  62464
#define OFF_E1  70656
#define OFF_AE  70784
#define OFF_CE  70912
#define OFF_RS  71040
#define SMEM_ATTN 71168

static __device__ __forceinline__ float pgen(int m, float e1v, float Ai, float Ci,
    const float* e2f, const float* bfv, const float* dfv, int j)
{
    float s = e1v + e2f[j];
    float pv = (s > 0.f) ? Ai * bfv[j] : Ci * dfv[j];
    return (m > 0) ? pv : 0.f;
}

__global__ __launch_bounds__(256, 2) void attn_mma_kernel(
    const float* __restrict__ e1, const int* __restrict__ adj,
    const float* __restrict__ exEh)
{
    extern __shared__ char smem[];
    uint32_t sb = smem_u32(smem);
    float* e2f = (float*)(smem + OFF_E2);
    float* bfv = (float*)(smem + OFF_BF);
    float* dfv = (float*)(smem + OFF_DF);
    float* e1s = (float*)(smem + OFF_E1);
    float* Aes = (float*)(smem + OFF_AE);
    float* Ces = (float*)(smem + OFF_CE);
    float* rsum = (float*)(smem + OFF_RS);

    int tid = threadIdx.x, lane = tid & 31, wid = tid >> 5;
    int i0 = blockIdx.x * MT;

    for (int j = tid; j < NKC_PAD; j += 256) {
        e2f[j] = g_e2p[j];
        bfv[j] = g_Bf[j];
        dfv[j] = g_Df[j];
    }
    if (tid < MT) {
        int gi = i0 + tid;
        bool v = gi < N_E;
        e1s[tid] = v ? e1[gi] : 0.f;
        Aes[tid] = v ? g_Ae[gi] : 0.f;
        Ces[tid] = v ? g_Ce[gi] : 0.f;
    }
    __syncthreads();

    // P-gen role: 8 threads per row, 4 j each
    int r = tid >> 3, jl0 = (tid & 7) * 4;
    int gi_r = i0 + r;
    const int* arow = adj + (size_t)(gi_r < N_E ? gi_r : 0) * N_KC;
    float e1v = e1s[r], Ai = Aes[r], Ci = Ces[r];
    float srow = 0.f;

    int wm = wid & 1, wn = wid >> 1;   // 2M x 4N, warp tile 16x64
    float acc[8][4];
    #pragma unroll
    for (int nb = 0; nb < 8; nb++)
        #pragma unroll
        for (int k = 0; k < 4; k++) acc[nb][k] = 0.f;

    char* ph = smem + OFF_AHI + r * RSTRIDE + jl0 * 2;
    char* pl = smem + OFF_ALO + r * RSTRIDE + jl0 * 2;

    for (int c = 0; c < NCHUNK_RUN; c++) {
        int j0 = c * KC;
        // B tile copy (same data for all blocks; L2-hot): 256 rows x 64B hi/lo
        {
            const uint4* sh = (const uint4*)(g_kcWhT_hi + ((size_t)c * 256 + tid) * KC);
            const uint4* sl = (const uint4*)(g_kcWhT_lo + ((size_t)c * 256 + tid) * KC);
            char* dh = smem + OFF_BHI + tid * RSTRIDE;
            char* dl = smem + OFF_BLO + tid * RSTRIDE;
            #pragma unroll
            for (int t = 0; t < 4; t++) {
                *(uint4*)(dh + t * 16) = sh[t];
                *(uint4*)(dl + t * 16) = sl[t];
            }
        }
        // P tile gen: 4 edges per thread
        float p0, p1, p2, p3;
        if (j0 + KC <= N_KC) {
            int4 av = *(const int4*)(arow + j0 + jl0);
            int j = j0 + jl0;
            p0 = pgen(av.x, e1v, Ai, Ci, e2f, bfv, dfv, j);
            p1 = pgen(av.y, e1v, Ai, Ci, e2f, bfv, dfv, j + 1);
            p2 = pgen(av.z, e1v, Ai, Ci, e2f, bfv, dfv, j + 2);
            p3 = pgen(av.w, e1v, Ai, Ci, e2f, bfv, dfv, j + 3);
        } else {
            int j = j0 + jl0;
            int m0 = (j     < N_KC) ? arow[j]     : 0;
            int m1 = (j + 1 < N_KC) ? arow[j + 1] : 0;
            int m2 = (j + 2 < N_KC) ? arow[j + 2] : 0;
            int m3 = (j + 3 < N_KC) ? arow[j + 3] : 0;
            p0 = pgen(m0, e1v, Ai, Ci, e2f, bfv, dfv, j);
            p1 = pgen(m1, e1v, Ai, Ci, e2f, bfv, dfv, j + 1);
            p2 = pgen(m2, e1v, Ai, Ci, e2f, bfv, dfv, j + 2);
            p3 = pgen(m3, e1v, Ai, Ci, e2f, bfv, dfv, j + 3);
        }
        srow += (p0 + p1) + (p2 + p3);
        {
            bf16 h0, l0, h1, l1, h2, l2, h3, l3;
            fsplit(p0, h0, l0); fsplit(p1, h1, l1);
            fsplit(p2, h2, l2); fsplit(p3, h3, l3);
            uint2 hw = make_uint2(pack2(h0, h1), pack2(h2, h3));
            uint2 lw = make_uint2(pack2(l0, l1), pack2(l2, l3));
            *(uint2*)ph = hw;
            *(uint2*)pl = lw;
        }
        __syncthreads();

        // MMA: 3-product bf16 hi/lo
        #pragma unroll
        for (int ks = 0; ks < 2; ks++) {
            uint32_t ahi[4], alo[4], bfrag[8][2];
            int arowi = lane & 15;
            int akoff = (ks * 16 + ((lane >> 4) & 1) * 8) * 2;
            {
                uint32_t ad = sb + OFF_AHI + (wm * 16 + arowi) * RSTRIDE + akoff;
                LDSM_X4(ahi[0], ahi[1], ahi[2], ahi[3], ad);
                ad += (OFF_ALO - OFF_AHI);
                LDSM_X4(alo[0], alo[1], alo[2], alo[3], ad);
            }
            int bnrow = (lane & 7) + ((lane >> 4) << 3);
            int bkoff = (ks * 16 + ((lane >> 3) & 1) * 8) * 2;
            #pragma unroll
            for (int nq = 0; nq < 4; nq++) {
                uint32_t bd = sb + OFF_BHI + (wn * 64 + nq * 16 + bnrow) * RSTRIDE + bkoff;
                LDSM_X4(bfrag[2 * nq][0], bfrag[2 * nq][1],
                        bfrag[2 * nq + 1][0], bfrag[2 * nq + 1][1], bd);
            }
            #pragma unroll
            for (int nb = 0; nb < 8; nb++)
                mma_bf16(acc[nb], ahi, bfrag[nb]);
            #pragma unroll
            for (int nb = 0; nb < 8; nb++)
                mma_bf16(acc[nb], alo, bfrag[nb]);
            #pragma unroll
            for (int nq = 0; nq < 4; nq++) {
                uint32_t bd = sb + OFF_BLO + (wn * 64 + nq * 16 + bnrow) * RSTRIDE + bkoff;
                LDSM_X4(bfrag[2 * nq][0], bfrag[2 * nq][1],
                        bfrag[2 * nq + 1][0], bfrag[2 * nq + 1][1], bd);
            }
            #pragma unroll
            for (int nb = 0; nb < 8; nb++)
                mma_bf16(acc[nb], ahi, bfrag[nb]);
        }
        __syncthreads();
    }

    // row sums: reduce over 8 threads per row
    srow += __shfl_xor_sync(0xFFFFFFFFu, srow, 1);
    srow += __shfl_xor_sync(0xFFFFFFFFu, srow, 2);
    srow += __shfl_xor_sync(0xFFFFFFFFu, srow, 4);
    if ((tid & 7) == 0) rsum[r] = srow;
    __syncthreads();

    // epilogue: normalize + write feat hi/lo
    #pragma unroll
    for (int nb = 0; nb < 8; nb++) {
        int row0 = wm * 16 + (lane >> 2);
        int col  = wn * 64 + nb * 8 + (lane & 3) * 2;
        #pragma unroll
        for (int h = 0; h < 2; h++) {
            int rr = row0 + h * 8;
            int gi = i0 + rr;
            if (gi >= N_E) continue;
            float v0 = acc[nb][2 * h];
            float v1 = acc[nb][2 * h + 1];
            float rs = rsum[rr];
            float nk0, nk1;
            if (rs > 0.f) {
                float ri = 1.f / rs;
                nk0 = v0 * ri;
                nk1 = v1 * ri;
            } else {
                nk0 = g_colmean[col];
                nk1 = g_colmean[col + 1];
            }
            float x0 = exEh[(size_t)gi * OUT_F + col];
            float x1 = exEh[(size_t)gi * OUT_F + col + 1];
            float q0 = nk0 * x0, q1 = nk1 * x1;
            size_t fb = (size_t)gi * (2 * OUT_F);
            bf16 h0, l0, h1, l1;
            fsplit(nk0, h0, l0); fsplit(nk1, h1, l1);
            *(uint32_t*)(g_feathi + fb + col) = pack2(h0, h1);
            *(uint32_t*)(g_featlo + fb + col) = pack2(l0, l1);
            fsplit(q0, h0, l0); fsplit(q1, h1, l1);
            *(uint32_t*)(g_feathi + fb + OUT_F + col) = pack2(h0, h1);
            *(uint32_t*)(g_featlo + fb + OUT_F + col) = pack2(l0, l1);
        }
    }
}

// ---------------- launch ----------------
extern "C" void kernel_launch(void* const* d_in, const int* in_sizes, int n_in,
                              void* d_out, int out_size)
{
    const float* ex   = (const float*)d_in[0];
    const float* kc   = (const float*)d_in[1];
    const int*   adj  = (const int*)d_in[2];
    const float* W1   = (const float*)d_in[3];
    const float* E    = (const float*)d_in[4];
    const float* a    = (const float*)d_in[5];
    const float* rd_w = (const float*)d_in[6];
    const float* rd_b = (const float*)d_in[7];
    float* out = (float*)d_out;

    float *kcWh, *exEh, *e1;
    bf16 *exhi, *exlo, *kchi, *kclo, *W1Thi, *W1Tlo, *EThi, *ETlo;
    bf16 *rdwhi, *rdwlo, *feathi, *featlo;
    cudaGetSymbolAddress((void**)&kcWh, g_kcWh);
    cudaGetSymbolAddress((void**)&exEh, g_exEh);
    cudaGetSymbolAddress((void**)&e1, g_e1);
    cudaGetSymbolAddress((void**)&exhi, g_exhi);
    cudaGetSymbolAddress((void**)&exlo, g_exlo);
    cudaGetSymbolAddress((void**)&kchi, g_kchi);
    cudaGetSymbolAddress((void**)&kclo, g_kclo);
    cudaGetSymbolAddress((void**)&W1Thi, g_W1Thi);
    cudaGetSymbolAddress((void**)&W1Tlo, g_W1Tlo);
    cudaGetSymbolAddress((void**)&EThi, g_EThi);
    cudaGetSymbolAddress((void**)&ETlo, g_ETlo);
    cudaGetSymbolAddress((void**)&rdwhi, g_rdwhi);
    cudaGetSymbolAddress((void**)&rdwlo, g_rdwlo);
    cudaGetSymbolAddress((void**)&feathi, g_feathi);
    cudaGetSymbolAddress((void**)&featlo, g_featlo);

    cudaFuncSetAttribute(attn_mma_kernel,
                         cudaFuncAttributeMaxDynamicSharedMemorySize, SMEM_ATTN);

    // 0. prep + splits + kc colsum partials
    mega_kernel<<<MB_TOT, 256>>>(ex, kc, rd_w, W1, E, a);

    // 1. kc_Wh = kc @ W1   [2000,256]
    hgemm_kernel<<<dim3(OUT_F / 128, (N_KC + 63) / 64), 256>>>(
        kchi, kclo, W1Thi, W1Tlo, kcWh, N_KC, OUT_F, IN_F, nullptr, 0);

    // 2. e1/e2 rowdots + exp tables + colmean
    rowdot_both_kernel<<<RB_TOT, 256>>>(ex, kc, W1);

    // 3. kcWh -> chunk-blocked transposed bf16 hi/lo
    conv_kernel<<<dim3(NKC_PAD / 32, OUT_F / 32), 256>>>(kcWh);

    // 4. ex_Eh = ex @ E   [10000,256]
    hgemm_kernel<<<dim3(OUT_F / 128, (N_E + 63) / 64), 256>>>(
        exhi, exlo, EThi, ETlo, exEh, N_E, OUT_F, IN_F, nullptr, 0);

    // 5. attention -> feat hi/lo [10000, 512]
    attn_mma_kernel<<<(N_E + MT - 1) / MT, 256, SMEM_ATTN>>>(e1, adj, exEh);

    // 6. out = elu(feat @ rd_w^T + rd_b)   [10000,256]
    hgemm_kernel<<<dim3(OUT_F / 128, (N_E + 63) / 64), 256>>>(
        feathi, featlo, rdwhi, rdwlo, out, N_E, OUT_F, 2 * OUT_F, rd_b, 1);
}

// round 9
// speedup vs baseline: 1.3779x; 1.3779x over previous
#include <cuda_runtime.h>
#include <cuda_bf16.h>
#include <math.h>
#include <stdint.h>

#define IN_F   256
#define OUT_F  256
#define N_E    10000
#define N_KC   2000
#define ALPHA  0.2f

#define MT      64
#define KC      32
#define NKC_PAD 2048
#define NCHUNK_RUN 63
#define RSTRIDE 80

#define NGEX    158        // exEh gemm blocks in fused kernel (2 x 79)
#define NATTN   157        // ceil(10000/64)

typedef __nv_bfloat16 bf16;

// ---------------- scratch ----------------
__device__ float g_kcWh[N_KC * OUT_F];
__device__ float g_exEh[N_E * OUT_F];
__device__ float g_e1[N_E];
__device__ float g_v1[IN_F];
__device__ float g_v2[IN_F];
__device__ bf16 g_kcWhT_hi[OUT_F * NKC_PAD];
__device__ bf16 g_kcWhT_lo[OUT_F * NKC_PAD];
__device__ float g_colmean[OUT_F];
__device__ float g_mkcp[8][IN_F];
__device__ float g_Ae[N_E];
__device__ float g_Ce[N_E];
__device__ float g_Bf[NKC_PAD];
__device__ float g_Df[NKC_PAD];
__device__ float g_e2p[NKC_PAD];
__device__ bf16 g_exhi[N_E * IN_F];
__device__ bf16 g_exlo[N_E * IN_F];
__device__ bf16 g_kchi[N_KC * IN_F];
__device__ bf16 g_kclo[N_KC * IN_F];
__device__ bf16 g_W1Thi[OUT_F * IN_F];
__device__ bf16 g_W1Tlo[OUT_F * IN_F];
__device__ bf16 g_EThi[OUT_F * IN_F];
__device__ bf16 g_ETlo[OUT_F * IN_F];
__device__ bf16 g_rdwhi[OUT_F * 2 * OUT_F];
__device__ bf16 g_rdwlo[OUT_F * 2 * OUT_F];
__device__ bf16 g_feathi[N_E * OUT_F];   // new_kc only (virtual concat in final GEMM)
__device__ bf16 g_featlo[N_E * OUT_F];

// ---------------- helpers ----------------
static __device__ __forceinline__ uint32_t smem_u32(const void* p) {
    uint32_t a;
    asm("{ .reg .u64 t; cvta.to.shared.u64 t, %1; cvt.u32.u64 %0, t; }" : "=r"(a) : "l"(p));
    return a;
}
#define LDSM_X4(R0,R1,R2,R3,ADDR) \
    asm volatile("ldmatrix.sync.aligned.m8n8.x4.shared.b16 {%0,%1,%2,%3}, [%4];" \
                 : "=r"(R0),"=r"(R1),"=r"(R2),"=r"(R3) : "r"(ADDR))

static __device__ __forceinline__ void mma_bf16(float* c, const uint32_t* a, const uint32_t* b) {
    asm volatile(
        "mma.sync.aligned.m16n8k16.row.col.f32.bf16.bf16.f32 "
        "{%0,%1,%2,%3}, {%4,%5,%6,%7}, {%8,%9}, {%0,%1,%2,%3};"
        : "+f"(c[0]), "+f"(c[1]), "+f"(c[2]), "+f"(c[3])
        : "r"(a[0]), "r"(a[1]), "r"(a[2]), "r"(a[3]), "r"(b[0]), "r"(b[1]));
}
static __device__ __forceinline__ void fsplit(float v, bf16& h, bf16& l) {
    h = __float2bfloat16(v);
    l = __float2bfloat16(v - __bfloat162float(h));
}
static __device__ __forceinline__ uint32_t pack2(bf16 a, bf16 b) {
    __nv_bfloat162 t = __halves2bfloat162(a, b);
    return *(uint32_t*)&t;
}
static __device__ __forceinline__ void split4_store(const float4 v, bf16* hi, bf16* lo) {
    bf16 h0, l0, h1, l1, h2, l2, h3, l3;
    fsplit(v.x, h0, l0); fsplit(v.y, h1, l1);
    fsplit(v.z, h2, l2); fsplit(v.w, h3, l3);
    *(uint32_t*)(hi)     = pack2(h0, h1);
    *(uint32_t*)(hi + 2) = pack2(h2, h3);
    *(uint32_t*)(lo)     = pack2(l0, l1);
    *(uint32_t*)(lo + 2) = pack2(l2, l3);
}

// ---------------- mega kernel ----------------
#define MB_EX   1
#define MB_KC   2501
#define MB_RDW  3001
#define MB_TW1  3129
#define MB_TE   3193
#define MB_MKC  3257
#define MB_TOT  3265
__global__ void mega_kernel(const float* __restrict__ ex, const float* __restrict__ kc,
                            const float* __restrict__ rdw, const float* __restrict__ W1,
                            const float* __restrict__ E, const float* __restrict__ a)
{
    int b = blockIdx.x, tid = threadIdx.x;
    if (b < MB_EX) {
        int k = tid;
        float s1 = 0.f, s2 = 0.f;
        #pragma unroll 8
        for (int j = 0; j < OUT_F; j++) {
            float w = W1[k * OUT_F + j];
            s1 += w * a[j];
            s2 += w * a[OUT_F + j];
        }
        g_v1[k] = s1;
        g_v2[k] = s2;
    } else if (b < MB_KC) {
        size_t i = ((size_t)(b - MB_EX) * 256 + tid) * 4;
        split4_store(*(const float4*)(ex + i), g_exhi + i, g_exlo + i);
    } else if (b < MB_RDW) {
        size_t i = ((size_t)(b - MB_KC) * 256 + tid) * 4;
        split4_store(*(const float4*)(kc + i), g_kchi + i, g_kclo + i);
    } else if (b < MB_TW1) {
        size_t i = ((size_t)(b - MB_RDW) * 256 + tid) * 4;
        split4_store(*(const float4*)(rdw + i), g_rdwhi + i, g_rdwlo + i);
    } else if (b < MB_MKC) {
        bool isW1 = b < MB_TE;
        int bb = b - (isW1 ? MB_TW1 : MB_TE);
        const float* src = isW1 ? W1 : E;
        bf16* hi = isW1 ? g_W1Thi : g_EThi;
        bf16* lo = isW1 ? g_W1Tlo : g_ETlo;
        __shared__ float t[32][33];
        int kb = (bb & 7) * 32, nb = (bb >> 3) * 32;
        int tx = tid & 31, ty = tid >> 5;
        #pragma unroll
        for (int rr = 0; rr < 32; rr += 8)
            t[ty + rr][tx] = src[(size_t)(kb + ty + rr) * OUT_F + nb + tx];
        __syncthreads();
        #pragma unroll
        for (int rr = 0; rr < 32; rr += 8) {
            int n = nb + ty + rr;
            bf16 h, l;
            fsplit(t[tx][ty + rr], h, l);
            hi[(size_t)n * IN_F + kb + tx] = h;
            lo[(size_t)n * IN_F + kb + tx] = l;
        }
    } else {
        int p = b - MB_MKC;
        float s = 0.f;
        for (int j = p * 250; j < (p + 1) * 250; j++)
            s += kc[(size_t)j * IN_F + tid];
        g_mkcp[p][tid] = s;
    }
}

// ---------------- rowdot_both + colmean ----------------
#define RB_E2  1250
#define RB_CM  1506
#define RB_TOT 1507
__global__ void rowdot_both_kernel(const float* __restrict__ ex, const float* __restrict__ kc,
                                   const float* __restrict__ W1)
{
    int b = blockIdx.x, tid = threadIdx.x;
    int lane = tid & 31, warp = tid >> 5;
    if (b < RB_E2) {
        int i = b * 8 + warp;
        if (i >= N_E) return;
        const float* row = ex + (size_t)i * IN_F;
        float s = 0.f;
        #pragma unroll
        for (int k = lane; k < IN_F; k += 32) s += row[k] * g_v1[k];
        #pragma unroll
        for (int o = 16; o; o >>= 1) s += __shfl_xor_sync(0xFFFFFFFFu, s, o);
        if (lane == 0) {
            g_e1[i] = s;
            g_Ae[i] = __expf(s);
            g_Ce[i] = __expf(ALPHA * s);
        }
    } else if (b < RB_CM) {
        int j = (b - RB_E2) * 8 + warp;
        if (j >= NKC_PAD) return;
        float s = 0.f;
        if (j < N_KC) {
            const float* row = kc + (size_t)j * IN_F;
            #pragma unroll
            for (int k = lane; k < IN_F; k += 32) s += row[k] * g_v2[k];
            #pragma unroll
            for (int o = 16; o; o >>= 1) s += __shfl_xor_sync(0xFFFFFFFFu, s, o);
            if (lane == 0) {
                g_e2p[j] = s;
                g_Bf[j] = __expf(s);
                g_Df[j] = __expf(ALPHA * s);
            }
        } else if (lane == 0) {
            g_e2p[j] = 0.f;
            g_Bf[j] = 0.f;
            g_Df[j] = 0.f;
        }
    } else {
        __shared__ float S[IN_F];
        float s = 0.f;
        #pragma unroll
        for (int p = 0; p < 8; p++) s += g_mkcp[p][tid];
        S[tid] = s;
        __syncthreads();
        float c = 0.f;
        #pragma unroll 8
        for (int k = 0; k < IN_F; k++)
            c += S[k] * W1[(size_t)k * OUT_F + tid];
        g_colmean[tid] = c * (1.0f / N_KC);
    }
}

// ---------------- conv: kcWh -> chunk-blocked bf16 hi/lo ----------------
__global__ void conv_kernel(const float* __restrict__ kcWh)
{
    __shared__ float t[32][33];
    int jb = blockIdx.x * 32, nb = blockIdx.y * 32;
    int tx = threadIdx.x & 31, ty = threadIdx.x >> 5;
    #pragma unroll
    for (int rr = 0; rr < 32; rr += 8) {
        int j = jb + ty + rr, n = nb + tx;
        t[ty + rr][tx] = (j < N_KC) ? kcWh[(size_t)j * OUT_F + n] : 0.f;
    }
    __syncthreads();
    #pragma unroll
    for (int rr = 0; rr < 32; rr += 8) {
        int n = nb + ty + rr;
        bf16 h, l;
        fsplit(t[tx][ty + rr], h, l);
        size_t di = ((size_t)(jb >> 5) * 256 + n) * KC + tx;
        g_kcWhT_hi[di] = h;
        g_kcWhT_lo[di] = l;
    }
}

// ---------------- hgemm body (128x128 tile, 8 warps 4Mx2N) ----------------
// epi==1: final GEMM — A is virtual [nk | nk*exEh] with nk stride 256; C = elu(C+bias)
#define HOF_AH 0
#define HOF_AL 10240
#define HOF_BH 20480
#define HOF_BL 30720
static __device__ __forceinline__ void hgemm_body(char* smem,
    const bf16* __restrict__ Ahi, const bf16* __restrict__ Alo,
    const bf16* __restrict__ Bhi, const bf16* __restrict__ Blo,
    float* __restrict__ C, int M, int N, int K,
    const float* __restrict__ bias, int epi, const float* __restrict__ exF,
    int bx, int by)
{
    uint32_t sb = smem_u32(smem);
    int tid = threadIdx.x, lane = tid & 31, wid = tid >> 5;
    int bm = by * 128, bn = bx * 128;
    int wm = wid >> 1, wn = wid & 1;
    size_t astr = (epi == 1) ? 256 : (size_t)K;

    float acc[2][8][4];
    #pragma unroll
    for (int mt = 0; mt < 2; mt++)
        #pragma unroll
        for (int nb = 0; nb < 8; nb++)
            #pragma unroll
            for (int k = 0; k < 4; k++) acc[mt][nb][k] = 0.f;

    int crow = tid >> 1, chalf = tid & 1;
    bool arow_ok = (bm + crow) < M;
    const uint4 zero4 = make_uint4(0, 0, 0, 0);

    for (int k0 = 0; k0 < K; k0 += 32) {
        // --- A tile
        {
            char* dh = smem + HOF_AH + crow * RSTRIDE + chalf * 32;
            char* dl = smem + HOF_AL + crow * RSTRIDE + chalf * 32;
            if (!arow_ok) {
                ((uint4*)dh)[0] = zero4; ((uint4*)dh)[1] = zero4;
                ((uint4*)dl)[0] = zero4; ((uint4*)dl)[1] = zero4;
            } else if (epi == 1 && k0 >= 256) {
                // virtual A: nk * exEh
                size_t rb = (size_t)(bm + crow) * 256 + (k0 - 256) + chalf * 16;
                uint4 vh[2], vl[2];
                float4 vx[4];
                vh[0] = *(const uint4*)(Ahi + rb); vh[1] = *(const uint4*)(Ahi + rb + 8);
                vl[0] = *(const uint4*)(Alo + rb); vl[1] = *(const uint4*)(Alo + rb + 8);
                vx[0] = *(const float4*)(exF + rb);      vx[1] = *(const float4*)(exF + rb + 4);
                vx[2] = *(const float4*)(exF + rb + 8);  vx[3] = *(const float4*)(exF + rb + 12);
                const bf16* ph = (const bf16*)vh;
                const bf16* pl = (const bf16*)vl;
                const float* px = (const float*)vx;
                uint32_t oh[8], ol[8];
                #pragma unroll
                for (int e = 0; e < 8; e++) {
                    float q0 = (__bfloat162float(ph[2*e])   + __bfloat162float(pl[2*e]))   * px[2*e];
                    float q1 = (__bfloat162float(ph[2*e+1]) + __bfloat162float(pl[2*e+1])) * px[2*e+1];
                    bf16 H0, L0, H1, L1;
                    fsplit(q0, H0, L0); fsplit(q1, H1, L1);
                    oh[e] = pack2(H0, H1);
                    ol[e] = pack2(L0, L1);
                }
                ((uint4*)dh)[0] = *(uint4*)&oh[0]; ((uint4*)dh)[1] = *(uint4*)&oh[4];
                ((uint4*)dl)[0] = *(uint4*)&ol[0]; ((uint4*)dl)[1] = *(uint4*)&ol[4];
            } else {
                const uint4* sh = (const uint4*)(Ahi + (size_t)(bm + crow) * astr + k0 + chalf * 16);
                const uint4* sl = (const uint4*)(Alo + (size_t)(bm + crow) * astr + k0 + chalf * 16);
                ((uint4*)dh)[0] = sh[0]; ((uint4*)dh)[1] = sh[1];
                ((uint4*)dl)[0] = sl[0]; ((uint4*)dl)[1] = sl[1];
            }
        }
        // --- B tile
        {
            const uint4* sh = (const uint4*)(Bhi + (size_t)(bn + crow) * K + k0 + chalf * 16);
            const uint4* sl = (const uint4*)(Blo + (size_t)(bn + crow) * K + k0 + chalf * 16);
            char* dh = smem + HOF_BH + crow * RSTRIDE + chalf * 32;
            char* dl = smem + HOF_BL + crow * RSTRIDE + chalf * 32;
            ((uint4*)dh)[0] = sh[0]; ((uint4*)dh)[1] = sh[1];
            ((uint4*)dl)[0] = sl[0]; ((uint4*)dl)[1] = sl[1];
        }
        __syncthreads();

        #pragma unroll
        for (int ks = 0; ks < 2; ks++) {
            uint32_t ahi[2][4], alo[2][4], bfrag[8][2];
            int arowi = lane & 15;
            int akoff = (ks * 16 + ((lane >> 4) & 1) * 8) * 2;
            #pragma unroll
            for (int mt = 0; mt < 2; mt++) {
                uint32_t ad = sb + HOF_AH + (wm * 32 + mt * 16 + arowi) * RSTRIDE + akoff;
                LDSM_X4(ahi[mt][0], ahi[mt][1], ahi[mt][2], ahi[mt][3], ad);
                ad += (HOF_AL - HOF_AH);
                LDSM_X4(alo[mt][0], alo[mt][1], alo[mt][2], alo[mt][3], ad);
            }
            int bnrow = (lane & 7) + ((lane >> 4) << 3);
            int bkoff = (ks * 16 + ((lane >> 3) & 1) * 8) * 2;
            #pragma unroll
            for (int nq = 0; nq < 4; nq++) {
                uint32_t bd = sb + HOF_BH + (wn * 64 + nq * 16 + bnrow) * RSTRIDE + bkoff;
                LDSM_X4(bfrag[2 * nq][0], bfrag[2 * nq][1],
                        bfrag[2 * nq + 1][0], bfrag[2 * nq + 1][1], bd);
            }
            #pragma unroll
            for (int mt = 0; mt < 2; mt++)
                #pragma unroll
                for (int nb = 0; nb < 8; nb++)
                    mma_bf16(acc[mt][nb], ahi[mt], bfrag[nb]);
            #pragma unroll
            for (int mt = 0; mt < 2; mt++)
                #pragma unroll
                for (int nb = 0; nb < 8; nb++)
                    mma_bf16(acc[mt][nb], alo[mt], bfrag[nb]);
            #pragma unroll
            for (int nq = 0; nq < 4; nq++) {
                uint32_t bd = sb + HOF_BL + (wn * 64 + nq * 16 + bnrow) * RSTRIDE + bkoff;
                LDSM_X4(bfrag[2 * nq][0], bfrag[2 * nq][1],
                        bfrag[2 * nq + 1][0], bfrag[2 * nq + 1][1], bd);
            }
            #pragma unroll
            for (int mt = 0; mt < 2; mt++)
                #pragma unroll
                for (int nb = 0; nb < 8; nb++)
                    mma_bf16(acc[mt][nb], ahi[mt], bfrag[nb]);
        }
        __syncthreads();
    }

    #pragma unroll
    for (int mt = 0; mt < 2; mt++) {
        #pragma unroll
        for (int nb = 0; nb < 8; nb++) {
            int row0 = wm * 32 + mt * 16 + (lane >> 2);
            int col = bn + wn * 64 + nb * 8 + (lane & 3) * 2;
            #pragma unroll
            for (int h = 0; h < 2; h++) {
                int r = bm + row0 + h * 8;
                if (r >= M) continue;
                float v0 = acc[mt][nb][2 * h];
                float v1 = acc[mt][nb][2 * h + 1];
                if (epi == 1) {
                    v0 += bias[col];
                    v1 += bias[col + 1];
                    v0 = v0 > 0.f ? v0 : expm1f(v0);
                    v1 = v1 > 0.f ? v1 : expm1f(v1);
                }
                C[(size_t)r * N + col]     = v0;
                C[(size_t)r * N + col + 1] = v1;
            }
        }
    }
}

__global__ __launch_bounds__(256, 2) void hgemm_kernel(
    const bf16* __restrict__ Ahi, const bf16* __restrict__ Alo,
    const bf16* __restrict__ Bhi, const bf16* __restrict__ Blo,
    float* __restrict__ C, int M, int N, int K,
    const float* __restrict__ bias, int epi, const float* __restrict__ exF)
{
    extern __shared__ char smem[];
    hgemm_body(smem, Ahi, Alo, Bhi, Blo, C, M, N, K, bias, epi, exF,
               blockIdx.x, blockIdx.y);
}

// ---------------- attention body (MT=64, R7 layout) ----------------
#define OFF_BHI 0
#define OFF_BLO 20480
#define OFF_AHI 40960
#define OFF_ALO 46080
#define OFF_E2  51200
#define OFF_BF  59392
#define OFF_DF  67584
#define OFF_E1  75776
#define OFF_AE  76032
#define OFF_CE  76288
#define OFF_RS  76544
#define OFF_RSF 77568
#define SMEM_ATTN 77824

static __device__ __forceinline__ float pgen(int m, float e1v, float Ai, float Ci,
    const float* e2f, const float* bfv, const float* dfv, int j)
{
    float s = e1v + e2f[j];
    float pv = (s > 0.f) ? Ai * bfv[j] : Ci * dfv[j];
    return (m > 0) ? pv : 0.f;
}
static __device__ __forceinline__ void psplit_store(char* ph, char* pl, int t,
                                                    float p0, float p1)
{
    bf16 h0, l0, h1, l1;
    fsplit(p0, h0, l0);
    fsplit(p1, h1, l1);
    *(uint32_t*)(ph + 4 * t) = pack2(h0, h1);
    *(uint32_t*)(pl + 4 * t) = pack2(l0, l1);
}

static __device__ __forceinline__ void attn_body(char* smem, int tile,
    const float* __restrict__ e1, const int* __restrict__ adj)
{
    uint32_t sb = smem_u32(smem);
    float* e2f = (float*)(smem + OFF_E2);
    float* bfv = (float*)(smem + OFF_BF);
    float* dfv = (float*)(smem + OFF_DF);
    float* e1s = (float*)(smem + OFF_E1);
    float* Aes = (float*)(smem + OFF_AE);
    float* Ces = (float*)(smem + OFF_CE);

    int tid = threadIdx.x, lane = tid & 31, wid = tid >> 5;
    int i0 = tile * MT;

    for (int j = tid; j < NKC_PAD; j += 256) {
        e2f[j] = g_e2p[j];
        bfv[j] = g_Bf[j];
        dfv[j] = g_Df[j];
    }
    if (tid < MT) {
        int gi = i0 + tid;
        bool v = gi < N_E;
        e1s[tid] = v ? e1[gi] : 0.f;
        Aes[tid] = v ? g_Ae[gi] : 0.f;
        Ces[tid] = v ? g_Ce[gi] : 0.f;
    }
    __syncthreads();

    int r = tid >> 2, jl0 = (tid & 3) * 8;
    int gi_r = i0 + r;
    const int* arow = adj + (size_t)(gi_r < N_E ? gi_r : 0) * N_KC;
    float e1v = e1s[r], Ai = Aes[r], Ci = Ces[r];
    float srow = 0.f;

    int wm = wid & 1, wn = wid >> 1;
    float acc[2][8][4];
    #pragma unroll
    for (int mt = 0; mt < 2; mt++)
        #pragma unroll
        for (int nb = 0; nb < 8; nb++)
            #pragma unroll
            for (int k = 0; k < 4; k++) acc[mt][nb][k] = 0.f;

    char* ph = smem + OFF_AHI + r * RSTRIDE + jl0 * 2;
    char* pl = smem + OFF_ALO + r * RSTRIDE + jl0 * 2;

    for (int c = 0; c < NCHUNK_RUN; c++) {
        int j0 = c * KC;
        {
            const uint4* sh = (const uint4*)(g_kcWhT_hi + ((size_t)c * 256 + tid) * KC);
            const uint4* sl = (const uint4*)(g_kcWhT_lo + ((size_t)c * 256 + tid) * KC);
            char* dh = smem + OFF_BHI + tid * RSTRIDE;
            char* dl = smem + OFF_BLO + tid * RSTRIDE;
            #pragma unroll
            for (int t = 0; t < 4; t++) {
                *(uint4*)(dh + t * 16) = sh[t];
                *(uint4*)(dl + t * 16) = sl[t];
            }
        }
        if (j0 + KC <= N_KC) {
            const int4* ap = (const int4*)(arow + j0 + jl0);
            int4 a0 = ap[0], a1 = ap[1];
            int am[8] = {a0.x, a0.y, a0.z, a0.w, a1.x, a1.y, a1.z, a1.w};
            #pragma unroll
            for (int t = 0; t < 4; t++) {
                int j = j0 + jl0 + 2 * t;
                float p0 = pgen(am[2 * t],     e1v, Ai, Ci, e2f, bfv, dfv, j);
                float p1 = pgen(am[2 * t + 1], e1v, Ai, Ci, e2f, bfv, dfv, j + 1);
                srow += p0 + p1;
                psplit_store(ph, pl, t, p0, p1);
            }
        } else {
            #pragma unroll
            for (int t = 0; t < 4; t++) {
                int j = j0 + jl0 + 2 * t;
                int m0 = (j     < N_KC) ? arow[j]     : 0;
                int m1 = (j + 1 < N_KC) ? arow[j + 1] : 0;
                float p0 = pgen(m0, e1v, Ai, Ci, e2f, bfv, dfv, (j     < N_KC) ? j     : 0);
                float p1 = pgen(m1, e1v, Ai, Ci, e2f, bfv, dfv, (j + 1 < N_KC) ? j + 1 : 0);
                srow += p0 + p1;
                psplit_store(ph, pl, t, p0, p1);
            }
        }
        __syncthreads();

        #pragma unroll
        for (int ks = 0; ks < 2; ks++) {
            uint32_t ahi[2][4], alo[2][4], bfrag[8][2];
            int arowi = lane & 15;
            int akoff = (ks * 16 + ((lane >> 4) & 1) * 8) * 2;
            #pragma unroll
            for (int mt = 0; mt < 2; mt++) {
                uint32_t ad = sb + OFF_AHI + (wm * 32 + mt * 16 + arowi) * RSTRIDE + akoff;
                LDSM_X4(ahi[mt][0], ahi[mt][1], ahi[mt][2], ahi[mt][3], ad);
                ad += (OFF_ALO - OFF_AHI);
                LDSM_X4(alo[mt][0], alo[mt][1], alo[mt][2], alo[mt][3], ad);
            }
            int bnrow = (lane & 7) + ((lane >> 4) << 3);
            int bkoff = (ks * 16 + ((lane >> 3) & 1) * 8) * 2;
            #pragma unroll
            for (int nq = 0; nq < 4; nq++) {
                uint32_t bd = sb + OFF_BHI + (wn * 64 + nq * 16 + bnrow) * RSTRIDE + bkoff;
                LDSM_X4(bfrag[2 * nq][0], bfrag[2 * nq][1],
                        bfrag[2 * nq + 1][0], bfrag[2 * nq + 1][1], bd);
            }
            #pragma unroll
            for (int mt = 0; mt < 2; mt++)
                #pragma unroll
                for (int nb = 0; nb < 8; nb++)
                    mma_bf16(acc[mt][nb], ahi[mt], bfrag[nb]);
            #pragma unroll
            for (int mt = 0; mt < 2; mt++)
                #pragma unroll
                for (int nb = 0; nb < 8; nb++)
                    mma_bf16(acc[mt][nb], alo[mt], bfrag[nb]);
            #pragma unroll
            for (int nq = 0; nq < 4; nq++) {
                uint32_t bd = sb + OFF_BLO + (wn * 64 + nq * 16 + bnrow) * RSTRIDE + bkoff;
                LDSM_X4(bfrag[2 * nq][0], bfrag[2 * nq][1],
                        bfrag[2 * nq + 1][0], bfrag[2 * nq + 1][1], bd);
            }
            #pragma unroll
            for (int mt = 0; mt < 2; mt++)
                #pragma unroll
                for (int nb = 0; nb < 8; nb++)
                    mma_bf16(acc[mt][nb], ahi[mt], bfrag[nb]);
        }
        __syncthreads();
    }

    ((float*)(smem + OFF_RS))[tid] = srow;
    __syncthreads();
    if (tid < MT) {
        const float* r4 = (const float*)(smem + OFF_RS) + tid * 4;
        ((float*)(smem + OFF_RSF))[tid] = (r4[0] + r4[1]) + (r4[2] + r4[3]);
    }
    __syncthreads();
    const float* rsF = (const float*)(smem + OFF_RSF);

    // epilogue: normalize; write new_kc hi/lo only
    #pragma unroll
    for (int mt = 0; mt < 2; mt++) {
        #pragma unroll
        for (int nb = 0; nb < 8; nb++) {
            int row0 = wm * 32 + mt * 16 + (lane >> 2);
            int col  = wn * 64 + nb * 8 + (lane & 3) * 2;
            #pragma unroll
            for (int h = 0; h < 2; h++) {
                int rr = row0 + h * 8;
                int gi = i0 + rr;
                if (gi >= N_E) continue;
                float v0 = acc[mt][nb][2 * h];
                float v1 = acc[mt][nb][2 * h + 1];
                float rs = rsF[rr];
                float nk0, nk1;
                if (rs > 0.f) {
                    float ri = 1.f / rs;
                    nk0 = v0 * ri;
                    nk1 = v1 * ri;
                } else {
                    nk0 = g_colmean[col];
                    nk1 = g_colmean[col + 1];
                }
                size_t fb = (size_t)gi * OUT_F + col;
                bf16 h0, l0, h1, l1;
                fsplit(nk0, h0, l0); fsplit(nk1, h1, l1);
                *(uint32_t*)(g_feathi + fb) = pack2(h0, h1);
                *(uint32_t*)(g_featlo + fb) = pack2(l0, l1);
            }
        }
    }
}

// ---------------- fused kernel: exEh GEMM blocks first, then attention ----------------
__global__ __launch_bounds__(256, 2) void attn_fused_kernel(
    const float* __restrict__ e1, const int* __restrict__ adj)
{
    extern __shared__ char smem[];
    if (blockIdx.x < NGEX) {
        int g = blockIdx.x;
        hgemm_body(smem, g_exhi, g_exlo, g_EThi, g_ETlo, (float*)g_exEh,
                   N_E, OUT_F, IN_F, nullptr, 0, nullptr, g & 1, g >> 1);
    } else {
        attn_body(smem, (int)blockIdx.x - NGEX, e1, adj);
    }
}

// ---------------- launch ----------------
extern "C" void kernel_launch(void* const* d_in, const int* in_sizes, int n_in,
                              void* d_out, int out_size)
{
    const float* ex   = (const float*)d_in[0];
    const float* kc   = (const float*)d_in[1];
    const int*   adj  = (const int*)d_in[2];
    const float* W1   = (const float*)d_in[3];
    const float* E    = (const float*)d_in[4];
    const float* a    = (const float*)d_in[5];
    const float* rd_w = (const float*)d_in[6];
    const float* rd_b = (const float*)d_in[7];
    float* out = (float*)d_out;

    float *kcWh, *exEh, *e1;
    bf16 *kchi, *kclo, *W1Thi, *W1Tlo, *rdwhi, *rdwlo, *feathi, *featlo;
    cudaGetSymbolAddress((void**)&kcWh, g_kcWh);
    cudaGetSymbolAddress((void**)&exEh, g_exEh);
    cudaGetSymbolAddress((void**)&e1, g_e1);
    cudaGetSymbolAddress((void**)&kchi, g_kchi);
    cudaGetSymbolAddress((void**)&kclo, g_kclo);
    cudaGetSymbolAddress((void**)&W1Thi, g_W1Thi);
    cudaGetSymbolAddress((void**)&W1Tlo, g_W1Tlo);
    cudaGetSymbolAddress((void**)&rdwhi, g_rdwhi);
    cudaGetSymbolAddress((void**)&rdwlo, g_rdwlo);
    cudaGetSymbolAddress((void**)&feathi, g_feathi);
    cudaGetSymbolAddress((void**)&featlo, g_featlo);

    cudaFuncSetAttribute(attn_fused_kernel,
                         cudaFuncAttributeMaxDynamicSharedMemorySize, SMEM_ATTN);
    cudaFuncSetAttribute(hgemm_kernel,
                         cudaFuncAttributeMaxDynamicSharedMemorySize, 40960);

    // 0. prep + splits + kc colsum partials
    mega_kernel<<<MB_TOT, 256>>>(ex, kc, rd_w, W1, E, a);

    // 1. kc_Wh = kc @ W1   [2000,256]
    hgemm_kernel<<<dim3(OUT_F / 128, (N_KC + 127) / 128), 256, 40960>>>(
        kchi, kclo, W1Thi, W1Tlo, kcWh, N_KC, OUT_F, IN_F, nullptr, 0, nullptr);

    // 2. e1/e2 rowdots + exp tables + colmean
    rowdot_both_kernel<<<RB_TOT, 256>>>(ex, kc, W1);

    // 3. kcWh -> chunk-blocked transposed bf16 hi/lo
    conv_kernel<<<dim3(NKC_PAD / 32, OUT_F / 32), 256>>>(kcWh);

    // 4. fused: exEh GEMM (158 blocks) + attention (157 blocks)
    attn_fused_kernel<<<NGEX + NATTN, 256, SMEM_ATTN>>>(e1, adj);

    // 5. out = elu([nk | nk*exEh] @ rd_w^T + rd_b)   [10000,256]
    hgemm_kernel<<<dim3(OUT_F / 128, (N_E + 127) / 128), 256, 40960>>>(
        feathi, featlo, rdwhi, rdwlo, out, N_E, OUT_F, 2 * OUT_F, rd_b, 1, exEh);
}

// round 10
// speedup vs baseline: 1.4240x; 1.0335x over previous
#include <cuda_runtime.h>
#include <cuda_bf16.h>
#include <math.h>
#include <stdint.h>

#define IN_F   256
#define OUT_F  256
#define N_E    10000
#define N_KC   2000
#define ALPHA  0.2f

#define MT      64
#define KC      32
#define NKC_PAD 2048
#define NCHUNK_RUN 63
#define RSTRIDE 80

#define NGEX    158
#define NATTN   157

typedef __nv_bfloat16 bf16;

// ---------------- scratch ----------------
__device__ float g_kcWh[N_KC * OUT_F];
__device__ float g_exEh[N_E * OUT_F];
__device__ float g_e1[N_E];
__device__ float g_v1[IN_F];
__device__ float g_v2[IN_F];
__device__ bf16 g_kcWhT_hi[OUT_F * NKC_PAD];
__device__ bf16 g_kcWhT_lo[OUT_F * NKC_PAD];
__device__ float g_colmean[OUT_F];
__device__ float g_mkcp[8][IN_F];
__device__ float g_Ae[N_E];
__device__ float g_Ce[N_E];
__device__ float2 g_tab[NKC_PAD];   // (exp(e2), exp(ALPHA*e2)), zero-padded
__device__ bf16 g_exhi[N_E * IN_F];
__device__ bf16 g_exlo[N_E * IN_F];
__device__ bf16 g_kchi[N_KC * IN_F];
__device__ bf16 g_kclo[N_KC * IN_F];
__device__ bf16 g_W1Thi[OUT_F * IN_F];
__device__ bf16 g_W1Tlo[OUT_F * IN_F];
__device__ bf16 g_EThi[OUT_F * IN_F];
__device__ bf16 g_ETlo[OUT_F * IN_F];
__device__ bf16 g_rdwhi[OUT_F * 2 * OUT_F];
__device__ bf16 g_rdwlo[OUT_F * 2 * OUT_F];
__device__ bf16 g_feathi[N_E * OUT_F];
__device__ bf16 g_featlo[N_E * OUT_F];

// ---------------- helpers ----------------
static __device__ __forceinline__ uint32_t smem_u32(const void* p) {
    uint32_t a;
    asm("{ .reg .u64 t; cvta.to.shared.u64 t, %1; cvt.u32.u64 %0, t; }" : "=r"(a) : "l"(p));
    return a;
}
#define LDSM_X4(R0,R1,R2,R3,ADDR) \
    asm volatile("ldmatrix.sync.aligned.m8n8.x4.shared.b16 {%0,%1,%2,%3}, [%4];" \
                 : "=r"(R0),"=r"(R1),"=r"(R2),"=r"(R3) : "r"(ADDR))
#define CP_ASYNC16(dst, src) \
    asm volatile("cp.async.ca.shared.global [%0], [%1], 16;" :: "r"(dst), "l"(src))
#define CP_COMMIT() asm volatile("cp.async.commit_group;" ::: "memory")
#define CP_WAIT0()  asm volatile("cp.async.wait_group 0;" ::: "memory")

static __device__ __forceinline__ void mma_bf16(float* c, const uint32_t* a, const uint32_t* b) {
    asm volatile(
        "mma.sync.aligned.m16n8k16.row.col.f32.bf16.bf16.f32 "
        "{%0,%1,%2,%3}, {%4,%5,%6,%7}, {%8,%9}, {%0,%1,%2,%3};"
        : "+f"(c[0]), "+f"(c[1]), "+f"(c[2]), "+f"(c[3])
        : "r"(a[0]), "r"(a[1]), "r"(a[2]), "r"(a[3]), "r"(b[0]), "r"(b[1]));
}
static __device__ __forceinline__ void fsplit(float v, bf16& h, bf16& l) {
    h = __float2bfloat16(v);
    l = __float2bfloat16(v - __bfloat162float(h));
}
static __device__ __forceinline__ uint32_t pack2(bf16 a, bf16 b) {
    __nv_bfloat162 t = __halves2bfloat162(a, b);
    return *(uint32_t*)&t;
}
static __device__ __forceinline__ void split4_store(const float4 v, bf16* hi, bf16* lo) {
    bf16 h0, l0, h1, l1, h2, l2, h3, l3;
    fsplit(v.x, h0, l0); fsplit(v.y, h1, l1);
    fsplit(v.z, h2, l2); fsplit(v.w, h3, l3);
    *(uint32_t*)(hi)     = pack2(h0, h1);
    *(uint32_t*)(hi + 2) = pack2(h2, h3);
    *(uint32_t*)(lo)     = pack2(l0, l1);
    *(uint32_t*)(lo + 2) = pack2(l2, l3);
}

// ---------------- mega kernel ----------------
#define MB_EX   1
#define MB_KC   2501
#define MB_RDW  3001
#define MB_TW1  3129
#define MB_TE   3193
#define MB_MKC  3257
#define MB_TOT  3265
__global__ void mega_kernel(const float* __restrict__ ex, const float* __restrict__ kc,
                            const float* __restrict__ rdw, const float* __restrict__ W1,
                            const float* __restrict__ E, const float* __restrict__ a)
{
    int b = blockIdx.x, tid = threadIdx.x;
    if (b < MB_EX) {
        int k = tid;
        float s1 = 0.f, s2 = 0.f;
        #pragma unroll 8
        for (int j = 0; j < OUT_F; j++) {
            float w = W1[k * OUT_F + j];
            s1 += w * a[j];
            s2 += w * a[OUT_F + j];
        }
        g_v1[k] = s1;
        g_v2[k] = s2;
    } else if (b < MB_KC) {
        size_t i = ((size_t)(b - MB_EX) * 256 + tid) * 4;
        split4_store(*(const float4*)(ex + i), g_exhi + i, g_exlo + i);
    } else if (b < MB_RDW) {
        size_t i = ((size_t)(b - MB_KC) * 256 + tid) * 4;
        split4_store(*(const float4*)(kc + i), g_kchi + i, g_kclo + i);
    } else if (b < MB_TW1) {
        size_t i = ((size_t)(b - MB_RDW) * 256 + tid) * 4;
        split4_store(*(const float4*)(rdw + i), g_rdwhi + i, g_rdwlo + i);
    } else if (b < MB_MKC) {
        bool isW1 = b < MB_TE;
        int bb = b - (isW1 ? MB_TW1 : MB_TE);
        const float* src = isW1 ? W1 : E;
        bf16* hi = isW1 ? g_W1Thi : g_EThi;
        bf16* lo = isW1 ? g_W1Tlo : g_ETlo;
        __shared__ float t[32][33];
        int kb = (bb & 7) * 32, nb = (bb >> 3) * 32;
        int tx = tid & 31, ty = tid >> 5;
        #pragma unroll
        for (int rr = 0; rr < 32; rr += 8)
            t[ty + rr][tx] = src[(size_t)(kb + ty + rr) * OUT_F + nb + tx];
        __syncthreads();
        #pragma unroll
        for (int rr = 0; rr < 32; rr += 8) {
            int n = nb + ty + rr;
            bf16 h, l;
            fsplit(t[tx][ty + rr], h, l);
            hi[(size_t)n * IN_F + kb + tx] = h;
            lo[(size_t)n * IN_F + kb + tx] = l;
        }
    } else {
        int p = b - MB_MKC;
        float s = 0.f;
        for (int j = p * 250; j < (p + 1) * 250; j++)
            s += kc[(size_t)j * IN_F + tid];
        g_mkcp[p][tid] = s;
    }
}

// ---------------- rowdot_both + colmean ----------------
#define RB_E2  1250
#define RB_CM  1506
#define RB_TOT 1507
__global__ void rowdot_both_kernel(const float* __restrict__ ex, const float* __restrict__ kc,
                                   const float* __restrict__ W1)
{
    int b = blockIdx.x, tid = threadIdx.x;
    int lane = tid & 31, warp = tid >> 5;
    if (b < RB_E2) {
        int i = b * 8 + warp;
        if (i >= N_E) return;
        const float* row = ex + (size_t)i * IN_F;
        float s = 0.f;
        #pragma unroll
        for (int k = lane; k < IN_F; k += 32) s += row[k] * g_v1[k];
        #pragma unroll
        for (int o = 16; o; o >>= 1) s += __shfl_xor_sync(0xFFFFFFFFu, s, o);
        if (lane == 0) {
            g_e1[i] = s;
            g_Ae[i] = __expf(s);
            g_Ce[i] = __expf(ALPHA * s);
        }
    } else if (b < RB_CM) {
        int j = (b - RB_E2) * 8 + warp;
        if (j >= NKC_PAD) return;
        if (j < N_KC) {
            const float* row = kc + (size_t)j * IN_F;
            float s = 0.f;
            #pragma unroll
            for (int k = lane; k < IN_F; k += 32) s += row[k] * g_v2[k];
            #pragma unroll
            for (int o = 16; o; o >>= 1) s += __shfl_xor_sync(0xFFFFFFFFu, s, o);
            if (lane == 0)
                g_tab[j] = make_float2(__expf(s), __expf(ALPHA * s));
        } else if (lane == 0) {
            g_tab[j] = make_float2(0.f, 0.f);
        }
    } else {
        __shared__ float S[IN_F];
        float s = 0.f;
        #pragma unroll
        for (int p = 0; p < 8; p++) s += g_mkcp[p][tid];
        S[tid] = s;
        __syncthreads();
        float c = 0.f;
        #pragma unroll 8
        for (int k = 0; k < IN_F; k++)
            c += S[k] * W1[(size_t)k * OUT_F + tid];
        g_colmean[tid] = c * (1.0f / N_KC);
    }
}

// ---------------- conv: kcWh -> chunk-blocked bf16 hi/lo ----------------
__global__ void conv_kernel(const float* __restrict__ kcWh)
{
    __shared__ float t[32][33];
    int jb = blockIdx.x * 32, nb = blockIdx.y * 32;
    int tx = threadIdx.x & 31, ty = threadIdx.x >> 5;
    #pragma unroll
    for (int rr = 0; rr < 32; rr += 8) {
        int j = jb + ty + rr, n = nb + tx;
        t[ty + rr][tx] = (j < N_KC) ? kcWh[(size_t)j * OUT_F + n] : 0.f;
    }
    __syncthreads();
    #pragma unroll
    for (int rr = 0; rr < 32; rr += 8) {
        int n = nb + ty + rr;
        bf16 h, l;
        fsplit(t[tx][ty + rr], h, l);
        size_t di = ((size_t)(jb >> 5) * 256 + n) * KC + tx;
        g_kcWhT_hi[di] = h;
        g_kcWhT_lo[di] = l;
    }
}

// ---------------- hgemm body (128x128 tile, 8 warps 4Mx2N) ----------------
#define HOF_AH 0
#define HOF_AL 10240
#define HOF_BH 20480
#define HOF_BL 30720
static __device__ __forceinline__ void hgemm_body(char* smem,
    const bf16* __restrict__ Ahi, const bf16* __restrict__ Alo,
    const bf16* __restrict__ Bhi, const bf16* __restrict__ Blo,
    float* __restrict__ C, int M, int N, int K,
    const float* __restrict__ bias, int epi, const float* __restrict__ exF,
    int bx, int by)
{
    uint32_t sb = smem_u32(smem);
    int tid = threadIdx.x, lane = tid & 31, wid = tid >> 5;
    int bm = by * 128, bn = bx * 128;
    int wm = wid >> 1, wn = wid & 1;
    size_t astr = (epi == 1) ? 256 : (size_t)K;

    float acc[2][8][4];
    #pragma unroll
    for (int mt = 0; mt < 2; mt++)
        #pragma unroll
        for (int nb = 0; nb < 8; nb++)
            #pragma unroll
            for (int k = 0; k < 4; k++) acc[mt][nb][k] = 0.f;

    int crow = tid >> 1, chalf = tid & 1;
    bool arow_ok = (bm + crow) < M;
    const uint4 zero4 = make_uint4(0, 0, 0, 0);

    for (int k0 = 0; k0 < K; k0 += 32) {
        {
            char* dh = smem + HOF_AH + crow * RSTRIDE + chalf * 32;
            char* dl = smem + HOF_AL + crow * RSTRIDE + chalf * 32;
            if (!arow_ok) {
                ((uint4*)dh)[0] = zero4; ((uint4*)dh)[1] = zero4;
                ((uint4*)dl)[0] = zero4; ((uint4*)dl)[1] = zero4;
            } else if (epi == 1 && k0 >= 256) {
                size_t rb = (size_t)(bm + crow) * 256 + (k0 - 256) + chalf * 16;
                uint4 vh[2], vl[2];
                float4 vx[4];
                vh[0] = *(const uint4*)(Ahi + rb); vh[1] = *(const uint4*)(Ahi + rb + 8);
                vl[0] = *(const uint4*)(Alo + rb); vl[1] = *(const uint4*)(Alo + rb + 8);
                vx[0] = *(const float4*)(exF + rb);      vx[1] = *(const float4*)(exF + rb + 4);
                vx[2] = *(const float4*)(exF + rb + 8);  vx[3] = *(const float4*)(exF + rb + 12);
                const bf16* ph = (const bf16*)vh;
                const bf16* pl = (const bf16*)vl;
                const float* px = (const float*)vx;
                uint32_t oh[8], ol[8];
                #pragma unroll
                for (int e = 0; e < 8; e++) {
                    float q0 = (__bfloat162float(ph[2*e])   + __bfloat162float(pl[2*e]))   * px[2*e];
                    float q1 = (__bfloat162float(ph[2*e+1]) + __bfloat162float(pl[2*e+1])) * px[2*e+1];
                    bf16 H0, L0, H1, L1;
                    fsplit(q0, H0, L0); fsplit(q1, H1, L1);
                    oh[e] = pack2(H0, H1);
                    ol[e] = pack2(L0, L1);
                }
                ((uint4*)dh)[0] = *(uint4*)&oh[0]; ((uint4*)dh)[1] = *(uint4*)&oh[4];
                ((uint4*)dl)[0] = *(uint4*)&ol[0]; ((uint4*)dl)[1] = *(uint4*)&ol[4];
            } else {
                const uint4* sh = (const uint4*)(Ahi + (size_t)(bm + crow) * astr + k0 + chalf * 16);
                const uint4* sl = (const uint4*)(Alo + (size_t)(bm + crow) * astr + k0 + chalf * 16);
                ((uint4*)dh)[0] = sh[0]; ((uint4*)dh)[1] = sh[1];
                ((uint4*)dl)[0] = sl[0]; ((uint4*)dl)[1] = sl[1];
            }
        }
        {
            const uint4* sh = (const uint4*)(Bhi + (size_t)(bn + crow) * K + k0 + chalf * 16);
            const uint4* sl = (const uint4*)(Blo + (size_t)(bn + crow) * K + k0 + chalf * 16);
            char* dh = smem + HOF_BH + crow * RSTRIDE + chalf * 32;
            char* dl = smem + HOF_BL + crow * RSTRIDE + chalf * 32;
            ((uint4*)dh)[0] = sh[0]; ((uint4*)dh)[1] = sh[1];
            ((uint4*)dl)[0] = sl[0]; ((uint4*)dl)[1] = sl[1];
        }
        __syncthreads();

        #pragma unroll
        for (int ks = 0; ks < 2; ks++) {
            uint32_t ahi[2][4], alo[2][4], bfrag[8][2];
            int arowi = lane & 15;
            int akoff = (ks * 16 + ((lane >> 4) & 1) * 8) * 2;
            #pragma unroll
            for (int mt = 0; mt < 2; mt++) {
                uint32_t ad = sb + HOF_AH + (wm * 32 + mt * 16 + arowi) * RSTRIDE + akoff;
                LDSM_X4(ahi[mt][0], ahi[mt][1], ahi[mt][2], ahi[mt][3], ad);
                ad += (HOF_AL - HOF_AH);
                LDSM_X4(alo[mt][0], alo[mt][1], alo[mt][2], alo[mt][3], ad);
            }
            int bnrow = (lane & 7) + ((lane >> 4) << 3);
            int bkoff = (ks * 16 + ((lane >> 3) & 1) * 8) * 2;
            #pragma unroll
            for (int nq = 0; nq < 4; nq++) {
                uint32_t bd = sb + HOF_BH + (wn * 64 + nq * 16 + bnrow) * RSTRIDE + bkoff;
                LDSM_X4(bfrag[2 * nq][0], bfrag[2 * nq][1],
                        bfrag[2 * nq + 1][0], bfrag[2 * nq + 1][1], bd);
            }
            #pragma unroll
            for (int mt = 0; mt < 2; mt++)
                #pragma unroll
                for (int nb = 0; nb < 8; nb++)
                    mma_bf16(acc[mt][nb], ahi[mt], bfrag[nb]);
            #pragma unroll
            for (int mt = 0; mt < 2; mt++)
                #pragma unroll
                for (int nb = 0; nb < 8; nb++)
                    mma_bf16(acc[mt][nb], alo[mt], bfrag[nb]);
            #pragma unroll
            for (int nq = 0; nq < 4; nq++) {
                uint32_t bd = sb + HOF_BL + (wn * 64 + nq * 16 + bnrow) * RSTRIDE + bkoff;
                LDSM_X4(bfrag[2 * nq][0], bfrag[2 * nq][1],
                        bfrag[2 * nq + 1][0], bfrag[2 * nq + 1][1], bd);
            }
            #pragma unroll
            for (int mt = 0; mt < 2; mt++)
                #pragma unroll
                for (int nb = 0; nb < 8; nb++)
                    mma_bf16(acc[mt][nb], ahi[mt], bfrag[nb]);
        }
        __syncthreads();
    }

    #pragma unroll
    for (int mt = 0; mt < 2; mt++) {
        #pragma unroll
        for (int nb = 0; nb < 8; nb++) {
            int row0 = wm * 32 + mt * 16 + (lane >> 2);
            int col = bn + wn * 64 + nb * 8 + (lane & 3) * 2;
            #pragma unroll
            for (int h = 0; h < 2; h++) {
                int r = bm + row0 + h * 8;
                if (r >= M) continue;
                float v0 = acc[mt][nb][2 * h];
                float v1 = acc[mt][nb][2 * h + 1];
                if (epi == 1) {
                    v0 += bias[col];
                    v1 += bias[col + 1];
                    v0 = v0 > 0.f ? v0 : expm1f(v0);
                    v1 = v1 > 0.f ? v1 : expm1f(v1);
                }
                C[(size_t)r * N + col]     = v0;
                C[(size_t)r * N + col + 1] = v1;
            }
        }
    }
}

__global__ __launch_bounds__(256, 2) void hgemm_kernel(
    const bf16* __restrict__ Ahi, const bf16* __restrict__ Alo,
    const bf16* __restrict__ Bhi, const bf16* __restrict__ Blo,
    float* __restrict__ C, int M, int N, int K,
    const float* __restrict__ bias, int epi, const float* __restrict__ exF)
{
    extern __shared__ char smem[];
    hgemm_body(smem, Ahi, Alo, Bhi, Blo, C, M, N, K, bias, epi, exF,
               blockIdx.x, blockIdx.y);
}

// ---------------- attention body: cp.async double-buffered, 1 sync/chunk ----------------
// smem: Bbuf[2] @ 0 (each 40960: hi +0, lo +20480); Abuf[2] @ 81920 (each 10240: hi+0, lo+5120)
#define AOF_B    0
#define AOF_BSZ  40960
#define AOF_BLO  20480
#define AOF_A    81920
#define AOF_ASZ  10240
#define AOF_ALO  5120
#define AOF_E1   102400
#define AOF_AE   102656
#define AOF_CE   102912
#define AOF_RS   103168
#define AOF_RSF  104192
#define SMEM_ATTN 104448

static __device__ __forceinline__ void cp_b_chunk(uint32_t sbB, int c, int tid)
{
    // row tid of chunk c: 64B hi + 64B lo via 8 cp.async of 16B
    const bf16* sh = g_kcWhT_hi + ((size_t)c * 256 + tid) * KC;
    const bf16* sl = g_kcWhT_lo + ((size_t)c * 256 + tid) * KC;
    uint32_t dh = sbB + tid * RSTRIDE;
    uint32_t dl = dh + AOF_BLO;
    #pragma unroll
    for (int t = 0; t < 4; t++) {
        CP_ASYNC16(dh + t * 16, (const char*)sh + t * 16);
        CP_ASYNC16(dl + t * 16, (const char*)sl + t * 16);
    }
    CP_COMMIT();
}

static __device__ __forceinline__ void attn_body(char* smem, int tile,
    const float* __restrict__ e1, const int* __restrict__ adj)
{
    uint32_t sb = smem_u32(smem);
    float* e1s = (float*)(smem + AOF_E1);
    float* Aes = (float*)(smem + AOF_AE);
    float* Ces = (float*)(smem + AOF_CE);

    int tid = threadIdx.x, lane = tid & 31, wid = tid >> 5;
    int i0 = tile * MT;

    // kick off B(0) immediately
    cp_b_chunk(sb + AOF_B, 0, tid);

    if (tid < MT) {
        int gi = i0 + tid;
        bool v = gi < N_E;
        e1s[tid] = v ? e1[gi] : 0.f;
        Aes[tid] = v ? g_Ae[gi] : 0.f;
        Ces[tid] = v ? g_Ce[gi] : 0.f;
    }
    __syncthreads();

    int r = tid >> 2, jl0 = (tid & 3) * 8;
    int gi_r = i0 + r;
    const int* arow = adj + (size_t)(gi_r < N_E ? gi_r : 0) * N_KC;
    float Ai = Aes[r], Ci = Ces[r];
    float srow = 0.f;

    int wm = wid & 1, wn = wid >> 1;
    float acc[2][8][4];
    #pragma unroll
    for (int mt = 0; mt < 2; mt++)
        #pragma unroll
        for (int nb = 0; nb < 8; nb++)
            #pragma unroll
            for (int k = 0; k < 4; k++) acc[mt][nb][k] = 0.f;

    for (int c = 0; c < NCHUNK_RUN; c++) {
        int buf = c & 1;
        int j0 = c * KC;
        uint32_t aBase = sb + AOF_A + buf * AOF_ASZ;

        // ---- P-gen into A buffer (chunk c)
        {
            float p[8];
            if (j0 + KC <= N_KC) {
                const int4* ap = (const int4*)(arow + j0 + jl0);
                int4 a0 = ap[0], a1 = ap[1];
                int am[8] = {a0.x, a0.y, a0.z, a0.w, a1.x, a1.y, a1.z, a1.w};
                #pragma unroll
                for (int e = 0; e < 8; e++) {
                    float2 t = __ldg(&g_tab[j0 + jl0 + e]);
                    float pv = Ai * t.x;
                    float v = (pv > 1.f) ? pv : Ci * t.y;
                    p[e] = (am[e] > 0) ? v : 0.f;
                }
            } else {
                #pragma unroll
                for (int e = 0; e < 8; e++) {
                    int j = j0 + jl0 + e;
                    int m = (j < N_KC) ? arow[j] : 0;
                    float2 t = __ldg(&g_tab[(j < N_KC) ? j : 0]);
                    float pv = Ai * t.x;
                    float v = (pv > 1.f) ? pv : Ci * t.y;
                    p[e] = (m > 0) ? v : 0.f;
                }
            }
            #pragma unroll
            for (int e = 0; e < 8; e++) srow += p[e];
            uint32_t oh[4], ol[4];
            #pragma unroll
            for (int e = 0; e < 4; e++) {
                bf16 h0, l0, h1, l1;
                fsplit(p[2*e], h0, l0); fsplit(p[2*e+1], h1, l1);
                oh[e] = pack2(h0, h1);
                ol[e] = pack2(l0, l1);
            }
            char* ph = smem + AOF_A + buf * AOF_ASZ + r * RSTRIDE + jl0 * 2;
            ((uint2*)ph)[0] = make_uint2(oh[0], oh[1]);
            ((uint2*)ph)[1] = make_uint2(oh[2], oh[3]);
            char* pl = ph + AOF_ALO;
            ((uint2*)pl)[0] = make_uint2(ol[0], ol[1]);
            ((uint2*)pl)[1] = make_uint2(ol[2], ol[3]);
        }

        CP_WAIT0();          // B(c) landed
        __syncthreads();     // A(c) + B(c) visible to all

        if (c + 1 < NCHUNK_RUN)
            cp_b_chunk(sb + AOF_B + (buf ^ 1) * AOF_BSZ, c + 1, tid);

        // ---- MMA on buffer `buf`
        uint32_t bBase = sb + AOF_B + buf * AOF_BSZ;
        #pragma unroll
        for (int ks = 0; ks < 2; ks++) {
            uint32_t ahi[2][4], alo[2][4], bfrag[8][2];
            int arowi = lane & 15;
            int akoff = (ks * 16 + ((lane >> 4) & 1) * 8) * 2;
            #pragma unroll
            for (int mt = 0; mt < 2; mt++) {
                uint32_t ad = aBase + (wm * 32 + mt * 16 + arowi) * RSTRIDE + akoff;
                LDSM_X4(ahi[mt][0], ahi[mt][1], ahi[mt][2], ahi[mt][3], ad);
                ad += AOF_ALO;
                LDSM_X4(alo[mt][0], alo[mt][1], alo[mt][2], alo[mt][3], ad);
            }
            int bnrow = (lane & 7) + ((lane >> 4) << 3);
            int bkoff = (ks * 16 + ((lane >> 3) & 1) * 8) * 2;
            #pragma unroll
            for (int nq = 0; nq < 4; nq++) {
                uint32_t bd = bBase + (wn * 64 + nq * 16 + bnrow) * RSTRIDE + bkoff;
                LDSM_X4(bfrag[2 * nq][0], bfrag[2 * nq][1],
                        bfrag[2 * nq + 1][0], bfrag[2 * nq + 1][1], bd);
            }
            #pragma unroll
            for (int mt = 0; mt < 2; mt++)
                #pragma unroll
                for (int nb = 0; nb < 8; nb++)
                    mma_bf16(acc[mt][nb], ahi[mt], bfrag[nb]);
            #pragma unroll
            for (int mt = 0; mt < 2; mt++)
                #pragma unroll
                for (int nb = 0; nb < 8; nb++)
                    mma_bf16(acc[mt][nb], alo[mt], bfrag[nb]);
            #pragma unroll
            for (int nq = 0; nq < 4; nq++) {
                uint32_t bd = bBase + AOF_BLO + (wn * 64 + nq * 16 + bnrow) * RSTRIDE + bkoff;
                LDSM_X4(bfrag[2 * nq][0], bfrag[2 * nq][1],
                        bfrag[2 * nq + 1][0], bfrag[2 * nq + 1][1], bd);
            }
            #pragma unroll
            for (int mt = 0; mt < 2; mt++)
                #pragma unroll
                for (int nb = 0; nb < 8; nb++)
                    mma_bf16(acc[mt][nb], ahi[mt], bfrag[nb]);
        }
    }

    __syncthreads();
    ((float*)(smem + AOF_RS))[tid] = srow;
    __syncthreads();
    if (tid < MT) {
        const float* r4 = (const float*)(smem + AOF_RS) + tid * 4;
        ((float*)(smem + AOF_RSF))[tid] = (r4[0] + r4[1]) + (r4[2] + r4[3]);
    }
    __syncthreads();
    const float* rsF = (const float*)(smem + AOF_RSF);

    #pragma unroll
    for (int mt = 0; mt < 2; mt++) {
        #pragma unroll
        for (int nb = 0; nb < 8; nb++) {
            int row0 = wm * 32 + mt * 16 + (lane >> 2);
            int col  = wn * 64 + nb * 8 + (lane & 3) * 2;
            #pragma unroll
            for (int h = 0; h < 2; h++) {
                int rr = row0 + h * 8;
                int gi = i0 + rr;
                if (gi >= N_E) continue;
                float v0 = acc[mt][nb][2 * h];
                float v1 = acc[mt][nb][2 * h + 1];
                float rs = rsF[rr];
                float nk0, nk1;
                if (rs > 0.f) {
                    float ri = 1.f / rs;
                    nk0 = v0 * ri;
                    nk1 = v1 * ri;
                } else {
                    nk0 = g_colmean[col];
                    nk1 = g_colmean[col + 1];
                }
                size_t fb = (size_t)gi * OUT_F + col;
                bf16 h0, l0, h1, l1;
                fsplit(nk0, h0, l0); fsplit(nk1, h1, l1);
                *(uint32_t*)(g_feathi + fb) = pack2(h0, h1);
                *(uint32_t*)(g_featlo + fb) = pack2(l0, l1);
            }
        }
    }
}

// ---------------- fused kernel: attention first, then exEh GEMM tail ----------------
__global__ __launch_bounds__(256, 2) void attn_fused_kernel(
    const float* __restrict__ e1, const int* __restrict__ adj)
{
    extern __shared__ char smem[];
    if (blockIdx.x < NATTN) {
        attn_body(smem, (int)blockIdx.x, e1, adj);
    } else {
        int g = blockIdx.x - NATTN;
        hgemm_body(smem, g_exhi, g_exlo, g_EThi, g_ETlo, (float*)g_exEh,
                   N_E, OUT_F, IN_F, nullptr, 0, nullptr, g & 1, g >> 1);
    }
}

// ---------------- launch ----------------
extern "C" void kernel_launch(void* const* d_in, const int* in_sizes, int n_in,
                              void* d_out, int out_size)
{
    const float* ex   = (const float*)d_in[0];
    const float* kc   = (const float*)d_in[1];
    const int*   adj  = (const int*)d_in[2];
    const float* W1   = (const float*)d_in[3];
    const float* E    = (const float*)d_in[4];
    const float* a    = (const float*)d_in[5];
    const float* rd_w = (const float*)d_in[6];
    const float* rd_b = (const float*)d_in[7];
    float* out = (float*)d_out;

    float *kcWh, *exEh, *e1;
    bf16 *kchi, *kclo, *W1Thi, *W1Tlo, *rdwhi, *rdwlo, *feathi, *featlo;
    cudaGetSymbolAddress((void**)&kcWh, g_kcWh);
    cudaGetSymbolAddress((void**)&exEh, g_exEh);
    cudaGetSymbolAddress((void**)&e1, g_e1);
    cudaGetSymbolAddress((void**)&kchi, g_kchi);
    cudaGetSymbolAddress((void**)&kclo, g_kclo);
    cudaGetSymbolAddress((void**)&W1Thi, g_W1Thi);
    cudaGetSymbolAddress((void**)&W1Tlo, g_W1Tlo);
    cudaGetSymbolAddress((void**)&rdwhi, g_rdwhi);
    cudaGetSymbolAddress((void**)&rdwlo, g_rdwlo);
    cudaGetSymbolAddress((void**)&feathi, g_feathi);
    cudaGetSymbolAddress((void**)&featlo, g_featlo);

    cudaFuncSetAttribute(attn_fused_kernel,
                         cudaFuncAttributeMaxDynamicSharedMemorySize, SMEM_ATTN);
    cudaFuncSetAttribute(hgemm_kernel,
                         cudaFuncAttributeMaxDynamicSharedMemorySize, 40960);

    // 0. prep + splits + kc colsum partials
    mega_kernel<<<MB_TOT, 256>>>(ex, kc, rd_w, W1, E, a);

    // 1. kc_Wh = kc @ W1   [2000,256]
    hgemm_kernel<<<dim3(OUT_F / 128, (N_KC + 127) / 128), 256, 40960>>>(
        kchi, kclo, W1Thi, W1Tlo, kcWh, N_KC, OUT_F, IN_F, nullptr, 0, nullptr);

    // 2. e1/e2 rowdots + exp tables + colmean
    rowdot_both_kernel<<<RB_TOT, 256>>>(ex, kc, W1);

    // 3. kcWh -> chunk-blocked transposed bf16 hi/lo
    conv_kernel<<<dim3(NKC_PAD / 32, OUT_F / 32), 256>>>(kcWh);

    // 4. fused: attention (157 blocks) + exEh GEMM (158 blocks)
    attn_fused_kernel<<<NATTN + NGEX, 256, SMEM_ATTN>>>(e1, adj);

    // 5. out = elu([nk | nk*exEh] @ rd_w^T + rd_b)   [10000,256]
    hgemm_kernel<<<dim3(OUT_F / 128, (N_E + 127) / 128), 256, 40960>>>(
        feathi, featlo, rdwhi, rdwlo, out, N_E, OUT_F, 2 * OUT_F, rd_b, 1, exEh);
}

// round 11
// speedup vs baseline: 1.7429x; 1.2240x over previous
#include <cuda_runtime.h>
#include <cuda_bf16.h>
#include <cuda_fp16.h>
#include <math.h>
#include <stdint.h>

#define IN_F   256
#define OUT_F  256
#define N_E    10000
#define N_KC   2000
#define ALPHA  0.2f

#define MT      64
#define KC      32
#define NKC_PAD 2048
#define NCHUNK_RUN 63
#define RSTRIDE 80

#define NGEX    158
#define NATTN   157

typedef __nv_bfloat16 bf16;

// ---------------- scratch ----------------
__device__ float g_kcWh[N_KC * OUT_F];
__device__ float g_exEh[N_E * OUT_F];
__device__ float g_v1[IN_F];
__device__ float g_v2[IN_F];
__device__ __half g_kcWhT_hi[OUT_F * NKC_PAD];   // fp16 hi, chunk-blocked transposed
__device__ __half g_kcWhT_lo[OUT_F * NKC_PAD];   // fp16 lo
__device__ float g_colmean[OUT_F];
__device__ float g_mkcp[8][IN_F];
__device__ float g_Ae[N_E];
__device__ float g_Ce[N_E];
__device__ float2 g_tab[NKC_PAD];   // (exp(e2), exp(ALPHA*e2)), zero-padded
__device__ bf16 g_exhi[N_E * IN_F];
__device__ bf16 g_exlo[N_E * IN_F];
__device__ bf16 g_kchi[N_KC * IN_F];
__device__ bf16 g_kclo[N_KC * IN_F];
__device__ bf16 g_W1Thi[OUT_F * IN_F];
__device__ bf16 g_W1Tlo[OUT_F * IN_F];
__device__ bf16 g_EThi[OUT_F * IN_F];
__device__ bf16 g_ETlo[OUT_F * IN_F];
__device__ bf16 g_rdwhi[OUT_F * 2 * OUT_F];
__device__ bf16 g_rdwlo[OUT_F * 2 * OUT_F];
__device__ bf16 g_feathi[N_E * OUT_F];
__device__ bf16 g_featlo[N_E * OUT_F];

// ---------------- helpers ----------------
static __device__ __forceinline__ uint32_t smem_u32(const void* p) {
    uint32_t a;
    asm("{ .reg .u64 t; cvta.to.shared.u64 t, %1; cvt.u32.u64 %0, t; }" : "=r"(a) : "l"(p));
    return a;
}
#define LDSM_X4(R0,R1,R2,R3,ADDR) \
    asm volatile("ldmatrix.sync.aligned.m8n8.x4.shared.b16 {%0,%1,%2,%3}, [%4];" \
                 : "=r"(R0),"=r"(R1),"=r"(R2),"=r"(R3) : "r"(ADDR))
#define CP_ASYNC16(dst, src) \
    asm volatile("cp.async.ca.shared.global [%0], [%1], 16;" :: "r"(dst), "l"(src))
#define CP_COMMIT() asm volatile("cp.async.commit_group;" ::: "memory")
#define CP_WAIT0()  asm volatile("cp.async.wait_group 0;" ::: "memory")

static __device__ __forceinline__ void mma_bf16(float* c, const uint32_t* a, const uint32_t* b) {
    asm volatile(
        "mma.sync.aligned.m16n8k16.row.col.f32.bf16.bf16.f32 "
        "{%0,%1,%2,%3}, {%4,%5,%6,%7}, {%8,%9}, {%0,%1,%2,%3};"
        : "+f"(c[0]), "+f"(c[1]), "+f"(c[2]), "+f"(c[3])
        : "r"(a[0]), "r"(a[1]), "r"(a[2]), "r"(a[3]), "r"(b[0]), "r"(b[1]));
}
static __device__ __forceinline__ void mma_fp16(float* c, const uint32_t* a, const uint32_t* b) {
    asm volatile(
        "mma.sync.aligned.m16n8k16.row.col.f32.f16.f16.f32 "
        "{%0,%1,%2,%3}, {%4,%5,%6,%7}, {%8,%9}, {%0,%1,%2,%3};"
        : "+f"(c[0]), "+f"(c[1]), "+f"(c[2]), "+f"(c[3])
        : "r"(a[0]), "r"(a[1]), "r"(a[2]), "r"(a[3]), "r"(b[0]), "r"(b[1]));
}
static __device__ __forceinline__ void fsplit(float v, bf16& h, bf16& l) {
    h = __float2bfloat16(v);
    l = __float2bfloat16(v - __bfloat162float(h));
}
static __device__ __forceinline__ uint32_t pack2(bf16 a, bf16 b) {
    __nv_bfloat162 t = __halves2bfloat162(a, b);
    return *(uint32_t*)&t;
}
static __device__ __forceinline__ void split4_store(const float4 v, bf16* hi, bf16* lo) {
    bf16 h0, l0, h1, l1, h2, l2, h3, l3;
    fsplit(v.x, h0, l0); fsplit(v.y, h1, l1);
    fsplit(v.z, h2, l2); fsplit(v.w, h3, l3);
    *(uint32_t*)(hi)     = pack2(h0, h1);
    *(uint32_t*)(hi + 2) = pack2(h2, h3);
    *(uint32_t*)(lo)     = pack2(l0, l1);
    *(uint32_t*)(lo + 2) = pack2(l2, l3);
}

// ---------------- mega kernel ----------------
#define MB_EX   1
#define MB_KC   2501
#define MB_RDW  3001
#define MB_TW1  3129
#define MB_TE   3193
#define MB_MKC  3257
#define MB_TOT  3265
__global__ void mega_kernel(const float* __restrict__ ex, const float* __restrict__ kc,
                            const float* __restrict__ rdw, const float* __restrict__ W1,
                            const float* __restrict__ E, const float* __restrict__ a)
{
    int b = blockIdx.x, tid = threadIdx.x;
    if (b < MB_EX) {
        int k = tid;
        float s1 = 0.f, s2 = 0.f;
        #pragma unroll 8
        for (int j = 0; j < OUT_F; j++) {
            float w = W1[k * OUT_F + j];
            s1 += w * a[j];
            s2 += w * a[OUT_F + j];
        }
        g_v1[k] = s1;
        g_v2[k] = s2;
    } else if (b < MB_KC) {
        size_t i = ((size_t)(b - MB_EX) * 256 + tid) * 4;
        split4_store(*(const float4*)(ex + i), g_exhi + i, g_exlo + i);
    } else if (b < MB_RDW) {
        size_t i = ((size_t)(b - MB_KC) * 256 + tid) * 4;
        split4_store(*(const float4*)(kc + i), g_kchi + i, g_kclo + i);
    } else if (b < MB_TW1) {
        size_t i = ((size_t)(b - MB_RDW) * 256 + tid) * 4;
        split4_store(*(const float4*)(rdw + i), g_rdwhi + i, g_rdwlo + i);
    } else if (b < MB_MKC) {
        bool isW1 = b < MB_TE;
        int bb = b - (isW1 ? MB_TW1 : MB_TE);
        const float* src = isW1 ? W1 : E;
        bf16* hi = isW1 ? g_W1Thi : g_EThi;
        bf16* lo = isW1 ? g_W1Tlo : g_ETlo;
        __shared__ float t[32][33];
        int kb = (bb & 7) * 32, nb = (bb >> 3) * 32;
        int tx = tid & 31, ty = tid >> 5;
        #pragma unroll
        for (int rr = 0; rr < 32; rr += 8)
            t[ty + rr][tx] = src[(size_t)(kb + ty + rr) * OUT_F + nb + tx];
        __syncthreads();
        #pragma unroll
        for (int rr = 0; rr < 32; rr += 8) {
            int n = nb + ty + rr;
            bf16 h, l;
            fsplit(t[tx][ty + rr], h, l);
            hi[(size_t)n * IN_F + kb + tx] = h;
            lo[(size_t)n * IN_F + kb + tx] = l;
        }
    } else {
        int p = b - MB_MKC;
        float s = 0.f;
        for (int j = p * 250; j < (p + 1) * 250; j++)
            s += kc[(size_t)j * IN_F + tid];
        g_mkcp[p][tid] = s;
    }
}

// ---------------- rowdot_both + colmean + conv(kcWh -> fp16 hi/lo) ----------------
#define RB_E2    1250
#define RB_CM    1506
#define RB_CONV0 1507
#define RB_TOT   2019      // + 512 conv blocks
__global__ void rowdot_both_kernel(const float* __restrict__ ex, const float* __restrict__ kc,
                                   const float* __restrict__ W1, const float* __restrict__ kcWh)
{
    int b = blockIdx.x, tid = threadIdx.x;
    int lane = tid & 31, warp = tid >> 5;
    if (b < RB_E2) {
        int i = b * 8 + warp;
        if (i >= N_E) return;
        const float* row = ex + (size_t)i * IN_F;
        float s = 0.f;
        #pragma unroll
        for (int k = lane; k < IN_F; k += 32) s += row[k] * g_v1[k];
        #pragma unroll
        for (int o = 16; o; o >>= 1) s += __shfl_xor_sync(0xFFFFFFFFu, s, o);
        if (lane == 0) {
            g_Ae[i] = __expf(s);
            g_Ce[i] = __expf(ALPHA * s);
        }
    } else if (b < RB_CM) {
        int j = (b - RB_E2) * 8 + warp;
        if (j >= NKC_PAD) return;
        if (j < N_KC) {
            const float* row = kc + (size_t)j * IN_F;
            float s = 0.f;
            #pragma unroll
            for (int k = lane; k < IN_F; k += 32) s += row[k] * g_v2[k];
            #pragma unroll
            for (int o = 16; o; o >>= 1) s += __shfl_xor_sync(0xFFFFFFFFu, s, o);
            if (lane == 0)
                g_tab[j] = make_float2(__expf(s), __expf(ALPHA * s));
        } else if (lane == 0) {
            g_tab[j] = make_float2(0.f, 0.f);
        }
    } else if (b < RB_CONV0) {
        __shared__ float S[IN_F];
        float s = 0.f;
        #pragma unroll
        for (int p = 0; p < 8; p++) s += g_mkcp[p][tid];
        S[tid] = s;
        __syncthreads();
        float c = 0.f;
        #pragma unroll 8
        for (int k = 0; k < IN_F; k++)
            c += S[k] * W1[(size_t)k * OUT_F + tid];
        g_colmean[tid] = c * (1.0f / N_KC);
    } else {
        // conv: kcWh fp32 -> chunk-blocked transposed fp16 hi/lo
        __shared__ float t[32][33];
        int bb = b - RB_CONV0;               // 0..511
        int jb = (bb & 63) * 32;             // 64 j-blocks
        int nb = (bb >> 6) * 32;             // 8 n-blocks
        int tx = tid & 31, ty = tid >> 5;
        #pragma unroll
        for (int rr = 0; rr < 32; rr += 8) {
            int j = jb + ty + rr, n = nb + tx;
            t[ty + rr][tx] = (j < N_KC) ? kcWh[(size_t)j * OUT_F + n] : 0.f;
        }
        __syncthreads();
        #pragma unroll
        for (int rr = 0; rr < 32; rr += 8) {
            int n = nb + ty + rr;
            float v = t[tx][ty + rr];
            __half h = __float2half_rn(v);
            __half l = __float2half_rn(v - __half2float(h));
            size_t di = ((size_t)(jb >> 5) * 256 + n) * KC + tx;
            g_kcWhT_hi[di] = h;
            g_kcWhT_lo[di] = l;
        }
    }
}

// ---------------- hgemm body (bf16 3-product, 128x128 tile, 8 warps 4Mx2N) ----------------
#define HOF_AH 0
#define HOF_AL 10240
#define HOF_BH 20480
#define HOF_BL 30720
static __device__ __forceinline__ void hgemm_body(char* smem,
    const bf16* __restrict__ Ahi, const bf16* __restrict__ Alo,
    const bf16* __restrict__ Bhi, const bf16* __restrict__ Blo,
    float* __restrict__ C, int M, int N, int K,
    const float* __restrict__ bias, int epi, const float* __restrict__ exF,
    int bx, int by)
{
    uint32_t sb = smem_u32(smem);
    int tid = threadIdx.x, lane = tid & 31, wid = tid >> 5;
    int bm = by * 128, bn = bx * 128;
    int wm = wid >> 1, wn = wid & 1;
    size_t astr = (epi == 1) ? 256 : (size_t)K;

    float acc[2][8][4];
    #pragma unroll
    for (int mt = 0; mt < 2; mt++)
        #pragma unroll
        for (int nb = 0; nb < 8; nb++)
            #pragma unroll
            for (int k = 0; k < 4; k++) acc[mt][nb][k] = 0.f;

    int crow = tid >> 1, chalf = tid & 1;
    bool arow_ok = (bm + crow) < M;
    const uint4 zero4 = make_uint4(0, 0, 0, 0);

    for (int k0 = 0; k0 < K; k0 += 32) {
        {
            char* dh = smem + HOF_AH + crow * RSTRIDE + chalf * 32;
            char* dl = smem + HOF_AL + crow * RSTRIDE + chalf * 32;
            if (!arow_ok) {
                ((uint4*)dh)[0] = zero4; ((uint4*)dh)[1] = zero4;
                ((uint4*)dl)[0] = zero4; ((uint4*)dl)[1] = zero4;
            } else if (epi == 1 && k0 >= 256) {
                size_t rb = (size_t)(bm + crow) * 256 + (k0 - 256) + chalf * 16;
                uint4 vh[2], vl[2];
                float4 vx[4];
                vh[0] = *(const uint4*)(Ahi + rb); vh[1] = *(const uint4*)(Ahi + rb + 8);
                vl[0] = *(const uint4*)(Alo + rb); vl[1] = *(const uint4*)(Alo + rb + 8);
                vx[0] = *(const float4*)(exF + rb);      vx[1] = *(const float4*)(exF + rb + 4);
                vx[2] = *(const float4*)(exF + rb + 8);  vx[3] = *(const float4*)(exF + rb + 12);
                const bf16* ph = (const bf16*)vh;
                const bf16* pl = (const bf16*)vl;
                const float* px = (const float*)vx;
                uint32_t oh[8], ol[8];
                #pragma unroll
                for (int e = 0; e < 8; e++) {
                    float q0 = (__bfloat162float(ph[2*e])   + __bfloat162float(pl[2*e]))   * px[2*e];
                    float q1 = (__bfloat162float(ph[2*e+1]) + __bfloat162float(pl[2*e+1])) * px[2*e+1];
                    bf16 H0, L0, H1, L1;
                    fsplit(q0, H0, L0); fsplit(q1, H1, L1);
                    oh[e] = pack2(H0, H1);
                    ol[e] = pack2(L0, L1);
                }
                ((uint4*)dh)[0] = *(uint4*)&oh[0]; ((uint4*)dh)[1] = *(uint4*)&oh[4];
                ((uint4*)dl)[0] = *(uint4*)&ol[0]; ((uint4*)dl)[1] = *(uint4*)&ol[4];
            } else {
                const uint4* sh = (const uint4*)(Ahi + (size_t)(bm + crow) * astr + k0 + chalf * 16);
                const uint4* sl = (const uint4*)(Alo + (size_t)(bm + crow) * astr + k0 + chalf * 16);
                ((uint4*)dh)[0] = sh[0]; ((uint4*)dh)[1] = sh[1];
                ((uint4*)dl)[0] = sl[0]; ((uint4*)dl)[1] = sl[1];
            }
        }
        {
            const uint4* sh = (const uint4*)(Bhi + (size_t)(bn + crow) * K + k0 + chalf * 16);
            const uint4* sl = (const uint4*)(Blo + (size_t)(bn + crow) * K + k0 + chalf * 16);
            char* dh = smem + HOF_BH + crow * RSTRIDE + chalf * 32;
            char* dl = smem + HOF_BL + crow * RSTRIDE + chalf * 32;
            ((uint4*)dh)[0] = sh[0]; ((uint4*)dh)[1] = sh[1];
            ((uint4*)dl)[0] = sl[0]; ((uint4*)dl)[1] = sl[1];
        }
        __syncthreads();

        #pragma unroll
        for (int ks = 0; ks < 2; ks++) {
            uint32_t ahi[2][4], alo[2][4], bfrag[8][2];
            int arowi = lane & 15;
            int akoff = (ks * 16 + ((lane >> 4) & 1) * 8) * 2;
            #pragma unroll
            for (int mt = 0; mt < 2; mt++) {
                uint32_t ad = sb + HOF_AH + (wm * 32 + mt * 16 + arowi) * RSTRIDE + akoff;
                LDSM_X4(ahi[mt][0], ahi[mt][1], ahi[mt][2], ahi[mt][3], ad);
                ad += (HOF_AL - HOF_AH);
                LDSM_X4(alo[mt][0], alo[mt][1], alo[mt][2], alo[mt][3], ad);
            }
            int bnrow = (lane & 7) + ((lane >> 4) << 3);
            int bkoff = (ks * 16 + ((lane >> 3) & 1) * 8) * 2;
            #pragma unroll
            for (int nq = 0; nq < 4; nq++) {
                uint32_t bd = sb + HOF_BH + (wn * 64 + nq * 16 + bnrow) * RSTRIDE + bkoff;
                LDSM_X4(bfrag[2 * nq][0], bfrag[2 * nq][1],
                        bfrag[2 * nq + 1][0], bfrag[2 * nq + 1][1], bd);
            }
            #pragma unroll
            for (int mt = 0; mt < 2; mt++)
                #pragma unroll
                for (int nb = 0; nb < 8; nb++)
                    mma_bf16(acc[mt][nb], ahi[mt], bfrag[nb]);
            #pragma unroll
            for (int mt = 0; mt < 2; mt++)
                #pragma unroll
                for (int nb = 0; nb < 8; nb++)
                    mma_bf16(acc[mt][nb], alo[mt], bfrag[nb]);
            #pragma unroll
            for (int nq = 0; nq < 4; nq++) {
                uint32_t bd = sb + HOF_BL + (wn * 64 + nq * 16 + bnrow) * RSTRIDE + bkoff;
                LDSM_X4(bfrag[2 * nq][0], bfrag[2 * nq][1],
                        bfrag[2 * nq + 1][0], bfrag[2 * nq + 1][1], bd);
            }
            #pragma unroll
            for (int mt = 0; mt < 2; mt++)
                #pragma unroll
                for (int nb = 0; nb < 8; nb++)
                    mma_bf16(acc[mt][nb], ahi[mt], bfrag[nb]);
        }
        __syncthreads();
    }

    #pragma unroll
    for (int mt = 0; mt < 2; mt++) {
        #pragma unroll
        for (int nb = 0; nb < 8; nb++) {
            int row0 = wm * 32 + mt * 16 + (lane >> 2);
            int col = bn + wn * 64 + nb * 8 + (lane & 3) * 2;
            #pragma unroll
            for (int h = 0; h < 2; h++) {
                int r = bm + row0 + h * 8;
                if (r >= M) continue;
                float v0 = acc[mt][nb][2 * h];
                float v1 = acc[mt][nb][2 * h + 1];
                if (epi == 1) {
                    v0 += bias[col];
                    v1 += bias[col + 1];
                    v0 = v0 > 0.f ? v0 : expm1f(v0);
                    v1 = v1 > 0.f ? v1 : expm1f(v1);
                }
                C[(size_t)r * N + col]     = v0;
                C[(size_t)r * N + col + 1] = v1;
            }
        }
    }
}

__global__ __launch_bounds__(256, 2) void hgemm_kernel(
    const bf16* __restrict__ Ahi, const bf16* __restrict__ Alo,
    const bf16* __restrict__ Bhi, const bf16* __restrict__ Blo,
    float* __restrict__ C, int M, int N, int K,
    const float* __restrict__ bias, int epi, const float* __restrict__ exF)
{
    extern __shared__ char smem[];
    hgemm_body(smem, Ahi, Alo, Bhi, Blo, C, M, N, K, bias, epi, exF,
               blockIdx.x, blockIdx.y);
}

// ---------------- attention body: fp16 2-product, cp.async double-buffered ----------------
#define AOF_B    0
#define AOF_BSZ  40960
#define AOF_BLO  20480
#define AOF_A    81920
#define AOF_ASZ  5120
#define AOF_AE   92160
#define AOF_CE   92416
#define AOF_RS   92672
#define AOF_RSF  93696
#define SMEM_ATTN 93952

static __device__ __forceinline__ void cp_b_chunk(uint32_t sbB, int c, int tid)
{
    const __half* sh = g_kcWhT_hi + ((size_t)c * 256 + tid) * KC;
    const __half* sl = g_kcWhT_lo + ((size_t)c * 256 + tid) * KC;
    uint32_t dh = sbB + tid * RSTRIDE;
    uint32_t dl = dh + AOF_BLO;
    #pragma unroll
    for (int t = 0; t < 4; t++) {
        CP_ASYNC16(dh + t * 16, (const char*)sh + t * 16);
        CP_ASYNC16(dl + t * 16, (const char*)sl + t * 16);
    }
    CP_COMMIT();
}

static __device__ __forceinline__ void attn_body(char* smem, int tile,
    const int* __restrict__ adj)
{
    uint32_t sb = smem_u32(smem);
    float* Aes = (float*)(smem + AOF_AE);
    float* Ces = (float*)(smem + AOF_CE);

    int tid = threadIdx.x, lane = tid & 31, wid = tid >> 5;
    int i0 = tile * MT;

    cp_b_chunk(sb + AOF_B, 0, tid);

    if (tid < MT) {
        int gi = i0 + tid;
        bool v = gi < N_E;
        Aes[tid] = v ? g_Ae[gi] : 0.f;
        Ces[tid] = v ? g_Ce[gi] : 0.f;
    }
    __syncthreads();

    int r = tid >> 2, jl0 = (tid & 3) * 8;
    int gi_r = i0 + r;
    const int* arow = adj + (size_t)(gi_r < N_E ? gi_r : 0) * N_KC;
    float Ai = Aes[r], Ci = Ces[r];
    float srow = 0.f;

    int wm = wid & 1, wn = wid >> 1;
    float acc[2][8][4];
    #pragma unroll
    for (int mt = 0; mt < 2; mt++)
        #pragma unroll
        for (int nb = 0; nb < 8; nb++)
            #pragma unroll
            for (int k = 0; k < 4; k++) acc[mt][nb][k] = 0.f;

    for (int c = 0; c < NCHUNK_RUN; c++) {
        int buf = c & 1;
        int j0 = c * KC;
        uint32_t aBase = sb + AOF_A + buf * AOF_ASZ;

        // ---- P-gen into A buffer (single fp16)
        {
            float p[8];
            if (j0 + KC <= N_KC) {
                const int4* ap = (const int4*)(arow + j0 + jl0);
                int4 a0 = ap[0], a1 = ap[1];
                int am[8] = {a0.x, a0.y, a0.z, a0.w, a1.x, a1.y, a1.z, a1.w};
                #pragma unroll
                for (int e = 0; e < 8; e++) {
                    float2 t = __ldg(&g_tab[j0 + jl0 + e]);
                    float pv = Ai * t.x;
                    float v = (pv > 1.f) ? pv : Ci * t.y;
                    p[e] = (am[e] > 0) ? v : 0.f;
                }
            } else {
                #pragma unroll
                for (int e = 0; e < 8; e++) {
                    int j = j0 + jl0 + e;
                    int m = (j < N_KC) ? arow[j] : 0;
                    float2 t = __ldg(&g_tab[(j < N_KC) ? j : 0]);
                    float pv = Ai * t.x;
                    float v = (pv > 1.f) ? pv : Ci * t.y;
                    p[e] = (m > 0) ? v : 0.f;
                }
            }
            #pragma unroll
            for (int e = 0; e < 8; e++) srow += p[e];
            __half2 q0 = __floats2half2_rn(p[0], p[1]);
            __half2 q1 = __floats2half2_rn(p[2], p[3]);
            __half2 q2 = __floats2half2_rn(p[4], p[5]);
            __half2 q3 = __floats2half2_rn(p[6], p[7]);
            uint4 w = make_uint4(*(uint32_t*)&q0, *(uint32_t*)&q1,
                                 *(uint32_t*)&q2, *(uint32_t*)&q3);
            *(uint4*)(smem + AOF_A + buf * AOF_ASZ + r * RSTRIDE + jl0 * 2) = w;
        }

        CP_WAIT0();
        __syncthreads();

        if (c + 1 < NCHUNK_RUN)
            cp_b_chunk(sb + AOF_B + (buf ^ 1) * AOF_BSZ, c + 1, tid);

        // ---- MMA: 2-product fp16 (P*Bh + P*Bl)
        uint32_t bBase = sb + AOF_B + buf * AOF_BSZ;
        #pragma unroll
        for (int ks = 0; ks < 2; ks++) {
            uint32_t af[2][4], bfrag[8][2];
            int arowi = lane & 15;
            int akoff = (ks * 16 + ((lane >> 4) & 1) * 8) * 2;
            #pragma unroll
            for (int mt = 0; mt < 2; mt++) {
                uint32_t ad = aBase + (wm * 32 + mt * 16 + arowi) * RSTRIDE + akoff;
                LDSM_X4(af[mt][0], af[mt][1], af[mt][2], af[mt][3], ad);
            }
            int bnrow = (lane & 7) + ((lane >> 4) << 3);
            int bkoff = (ks * 16 + ((lane >> 3) & 1) * 8) * 2;
            #pragma unroll
            for (int nq = 0; nq < 4; nq++) {
                uint32_t bd = bBase + (wn * 64 + nq * 16 + bnrow) * RSTRIDE + bkoff;
                LDSM_X4(bfrag[2 * nq][0], bfrag[2 * nq][1],
                        bfrag[2 * nq + 1][0], bfrag[2 * nq + 1][1], bd);
            }
            #pragma unroll
            for (int mt = 0; mt < 2; mt++)
                #pragma unroll
                for (int nb = 0; nb < 8; nb++)
                    mma_fp16(acc[mt][nb], af[mt], bfrag[nb]);
            #pragma unroll
            for (int nq = 0; nq < 4; nq++) {
                uint32_t bd = bBase + AOF_BLO + (wn * 64 + nq * 16 + bnrow) * RSTRIDE + bkoff;
                LDSM_X4(bfrag[2 * nq][0], bfrag[2 * nq][1],
                        bfrag[2 * nq + 1][0], bfrag[2 * nq + 1][1], bd);
            }
            #pragma unroll
            for (int mt = 0; mt < 2; mt++)
                #pragma unroll
                for (int nb = 0; nb < 8; nb++)
                    mma_fp16(acc[mt][nb], af[mt], bfrag[nb]);
        }
    }

    __syncthreads();
    ((float*)(smem + AOF_RS))[tid] = srow;
    __syncthreads();
    if (tid < MT) {
        const float* r4 = (const float*)(smem + AOF_RS) + tid * 4;
        ((float*)(smem + AOF_RSF))[tid] = (r4[0] + r4[1]) + (r4[2] + r4[3]);
    }
    __syncthreads();
    const float* rsF = (const float*)(smem + AOF_RSF);

    #pragma unroll
    for (int mt = 0; mt < 2; mt++) {
        #pragma unroll
        for (int nb = 0; nb < 8; nb++) {
            int row0 = wm * 32 + mt * 16 + (lane >> 2);
            int col  = wn * 64 + nb * 8 + (lane & 3) * 2;
            #pragma unroll
            for (int h = 0; h < 2; h++) {
                int rr = row0 + h * 8;
                int gi = i0 + rr;
                if (gi >= N_E) continue;
                float v0 = acc[mt][nb][2 * h];
                float v1 = acc[mt][nb][2 * h + 1];
                float rs = rsF[rr];
                float nk0, nk1;
                if (rs > 0.f) {
                    float ri = 1.f / rs;
                    nk0 = v0 * ri;
                    nk1 = v1 * ri;
                } else {
                    nk0 = g_colmean[col];
                    nk1 = g_colmean[col + 1];
                }
                size_t fb = (size_t)gi * OUT_F + col;
                bf16 h0, l0, h1, l1;
                fsplit(nk0, h0, l0); fsplit(nk1, h1, l1);
                *(uint32_t*)(g_feathi + fb) = pack2(h0, h1);
                *(uint32_t*)(g_featlo + fb) = pack2(l0, l1);
            }
        }
    }
}

// ---------------- fused kernel: attention first, exEh GEMM tail ----------------
__global__ __launch_bounds__(256, 2) void attn_fused_kernel(const int* __restrict__ adj)
{
    extern __shared__ char smem[];
    if (blockIdx.x < NATTN) {
        attn_body(smem, (int)blockIdx.x, adj);
    } else {
        int g = blockIdx.x - NATTN;
        hgemm_body(smem, g_exhi, g_exlo, g_EThi, g_ETlo, (float*)g_exEh,
                   N_E, OUT_F, IN_F, nullptr, 0, nullptr, g & 1, g >> 1);
    }
}

// ---------------- launch ----------------
extern "C" void kernel_launch(void* const* d_in, const int* in_sizes, int n_in,
                              void* d_out, int out_size)
{
    const float* ex   = (const float*)d_in[0];
    const float* kc   = (const float*)d_in[1];
    const int*   adj  = (const int*)d_in[2];
    const float* W1   = (const float*)d_in[3];
    const float* E    = (const float*)d_in[4];
    const float* a    = (const float*)d_in[5];
    const float* rd_w = (const float*)d_in[6];
    const float* rd_b = (const float*)d_in[7];
    float* out = (float*)d_out;

    float *kcWh, *exEh;
    bf16 *kchi, *kclo, *W1Thi, *W1Tlo, *rdwhi, *rdwlo, *feathi, *featlo;
    cudaGetSymbolAddress((void**)&kcWh, g_kcWh);
    cudaGetSymbolAddress((void**)&exEh, g_exEh);
    cudaGetSymbolAddress((void**)&kchi, g_kchi);
    cudaGetSymbolAddress((void**)&kclo, g_kclo);
    cudaGetSymbolAddress((void**)&W1Thi, g_W1Thi);
    cudaGetSymbolAddress((void**)&W1Tlo, g_W1Tlo);
    cudaGetSymbolAddress((void**)&rdwhi, g_rdwhi);
    cudaGetSymbolAddress((void**)&rdwlo, g_rdwlo);
    cudaGetSymbolAddress((void**)&feathi, g_feathi);
    cudaGetSymbolAddress((void**)&featlo, g_featlo);

    cudaFuncSetAttribute(attn_fused_kernel,
                         cudaFuncAttributeMaxDynamicSharedMemorySize, SMEM_ATTN);
    cudaFuncSetAttribute(hgemm_kernel,
                         cudaFuncAttributeMaxDynamicSharedMemorySize, 40960);

    // 0. prep + splits + kc colsum partials
    mega_kernel<<<MB_TOT, 256>>>(ex, kc, rd_w, W1, E, a);

    // 1. kc_Wh = kc @ W1   [2000,256]
    hgemm_kernel<<<dim3(OUT_F / 128, (N_KC + 127) / 128), 256, 40960>>>(
        kchi, kclo, W1Thi, W1Tlo, kcWh, N_KC, OUT_F, IN_F, nullptr, 0, nullptr);

    // 2. rowdots + exp tables + colmean + conv(kcWh -> fp16 hi/lo)
    rowdot_both_kernel<<<RB_TOT, 256>>>(ex, kc, W1, kcWh);

    // 3. fused: attention (157) + exEh GEMM (158)   <- profiled launch (index 3)
    attn_fused_kernel<<<NATTN + NGEX, 256, SMEM_ATTN>>>(adj);

    // 4. out = elu([nk | nk*exEh] @ rd_w^T + rd_b)   [10000,256]
    hgemm_kernel<<<dim3(OUT_F / 128, (N_E + 127) / 128), 256, 40960>>>(
        feathi, featlo, rdwhi, rdwlo, out, N_E, OUT_F, 2 * OUT_F, rd_b, 1, exEh);
}

// round 12
// speedup vs baseline: 1.7688x; 1.0149x over previous
#include <cuda_runtime.h>
#include <cuda_bf16.h>
#include <cuda_fp16.h>
#include <math.h>
#include <stdint.h>

#define IN_F   256
#define OUT_F  256
#define N_E    10000
#define N_KC   2000
#define ALPHA  0.2f

#define MT      64
#define KC      32
#define NKC_PAD 2048
#define NCHUNK_RUN 63
#define RSTRIDE 80

#define NGEX    158
#define NATTN   157
#define NATTN2  (2 * NATTN)   // split-K: 2 blocks per tile

typedef __nv_bfloat16 bf16;

// ---------------- scratch ----------------
__device__ float g_kcWh[N_KC * OUT_F];
__device__ float g_exEh[N_E * OUT_F];
__device__ float g_v1[IN_F];
__device__ float g_v2[IN_F];
__device__ __half g_kcWhT_hi[OUT_F * NKC_PAD];
__device__ __half g_kcWhT_lo[OUT_F * NKC_PAD];
__device__ float g_colmean[OUT_F];
__device__ float g_mkcp[8][IN_F];
__device__ float g_Ae[N_E];
__device__ float g_Ce[N_E];
__device__ float2 g_tab[NKC_PAD];
__device__ bf16 g_exhi[N_E * IN_F];
__device__ bf16 g_exlo[N_E * IN_F];
__device__ bf16 g_kchi[N_KC * IN_F];
__device__ bf16 g_kclo[N_KC * IN_F];
__device__ bf16 g_W1Thi[OUT_F * IN_F];
__device__ bf16 g_W1Tlo[OUT_F * IN_F];
__device__ bf16 g_EThi[OUT_F * IN_F];
__device__ bf16 g_ETlo[OUT_F * IN_F];
__device__ bf16 g_rdwhi[OUT_F * 2 * OUT_F];
__device__ bf16 g_rdwlo[OUT_F * 2 * OUT_F];
__device__ bf16 g_feathi[N_E * OUT_F];
__device__ bf16 g_featlo[N_E * OUT_F];
// split-K partials
__device__ float g_pacc[2][N_E * OUT_F];     // 2 x 10.24 MB
__device__ float g_psr[2][NATTN * MT];
__device__ int   g_cnt[NATTN];

// ---------------- helpers ----------------
static __device__ __forceinline__ uint32_t smem_u32(const void* p) {
    uint32_t a;
    asm("{ .reg .u64 t; cvta.to.shared.u64 t, %1; cvt.u32.u64 %0, t; }" : "=r"(a) : "l"(p));
    return a;
}
#define LDSM_X4(R0,R1,R2,R3,ADDR) \
    asm volatile("ldmatrix.sync.aligned.m8n8.x4.shared.b16 {%0,%1,%2,%3}, [%4];" \
                 : "=r"(R0),"=r"(R1),"=r"(R2),"=r"(R3) : "r"(ADDR))
#define CP_ASYNC16(dst, src) \
    asm volatile("cp.async.ca.shared.global [%0], [%1], 16;" :: "r"(dst), "l"(src))
#define CP_COMMIT() asm volatile("cp.async.commit_group;" ::: "memory")
#define CP_WAIT0()  asm volatile("cp.async.wait_group 0;" ::: "memory")

static __device__ __forceinline__ void mma_bf16(float* c, const uint32_t* a, const uint32_t* b) {
    asm volatile(
        "mma.sync.aligned.m16n8k16.row.col.f32.bf16.bf16.f32 "
        "{%0,%1,%2,%3}, {%4,%5,%6,%7}, {%8,%9}, {%0,%1,%2,%3};"
        : "+f"(c[0]), "+f"(c[1]), "+f"(c[2]), "+f"(c[3])
        : "r"(a[0]), "r"(a[1]), "r"(a[2]), "r"(a[3]), "r"(b[0]), "r"(b[1]));
}
static __device__ __forceinline__ void mma_fp16(float* c, const uint32_t* a, const uint32_t* b) {
    asm volatile(
        "mma.sync.aligned.m16n8k16.row.col.f32.f16.f16.f32 "
        "{%0,%1,%2,%3}, {%4,%5,%6,%7}, {%8,%9}, {%0,%1,%2,%3};"
        : "+f"(c[0]), "+f"(c[1]), "+f"(c[2]), "+f"(c[3])
        : "r"(a[0]), "r"(a[1]), "r"(a[2]), "r"(a[3]), "r"(b[0]), "r"(b[1]));
}
static __device__ __forceinline__ void fsplit(float v, bf16& h, bf16& l) {
    h = __float2bfloat16(v);
    l = __float2bfloat16(v - __bfloat162float(h));
}
static __device__ __forceinline__ uint32_t pack2(bf16 a, bf16 b) {
    __nv_bfloat162 t = __halves2bfloat162(a, b);
    return *(uint32_t*)&t;
}
static __device__ __forceinline__ void split4_store(const float4 v, bf16* hi, bf16* lo) {
    bf16 h0, l0, h1, l1, h2, l2, h3, l3;
    fsplit(v.x, h0, l0); fsplit(v.y, h1, l1);
    fsplit(v.z, h2, l2); fsplit(v.w, h3, l3);
    *(uint32_t*)(hi)     = pack2(h0, h1);
    *(uint32_t*)(hi + 2) = pack2(h2, h3);
    *(uint32_t*)(lo)     = pack2(l0, l1);
    *(uint32_t*)(lo + 2) = pack2(l2, l3);
}

// ---------------- mega kernel ----------------
#define MB_EX   1
#define MB_KC   2501
#define MB_RDW  3001
#define MB_TW1  3129
#define MB_TE   3193
#define MB_MKC  3257
#define MB_TOT  3265
__global__ void mega_kernel(const float* __restrict__ ex, const float* __restrict__ kc,
                            const float* __restrict__ rdw, const float* __restrict__ W1,
                            const float* __restrict__ E, const float* __restrict__ a)
{
    int b = blockIdx.x, tid = threadIdx.x;
    if (b < MB_EX) {
        int k = tid;
        float s1 = 0.f, s2 = 0.f;
        #pragma unroll 8
        for (int j = 0; j < OUT_F; j++) {
            float w = W1[k * OUT_F + j];
            s1 += w * a[j];
            s2 += w * a[OUT_F + j];
        }
        g_v1[k] = s1;
        g_v2[k] = s2;
        if (tid < NATTN) g_cnt[tid] = 0;   // reset split-K flags each replay
    } else if (b < MB_KC) {
        size_t i = ((size_t)(b - MB_EX) * 256 + tid) * 4;
        split4_store(*(const float4*)(ex + i), g_exhi + i, g_exlo + i);
    } else if (b < MB_RDW) {
        size_t i = ((size_t)(b - MB_KC) * 256 + tid) * 4;
        split4_store(*(const float4*)(kc + i), g_kchi + i, g_kclo + i);
    } else if (b < MB_TW1) {
        size_t i = ((size_t)(b - MB_RDW) * 256 + tid) * 4;
        split4_store(*(const float4*)(rdw + i), g_rdwhi + i, g_rdwlo + i);
    } else if (b < MB_MKC) {
        bool isW1 = b < MB_TE;
        int bb = b - (isW1 ? MB_TW1 : MB_TE);
        const float* src = isW1 ? W1 : E;
        bf16* hi = isW1 ? g_W1Thi : g_EThi;
        bf16* lo = isW1 ? g_W1Tlo : g_ETlo;
        __shared__ float t[32][33];
        int kb = (bb & 7) * 32, nb = (bb >> 3) * 32;
        int tx = tid & 31, ty = tid >> 5;
        #pragma unroll
        for (int rr = 0; rr < 32; rr += 8)
            t[ty + rr][tx] = src[(size_t)(kb + ty + rr) * OUT_F + nb + tx];
        __syncthreads();
        #pragma unroll
        for (int rr = 0; rr < 32; rr += 8) {
            int n = nb + ty + rr;
            bf16 h, l;
            fsplit(t[tx][ty + rr], h, l);
            hi[(size_t)n * IN_F + kb + tx] = h;
            lo[(size_t)n * IN_F + kb + tx] = l;
        }
    } else {
        int p = b - MB_MKC;
        float s = 0.f;
        for (int j = p * 250; j < (p + 1) * 250; j++)
            s += kc[(size_t)j * IN_F + tid];
        g_mkcp[p][tid] = s;
    }
}

// ---------------- rowdot_both + colmean + conv(kcWh -> fp16 hi/lo) ----------------
#define RB_E2    1250
#define RB_CM    1506
#define RB_CONV0 1507
#define RB_TOT   2019
__global__ void rowdot_both_kernel(const float* __restrict__ ex, const float* __restrict__ kc,
                                   const float* __restrict__ W1, const float* __restrict__ kcWh)
{
    int b = blockIdx.x, tid = threadIdx.x;
    int lane = tid & 31, warp = tid >> 5;
    if (b < RB_E2) {
        int i = b * 8 + warp;
        if (i >= N_E) return;
        const float* row = ex + (size_t)i * IN_F;
        float s = 0.f;
        #pragma unroll
        for (int k = lane; k < IN_F; k += 32) s += row[k] * g_v1[k];
        #pragma unroll
        for (int o = 16; o; o >>= 1) s += __shfl_xor_sync(0xFFFFFFFFu, s, o);
        if (lane == 0) {
            g_Ae[i] = __expf(s);
            g_Ce[i] = __expf(ALPHA * s);
        }
    } else if (b < RB_CM) {
        int j = (b - RB_E2) * 8 + warp;
        if (j >= NKC_PAD) return;
        if (j < N_KC) {
            const float* row = kc + (size_t)j * IN_F;
            float s = 0.f;
            #pragma unroll
            for (int k = lane; k < IN_F; k += 32) s += row[k] * g_v2[k];
            #pragma unroll
            for (int o = 16; o; o >>= 1) s += __shfl_xor_sync(0xFFFFFFFFu, s, o);
            if (lane == 0)
                g_tab[j] = make_float2(__expf(s), __expf(ALPHA * s));
        } else if (lane == 0) {
            g_tab[j] = make_float2(0.f, 0.f);
        }
    } else if (b < RB_CONV0) {
        __shared__ float S[IN_F];
        float s = 0.f;
        #pragma unroll
        for (int p = 0; p < 8; p++) s += g_mkcp[p][tid];
        S[tid] = s;
        __syncthreads();
        float c = 0.f;
        #pragma unroll 8
        for (int k = 0; k < IN_F; k++)
            c += S[k] * W1[(size_t)k * OUT_F + tid];
        g_colmean[tid] = c * (1.0f / N_KC);
    } else {
        __shared__ float t[32][33];
        int bb = b - RB_CONV0;
        int jb = (bb & 63) * 32;
        int nb = (bb >> 6) * 32;
        int tx = tid & 31, ty = tid >> 5;
        #pragma unroll
        for (int rr = 0; rr < 32; rr += 8) {
            int j = jb + ty + rr, n = nb + tx;
            t[ty + rr][tx] = (j < N_KC) ? kcWh[(size_t)j * OUT_F + n] : 0.f;
        }
        __syncthreads();
        #pragma unroll
        for (int rr = 0; rr < 32; rr += 8) {
            int n = nb + ty + rr;
            float v = t[tx][ty + rr];
            __half h = __float2half_rn(v);
            __half l = __float2half_rn(v - __half2float(h));
            size_t di = ((size_t)(jb >> 5) * 256 + n) * KC + tx;
            g_kcWhT_hi[di] = h;
            g_kcWhT_lo[di] = l;
        }
    }
}

// ---------------- hgemm body (bf16 3-product, 128x128 tile) ----------------
#define HOF_AH 0
#define HOF_AL 10240
#define HOF_BH 20480
#define HOF_BL 30720
static __device__ __forceinline__ void hgemm_body(char* smem,
    const bf16* __restrict__ Ahi, const bf16* __restrict__ Alo,
    const bf16* __restrict__ Bhi, const bf16* __restrict__ Blo,
    float* __restrict__ C, int M, int N, int K,
    const float* __restrict__ bias, int epi, const float* __restrict__ exF,
    int bx, int by)
{
    uint32_t sb = smem_u32(smem);
    int tid = threadIdx.x, lane = tid & 31, wid = tid >> 5;
    int bm = by * 128, bn = bx * 128;
    int wm = wid >> 1, wn = wid & 1;
    size_t astr = (epi == 1) ? 256 : (size_t)K;

    float acc[2][8][4];
    #pragma unroll
    for (int mt = 0; mt < 2; mt++)
        #pragma unroll
        for (int nb = 0; nb < 8; nb++)
            #pragma unroll
            for (int k = 0; k < 4; k++) acc[mt][nb][k] = 0.f;

    int crow = tid >> 1, chalf = tid & 1;
    bool arow_ok = (bm + crow) < M;
    const uint4 zero4 = make_uint4(0, 0, 0, 0);

    for (int k0 = 0; k0 < K; k0 += 32) {
        {
            char* dh = smem + HOF_AH + crow * RSTRIDE + chalf * 32;
            char* dl = smem + HOF_AL + crow * RSTRIDE + chalf * 32;
            if (!arow_ok) {
                ((uint4*)dh)[0] = zero4; ((uint4*)dh)[1] = zero4;
                ((uint4*)dl)[0] = zero4; ((uint4*)dl)[1] = zero4;
            } else if (epi == 1 && k0 >= 256) {
                size_t rb = (size_t)(bm + crow) * 256 + (k0 - 256) + chalf * 16;
                uint4 vh[2], vl[2];
                float4 vx[4];
                vh[0] = *(const uint4*)(Ahi + rb); vh[1] = *(const uint4*)(Ahi + rb + 8);
                vl[0] = *(const uint4*)(Alo + rb); vl[1] = *(const uint4*)(Alo + rb + 8);
                vx[0] = *(const float4*)(exF + rb);      vx[1] = *(const float4*)(exF + rb + 4);
                vx[2] = *(const float4*)(exF + rb + 8);  vx[3] = *(const float4*)(exF + rb + 12);
                const bf16* ph = (const bf16*)vh;
                const bf16* pl = (const bf16*)vl;
                const float* px = (const float*)vx;
                uint32_t oh[8], ol[8];
                #pragma unroll
                for (int e = 0; e < 8; e++) {
                    float q0 = (__bfloat162float(ph[2*e])   + __bfloat162float(pl[2*e]))   * px[2*e];
                    float q1 = (__bfloat162float(ph[2*e+1]) + __bfloat162float(pl[2*e+1])) * px[2*e+1];
                    bf16 H0, L0, H1, L1;
                    fsplit(q0, H0, L0); fsplit(q1, H1, L1);
                    oh[e] = pack2(H0, H1);
                    ol[e] = pack2(L0, L1);
                }
                ((uint4*)dh)[0] = *(uint4*)&oh[0]; ((uint4*)dh)[1] = *(uint4*)&oh[4];
                ((uint4*)dl)[0] = *(uint4*)&ol[0]; ((uint4*)dl)[1] = *(uint4*)&ol[4];
            } else {
                const uint4* sh = (const uint4*)(Ahi + (size_t)(bm + crow) * astr + k0 + chalf * 16);
                const uint4* sl = (const uint4*)(Alo + (size_t)(bm + crow) * astr + k0 + chalf * 16);
                ((uint4*)dh)[0] = sh[0]; ((uint4*)dh)[1] = sh[1];
                ((uint4*)dl)[0] = sl[0]; ((uint4*)dl)[1] = sl[1];
            }
        }
        {
            const uint4* sh = (const uint4*)(Bhi + (size_t)(bn + crow) * K + k0 + chalf * 16);
            const uint4* sl = (const uint4*)(Blo + (size_t)(bn + crow) * K + k0 + chalf * 16);
            char* dh = smem + HOF_BH + crow * RSTRIDE + chalf * 32;
            char* dl = smem + HOF_BL + crow * RSTRIDE + chalf * 32;
            ((uint4*)dh)[0] = sh[0]; ((uint4*)dh)[1] = sh[1];
            ((uint4*)dl)[0] = sl[0]; ((uint4*)dl)[1] = sl[1];
        }
        __syncthreads();

        #pragma unroll
        for (int ks = 0; ks < 2; ks++) {
            uint32_t ahi[2][4], alo[2][4], bfrag[8][2];
            int arowi = lane & 15;
            int akoff = (ks * 16 + ((lane >> 4) & 1) * 8) * 2;
            #pragma unroll
            for (int mt = 0; mt < 2; mt++) {
                uint32_t ad = sb + HOF_AH + (wm * 32 + mt * 16 + arowi) * RSTRIDE + akoff;
                LDSM_X4(ahi[mt][0], ahi[mt][1], ahi[mt][2], ahi[mt][3], ad);
                ad += (HOF_AL - HOF_AH);
                LDSM_X4(alo[mt][0], alo[mt][1], alo[mt][2], alo[mt][3], ad);
            }
            int bnrow = (lane & 7) + ((lane >> 4) << 3);
            int bkoff = (ks * 16 + ((lane >> 3) & 1) * 8) * 2;
            #pragma unroll
            for (int nq = 0; nq < 4; nq++) {
                uint32_t bd = sb + HOF_BH + (wn * 64 + nq * 16 + bnrow) * RSTRIDE + bkoff;
                LDSM_X4(bfrag[2 * nq][0], bfrag[2 * nq][1],
                        bfrag[2 * nq + 1][0], bfrag[2 * nq + 1][1], bd);
            }
            #pragma unroll
            for (int mt = 0; mt < 2; mt++)
                #pragma unroll
                for (int nb = 0; nb < 8; nb++)
                    mma_bf16(acc[mt][nb], ahi[mt], bfrag[nb]);
            #pragma unroll
            for (int mt = 0; mt < 2; mt++)
                #pragma unroll
                for (int nb = 0; nb < 8; nb++)
                    mma_bf16(acc[mt][nb], alo[mt], bfrag[nb]);
            #pragma unroll
            for (int nq = 0; nq < 4; nq++) {
                uint32_t bd = sb + HOF_BL + (wn * 64 + nq * 16 + bnrow) * RSTRIDE + bkoff;
                LDSM_X4(bfrag[2 * nq][0], bfrag[2 * nq][1],
                        bfrag[2 * nq + 1][0], bfrag[2 * nq + 1][1], bd);
            }
            #pragma unroll
            for (int mt = 0; mt < 2; mt++)
                #pragma unroll
                for (int nb = 0; nb < 8; nb++)
                    mma_bf16(acc[mt][nb], ahi[mt], bfrag[nb]);
        }
        __syncthreads();
    }

    #pragma unroll
    for (int mt = 0; mt < 2; mt++) {
        #pragma unroll
        for (int nb = 0; nb < 8; nb++) {
            int row0 = wm * 32 + mt * 16 + (lane >> 2);
            int col = bn + wn * 64 + nb * 8 + (lane & 3) * 2;
            #pragma unroll
            for (int h = 0; h < 2; h++) {
                int r = bm + row0 + h * 8;
                if (r >= M) continue;
                float v0 = acc[mt][nb][2 * h];
                float v1 = acc[mt][nb][2 * h + 1];
                if (epi == 1) {
                    v0 += bias[col];
                    v1 += bias[col + 1];
                    v0 = v0 > 0.f ? v0 : expm1f(v0);
                    v1 = v1 > 0.f ? v1 : expm1f(v1);
                }
                C[(size_t)r * N + col]     = v0;
                C[(size_t)r * N + col + 1] = v1;
            }
        }
    }
}

__global__ __launch_bounds__(256, 2) void hgemm_kernel(
    const bf16* __restrict__ Ahi, const bf16* __restrict__ Alo,
    const bf16* __restrict__ Bhi, const bf16* __restrict__ Blo,
    float* __restrict__ C, int M, int N, int K,
    const float* __restrict__ bias, int epi, const float* __restrict__ exF)
{
    extern __shared__ char smem[];
    hgemm_body(smem, Ahi, Alo, Bhi, Blo, C, M, N, K, bias, epi, exF,
               blockIdx.x, blockIdx.y);
}

// ---------------- attention body: split-K halves + fp16 2-product ----------------
#define AOF_B    0
#define AOF_BSZ  40960
#define AOF_BLO  20480
#define AOF_A    81920
#define AOF_ASZ  5120
#define AOF_AE   92160
#define AOF_CE   92416
#define AOF_RS   92672
#define AOF_RSF  93696
#define SMEM_ATTN 93952

static __device__ __forceinline__ void cp_b_chunk(uint32_t sbB, int c, int tid)
{
    const __half* sh = g_kcWhT_hi + ((size_t)c * 256 + tid) * KC;
    const __half* sl = g_kcWhT_lo + ((size_t)c * 256 + tid) * KC;
    uint32_t dh = sbB + tid * RSTRIDE;
    uint32_t dl = dh + AOF_BLO;
    #pragma unroll
    for (int t = 0; t < 4; t++) {
        CP_ASYNC16(dh + t * 16, (const char*)sh + t * 16);
        CP_ASYNC16(dl + t * 16, (const char*)sl + t * 16);
    }
    CP_COMMIT();
}

static __device__ __forceinline__ void attn_body(char* smem, int tile, int half,
    const int* __restrict__ adj)
{
    uint32_t sb = smem_u32(smem);
    float* Aes = (float*)(smem + AOF_AE);
    float* Ces = (float*)(smem + AOF_CE);

    int tid = threadIdx.x, lane = tid & 31, wid = tid >> 5;
    int i0 = tile * MT;
    int c0 = half ? 32 : 0;
    int c1 = half ? NCHUNK_RUN : 32;

    cp_b_chunk(sb + AOF_B, c0, tid);

    if (tid < MT) {
        int gi = i0 + tid;
        bool v = gi < N_E;
        Aes[tid] = v ? g_Ae[gi] : 0.f;
        Ces[tid] = v ? g_Ce[gi] : 0.f;
    }
    __syncthreads();

    int r = tid >> 2, jl0 = (tid & 3) * 8;
    int gi_r = i0 + r;
    const int* arow = adj + (size_t)(gi_r < N_E ? gi_r : 0) * N_KC;
    float Ai = Aes[r], Ci = Ces[r];
    float srow = 0.f;

    int wm = wid & 1, wn = wid >> 1;
    float acc[2][8][4];
    #pragma unroll
    for (int mt = 0; mt < 2; mt++)
        #pragma unroll
        for (int nb = 0; nb < 8; nb++)
            #pragma unroll
            for (int k = 0; k < 4; k++) acc[mt][nb][k] = 0.f;

    for (int c = c0; c < c1; c++) {
        int buf = (c - c0) & 1;
        int j0 = c * KC;
        uint32_t aBase = sb + AOF_A + buf * AOF_ASZ;

        // ---- P-gen (single fp16)
        {
            float p[8];
            if (j0 + KC <= N_KC) {
                const int4* ap = (const int4*)(arow + j0 + jl0);
                int4 a0 = ap[0], a1 = ap[1];
                int am[8] = {a0.x, a0.y, a0.z, a0.w, a1.x, a1.y, a1.z, a1.w};
                #pragma unroll
                for (int e = 0; e < 8; e++) {
                    float2 t = __ldg(&g_tab[j0 + jl0 + e]);
                    float pv = Ai * t.x;
                    float v = (pv > 1.f) ? pv : Ci * t.y;
                    p[e] = (am[e] > 0) ? v : 0.f;
                }
            } else {
                #pragma unroll
                for (int e = 0; e < 8; e++) {
                    int j = j0 + jl0 + e;
                    int m = (j < N_KC) ? arow[j] : 0;
                    float2 t = __ldg(&g_tab[(j < N_KC) ? j : 0]);
                    float pv = Ai * t.x;
                    float v = (pv > 1.f) ? pv : Ci * t.y;
                    p[e] = (m > 0) ? v : 0.f;
                }
            }
            #pragma unroll
            for (int e = 0; e < 8; e++) srow += p[e];
            __half2 q0 = __floats2half2_rn(p[0], p[1]);
            __half2 q1 = __floats2half2_rn(p[2], p[3]);
            __half2 q2 = __floats2half2_rn(p[4], p[5]);
            __half2 q3 = __floats2half2_rn(p[6], p[7]);
            uint4 w = make_uint4(*(uint32_t*)&q0, *(uint32_t*)&q1,
                                 *(uint32_t*)&q2, *(uint32_t*)&q3);
            *(uint4*)(smem + AOF_A + buf * AOF_ASZ + r * RSTRIDE + jl0 * 2) = w;
        }

        CP_WAIT0();
        __syncthreads();

        if (c + 1 < c1)
            cp_b_chunk(sb + AOF_B + (buf ^ 1) * AOF_BSZ, c + 1, tid);

        // ---- MMA: 2-product fp16
        uint32_t bBase = sb + AOF_B + buf * AOF_BSZ;
        #pragma unroll
        for (int ks = 0; ks < 2; ks++) {
            uint32_t af[2][4], bfrag[8][2];
            int arowi = lane & 15;
            int akoff = (ks * 16 + ((lane >> 4) & 1) * 8) * 2;
            #pragma unroll
            for (int mt = 0; mt < 2; mt++) {
                uint32_t ad = aBase + (wm * 32 + mt * 16 + arowi) * RSTRIDE + akoff;
                LDSM_X4(af[mt][0], af[mt][1], af[mt][2], af[mt][3], ad);
            }
            int bnrow = (lane & 7) + ((lane >> 4) << 3);
            int bkoff = (ks * 16 + ((lane >> 3) & 1) * 8) * 2;
            #pragma unroll
            for (int nq = 0; nq < 4; nq++) {
                uint32_t bd = bBase + (wn * 64 + nq * 16 + bnrow) * RSTRIDE + bkoff;
                LDSM_X4(bfrag[2 * nq][0], bfrag[2 * nq][1],
                        bfrag[2 * nq + 1][0], bfrag[2 * nq + 1][1], bd);
            }
            #pragma unroll
            for (int mt = 0; mt < 2; mt++)
                #pragma unroll
                for (int nb = 0; nb < 8; nb++)
                    mma_fp16(acc[mt][nb], af[mt], bfrag[nb]);
            #pragma unroll
            for (int nq = 0; nq < 4; nq++) {
                uint32_t bd = bBase + AOF_BLO + (wn * 64 + nq * 16 + bnrow) * RSTRIDE + bkoff;
                LDSM_X4(bfrag[2 * nq][0], bfrag[2 * nq][1],
                        bfrag[2 * nq + 1][0], bfrag[2 * nq + 1][1], bd);
            }
            #pragma unroll
            for (int mt = 0; mt < 2; mt++)
                #pragma unroll
                for (int nb = 0; nb < 8; nb++)
                    mma_fp16(acc[mt][nb], af[mt], bfrag[nb]);
        }
    }

    // ---- per-row partial sums
    __syncthreads();
    ((float*)(smem + AOF_RS))[tid] = srow;
    __syncthreads();
    if (tid < MT) {
        const float* r4 = (const float*)(smem + AOF_RS) + tid * 4;
        ((float*)(smem + AOF_RSF))[tid] = (r4[0] + r4[1]) + (r4[2] + r4[3]);
    }
    __syncthreads();
    const float* rsF = (const float*)(smem + AOF_RSF);

    // ---- store partials
    #pragma unroll
    for (int mt = 0; mt < 2; mt++) {
        #pragma unroll
        for (int nb = 0; nb < 8; nb++) {
            int row0 = wm * 32 + mt * 16 + (lane >> 2);
            int col  = wn * 64 + nb * 8 + (lane & 3) * 2;
            #pragma unroll
            for (int h = 0; h < 2; h++) {
                int rr = row0 + h * 8;
                int gi = i0 + rr;
                if (gi >= N_E) continue;
                *(float2*)&g_pacc[half][(size_t)gi * OUT_F + col] =
                    make_float2(acc[mt][nb][2 * h], acc[mt][nb][2 * h + 1]);
            }
        }
    }
    if (tid < MT) g_psr[half][tile * MT + tid] = rsF[tid];
    __threadfence();
    __syncthreads();

    __shared__ int sLast;
    if (tid == 0) sLast = (atomicAdd(&g_cnt[tile], 1) == 1);
    __syncthreads();
    if (!sLast) return;

    // ---- combiner: add other half's partials, normalize, write feat
    int other = half ^ 1;
    if (tid < MT)
        ((float*)(smem + AOF_RS))[tid] = rsF[tid] + g_psr[other][tile * MT + tid];
    __syncthreads();
    const float* rsC = (const float*)(smem + AOF_RS);

    #pragma unroll
    for (int mt = 0; mt < 2; mt++) {
        #pragma unroll
        for (int nb = 0; nb < 8; nb++) {
            int row0 = wm * 32 + mt * 16 + (lane >> 2);
            int col  = wn * 64 + nb * 8 + (lane & 3) * 2;
            #pragma unroll
            for (int h = 0; h < 2; h++) {
                int rr = row0 + h * 8;
                int gi = i0 + rr;
                if (gi >= N_E) continue;
                float2 po = *(const float2*)&g_pacc[other][(size_t)gi * OUT_F + col];
                float v0 = acc[mt][nb][2 * h]     + po.x;
                float v1 = acc[mt][nb][2 * h + 1] + po.y;
                float rs = rsC[rr];
                float nk0, nk1;
                if (rs > 0.f) {
                    float ri = 1.f / rs;
                    nk0 = v0 * ri;
                    nk1 = v1 * ri;
                } else {
                    nk0 = g_colmean[col];
                    nk1 = g_colmean[col + 1];
                }
                size_t fb = (size_t)gi * OUT_F + col;
                bf16 h0, l0, h1, l1;
                fsplit(nk0, h0, l0); fsplit(nk1, h1, l1);
                *(uint32_t*)(g_feathi + fb) = pack2(h0, h1);
                *(uint32_t*)(g_featlo + fb) = pack2(l0, l1);
            }
        }
    }
}

// ---------------- fused kernel: attention halves first, exEh GEMM tail ----------------
__global__ __launch_bounds__(256, 2) void attn_fused_kernel(const int* __restrict__ adj)
{
    extern __shared__ char smem[];
    if (blockIdx.x < NATTN2) {
        attn_body(smem, (int)(blockIdx.x >> 1), (int)(blockIdx.x & 1), adj);
    } else {
        int g = blockIdx.x - NATTN2;
        hgemm_body(smem, g_exhi, g_exlo, g_EThi, g_ETlo, (float*)g_exEh,
                   N_E, OUT_F, IN_F, nullptr, 0, nullptr, g & 1, g >> 1);
    }
}

// ---------------- launch ----------------
extern "C" void kernel_launch(void* const* d_in, const int* in_sizes, int n_in,
                              void* d_out, int out_size)
{
    const float* ex   = (const float*)d_in[0];
    const float* kc   = (const float*)d_in[1];
    const int*   adj  = (const int*)d_in[2];
    const float* W1   = (const float*)d_in[3];
    const float* E    = (const float*)d_in[4];
    const float* a    = (const float*)d_in[5];
    const float* rd_w = (const float*)d_in[6];
    const float* rd_b = (const float*)d_in[7];
    float* out = (float*)d_out;

    float *kcWh, *exEh;
    bf16 *kchi, *kclo, *W1Thi, *W1Tlo, *rdwhi, *rdwlo, *feathi, *featlo;
    cudaGetSymbolAddress((void**)&kcWh, g_kcWh);
    cudaGetSymbolAddress((void**)&exEh, g_exEh);
    cudaGetSymbolAddress((void**)&kchi, g_kchi);
    cudaGetSymbolAddress((void**)&kclo, g_kclo);
    cudaGetSymbolAddress((void**)&W1Thi, g_W1Thi);
    cudaGetSymbolAddress((void**)&W1Tlo, g_W1Tlo);
    cudaGetSymbolAddress((void**)&rdwhi, g_rdwhi);
    cudaGetSymbolAddress((void**)&rdwlo, g_rdwlo);
    cudaGetSymbolAddress((void**)&feathi, g_feathi);
    cudaGetSymbolAddress((void**)&featlo, g_featlo);

    cudaFuncSetAttribute(attn_fused_kernel,
                         cudaFuncAttributeMaxDynamicSharedMemorySize, SMEM_ATTN);
    cudaFuncSetAttribute(hgemm_kernel,
                         cudaFuncAttributeMaxDynamicSharedMemorySize, 40960);

    // 0. prep + splits + kc colsum partials + flag reset
    mega_kernel<<<MB_TOT, 256>>>(ex, kc, rd_w, W1, E, a);

    // 1. kc_Wh = kc @ W1   [2000,256]
    hgemm_kernel<<<dim3(OUT_F / 128, (N_KC + 127) / 128), 256, 40960>>>(
        kchi, kclo, W1Thi, W1Tlo, kcWh, N_KC, OUT_F, IN_F, nullptr, 0, nullptr);

    // 2. rowdots + exp tables + colmean + conv(kcWh -> fp16 hi/lo)
    rowdot_both_kernel<<<RB_TOT, 256>>>(ex, kc, W1, kcWh);

    // 3. fused: attention split-K (314) + exEh GEMM (158)
    attn_fused_kernel<<<NATTN2 + NGEX, 256, SMEM_ATTN>>>(adj);

    // 4. out = elu([nk | nk*exEh] @ rd_w^T + rd_b)   [10000,256]
    hgemm_kernel<<<dim3(OUT_F / 128, (N_E + 127) / 128), 256, 40960>>>(
        feathi, featlo, rdwhi, rdwlo, out, N_E, OUT_F, 2 * OUT_F, rd_b, 1, exEh);
}

// round 13
// speedup vs baseline: 2.0592x; 1.1642x over previous
#include <cuda_runtime.h>
#include <cuda_bf16.h>
#include <cuda_fp16.h>
#include <math.h>
#include <stdint.h>

#define IN_F   256
#define OUT_F  256
#define N_E    10000
#define N_KC   2000
#define ALPHA  0.2f

#define MT      64
#define KC      32
#define NKC_PAD 2048
#define NCHUNK_RUN 63
#define RSTRIDE 80

#define NGEX    158
#define NATTN   157
#define NATTN2  (2 * NATTN)

typedef __nv_bfloat16 bf16;

// ---------------- scratch ----------------
__device__ float g_kcWh[N_KC * OUT_F];
__device__ float g_exEh[N_E * OUT_F];
__device__ float g_v1[IN_F];
__device__ float g_v2[IN_F];
__device__ __half g_kcWhT[OUT_F * NKC_PAD];    // single fp16, chunk-blocked transposed
__device__ float g_colmean[OUT_F];
__device__ float g_mkcp[8][IN_F];
__device__ float g_Ae[N_E];
__device__ float g_Ce[N_E];
__device__ float2 g_tab[NKC_PAD];
__device__ bf16 g_exhi[N_E * IN_F];
__device__ bf16 g_exlo[N_E * IN_F];
__device__ bf16 g_kchi[N_KC * IN_F];
__device__ bf16 g_kclo[N_KC * IN_F];
__device__ bf16 g_W1Thi[OUT_F * IN_F];
__device__ bf16 g_W1Tlo[OUT_F * IN_F];
__device__ bf16 g_EThi[OUT_F * IN_F];
__device__ bf16 g_ETlo[OUT_F * IN_F];
__device__ bf16 g_rdwhi[OUT_F * 2 * OUT_F];
__device__ bf16 g_rdwlo[OUT_F * 2 * OUT_F];
__device__ bf16 g_feathi[N_E * OUT_F];
__device__ bf16 g_featlo[N_E * OUT_F];
// split-K partials
__device__ float g_pacc[2][N_E * OUT_F];
__device__ float g_psr[2][NATTN * MT];
__device__ int   g_cnt[NATTN];

// ---------------- helpers ----------------
static __device__ __forceinline__ uint32_t smem_u32(const void* p) {
    uint32_t a;
    asm("{ .reg .u64 t; cvta.to.shared.u64 t, %1; cvt.u32.u64 %0, t; }" : "=r"(a) : "l"(p));
    return a;
}
#define LDSM_X4(R0,R1,R2,R3,ADDR) \
    asm volatile("ldmatrix.sync.aligned.m8n8.x4.shared.b16 {%0,%1,%2,%3}, [%4];" \
                 : "=r"(R0),"=r"(R1),"=r"(R2),"=r"(R3) : "r"(ADDR))
#define CP_ASYNC16(dst, src) \
    asm volatile("cp.async.ca.shared.global [%0], [%1], 16;" :: "r"(dst), "l"(src))
#define CP_COMMIT() asm volatile("cp.async.commit_group;" ::: "memory")
#define CP_WAIT0()  asm volatile("cp.async.wait_group 0;" ::: "memory")

static __device__ __forceinline__ void mma_bf16(float* c, const uint32_t* a, const uint32_t* b) {
    asm volatile(
        "mma.sync.aligned.m16n8k16.row.col.f32.bf16.bf16.f32 "
        "{%0,%1,%2,%3}, {%4,%5,%6,%7}, {%8,%9}, {%0,%1,%2,%3};"
        : "+f"(c[0]), "+f"(c[1]), "+f"(c[2]), "+f"(c[3])
        : "r"(a[0]), "r"(a[1]), "r"(a[2]), "r"(a[3]), "r"(b[0]), "r"(b[1]));
}
static __device__ __forceinline__ void mma_fp16(float* c, const uint32_t* a, const uint32_t* b) {
    asm volatile(
        "mma.sync.aligned.m16n8k16.row.col.f32.f16.f16.f32 "
        "{%0,%1,%2,%3}, {%4,%5,%6,%7}, {%8,%9}, {%0,%1,%2,%3};"
        : "+f"(c[0]), "+f"(c[1]), "+f"(c[2]), "+f"(c[3])
        : "r"(a[0]), "r"(a[1]), "r"(a[2]), "r"(a[3]), "r"(b[0]), "r"(b[1]));
}
static __device__ __forceinline__ void fsplit(float v, bf16& h, bf16& l) {
    h = __float2bfloat16(v);
    l = __float2bfloat16(v - __bfloat162float(h));
}
static __device__ __forceinline__ uint32_t pack2(bf16 a, bf16 b) {
    __nv_bfloat162 t = __halves2bfloat162(a, b);
    return *(uint32_t*)&t;
}
static __device__ __forceinline__ void split4_store(const float4 v, bf16* hi, bf16* lo) {
    bf16 h0, l0, h1, l1, h2, l2, h3, l3;
    fsplit(v.x, h0, l0); fsplit(v.y, h1, l1);
    fsplit(v.z, h2, l2); fsplit(v.w, h3, l3);
    *(uint32_t*)(hi)     = pack2(h0, h1);
    *(uint32_t*)(hi + 2) = pack2(h2, h3);
    *(uint32_t*)(lo)     = pack2(l0, l1);
    *(uint32_t*)(lo + 2) = pack2(l2, l3);
}

// ---------------- mega kernel ----------------
#define MB_EX   1
#define MB_KC   2501
#define MB_RDW  3001
#define MB_TW1  3129
#define MB_TE   3193
#define MB_MKC  3257
#define MB_TOT  3265
__global__ void mega_kernel(const float* __restrict__ ex, const float* __restrict__ kc,
                            const float* __restrict__ rdw, const float* __restrict__ W1,
                            const float* __restrict__ E, const float* __restrict__ a)
{
    int b = blockIdx.x, tid = threadIdx.x;
    if (b < MB_EX) {
        int k = tid;
        float s1 = 0.f, s2 = 0.f;
        #pragma unroll 8
        for (int j = 0; j < OUT_F; j++) {
            float w = W1[k * OUT_F + j];
            s1 += w * a[j];
            s2 += w * a[OUT_F + j];
        }
        g_v1[k] = s1;
        g_v2[k] = s2;
        if (tid < NATTN) g_cnt[tid] = 0;
    } else if (b < MB_KC) {
        size_t i = ((size_t)(b - MB_EX) * 256 + tid) * 4;
        split4_store(*(const float4*)(ex + i), g_exhi + i, g_exlo + i);
    } else if (b < MB_RDW) {
        size_t i = ((size_t)(b - MB_KC) * 256 + tid) * 4;
        split4_store(*(const float4*)(kc + i), g_kchi + i, g_kclo + i);
    } else if (b < MB_TW1) {
        size_t i = ((size_t)(b - MB_RDW) * 256 + tid) * 4;
        split4_store(*(const float4*)(rdw + i), g_rdwhi + i, g_rdwlo + i);
    } else if (b < MB_MKC) {
        bool isW1 = b < MB_TE;
        int bb = b - (isW1 ? MB_TW1 : MB_TE);
        const float* src = isW1 ? W1 : E;
        bf16* hi = isW1 ? g_W1Thi : g_EThi;
        bf16* lo = isW1 ? g_W1Tlo : g_ETlo;
        __shared__ float t[32][33];
        int kb = (bb & 7) * 32, nb = (bb >> 3) * 32;
        int tx = tid & 31, ty = tid >> 5;
        #pragma unroll
        for (int rr = 0; rr < 32; rr += 8)
            t[ty + rr][tx] = src[(size_t)(kb + ty + rr) * OUT_F + nb + tx];
        __syncthreads();
        #pragma unroll
        for (int rr = 0; rr < 32; rr += 8) {
            int n = nb + ty + rr;
            bf16 h, l;
            fsplit(t[tx][ty + rr], h, l);
            hi[(size_t)n * IN_F + kb + tx] = h;
            lo[(size_t)n * IN_F + kb + tx] = l;
        }
    } else {
        int p = b - MB_MKC;
        float s = 0.f;
        for (int j = p * 250; j < (p + 1) * 250; j++)
            s += kc[(size_t)j * IN_F + tid];
        g_mkcp[p][tid] = s;
    }
}

// ---------------- rowdot_both + colmean + conv(kcWh -> single fp16) ----------------
#define RB_E2    1250
#define RB_CM    1506
#define RB_CONV0 1507
#define RB_TOT   2019
__global__ void rowdot_both_kernel(const float* __restrict__ ex, const float* __restrict__ kc,
                                   const float* __restrict__ W1, const float* __restrict__ kcWh)
{
    int b = blockIdx.x, tid = threadIdx.x;
    int lane = tid & 31, warp = tid >> 5;
    if (b < RB_E2) {
        int i = b * 8 + warp;
        if (i >= N_E) return;
        const float* row = ex + (size_t)i * IN_F;
        float s = 0.f;
        #pragma unroll
        for (int k = lane; k < IN_F; k += 32) s += row[k] * g_v1[k];
        #pragma unroll
        for (int o = 16; o; o >>= 1) s += __shfl_xor_sync(0xFFFFFFFFu, s, o);
        if (lane == 0) {
            g_Ae[i] = __expf(s);
            g_Ce[i] = __expf(ALPHA * s);
        }
    } else if (b < RB_CM) {
        int j = (b - RB_E2) * 8 + warp;
        if (j >= NKC_PAD) return;
        if (j < N_KC) {
            const float* row = kc + (size_t)j * IN_F;
            float s = 0.f;
            #pragma unroll
            for (int k = lane; k < IN_F; k += 32) s += row[k] * g_v2[k];
            #pragma unroll
            for (int o = 16; o; o >>= 1) s += __shfl_xor_sync(0xFFFFFFFFu, s, o);
            if (lane == 0)
                g_tab[j] = make_float2(__expf(s), __expf(ALPHA * s));
        } else if (lane == 0) {
            g_tab[j] = make_float2(0.f, 0.f);
        }
    } else if (b < RB_CONV0) {
        __shared__ float S[IN_F];
        float s = 0.f;
        #pragma unroll
        for (int p = 0; p < 8; p++) s += g_mkcp[p][tid];
        S[tid] = s;
        __syncthreads();
        float c = 0.f;
        #pragma unroll 8
        for (int k = 0; k < IN_F; k++)
            c += S[k] * W1[(size_t)k * OUT_F + tid];
        g_colmean[tid] = c * (1.0f / N_KC);
    } else {
        __shared__ float t[32][33];
        int bb = b - RB_CONV0;
        int jb = (bb & 63) * 32;
        int nb = (bb >> 6) * 32;
        int tx = tid & 31, ty = tid >> 5;
        #pragma unroll
        for (int rr = 0; rr < 32; rr += 8) {
            int j = jb + ty + rr, n = nb + tx;
            t[ty + rr][tx] = (j < N_KC) ? kcWh[(size_t)j * OUT_F + n] : 0.f;
        }
        __syncthreads();
        #pragma unroll
        for (int rr = 0; rr < 32; rr += 8) {
            int n = nb + ty + rr;
            size_t di = ((size_t)(jb >> 5) * 256 + n) * KC + tx;
            g_kcWhT[di] = __float2half_rn(t[tx][ty + rr]);
        }
    }
}

// ---------------- hgemm body (bf16 3-product, 128x128 tile) ----------------
#define HOF_AH 0
#define HOF_AL 10240
#define HOF_BH 20480
#define HOF_BL 30720
static __device__ __forceinline__ void hgemm_body(char* smem,
    const bf16* __restrict__ Ahi, const bf16* __restrict__ Alo,
    const bf16* __restrict__ Bhi, const bf16* __restrict__ Blo,
    float* __restrict__ C, int M, int N, int K,
    const float* __restrict__ bias, int epi, const float* __restrict__ exF,
    int bx, int by)
{
    uint32_t sb = smem_u32(smem);
    int tid = threadIdx.x, lane = tid & 31, wid = tid >> 5;
    int bm = by * 128, bn = bx * 128;
    int wm = wid >> 1, wn = wid & 1;
    size_t astr = (epi == 1) ? 256 : (size_t)K;

    float acc[2][8][4];
    #pragma unroll
    for (int mt = 0; mt < 2; mt++)
        #pragma unroll
        for (int nb = 0; nb < 8; nb++)
            #pragma unroll
            for (int k = 0; k < 4; k++) acc[mt][nb][k] = 0.f;

    int crow = tid >> 1, chalf = tid & 1;
    bool arow_ok = (bm + crow) < M;
    const uint4 zero4 = make_uint4(0, 0, 0, 0);

    for (int k0 = 0; k0 < K; k0 += 32) {
        {
            char* dh = smem + HOF_AH + crow * RSTRIDE + chalf * 32;
            char* dl = smem + HOF_AL + crow * RSTRIDE + chalf * 32;
            if (!arow_ok) {
                ((uint4*)dh)[0] = zero4; ((uint4*)dh)[1] = zero4;
                ((uint4*)dl)[0] = zero4; ((uint4*)dl)[1] = zero4;
            } else if (epi == 1 && k0 >= 256) {
                size_t rb = (size_t)(bm + crow) * 256 + (k0 - 256) + chalf * 16;
                uint4 vh[2], vl[2];
                float4 vx[4];
                vh[0] = *(const uint4*)(Ahi + rb); vh[1] = *(const uint4*)(Ahi + rb + 8);
                vl[0] = *(const uint4*)(Alo + rb); vl[1] = *(const uint4*)(Alo + rb + 8);
                vx[0] = *(const float4*)(exF + rb);      vx[1] = *(const float4*)(exF + rb + 4);
                vx[2] = *(const float4*)(exF + rb + 8);  vx[3] = *(const float4*)(exF + rb + 12);
                const bf16* ph = (const bf16*)vh;
                const bf16* pl = (const bf16*)vl;
                const float* px = (const float*)vx;
                uint32_t oh[8], ol[8];
                #pragma unroll
                for (int e = 0; e < 8; e++) {
                    float q0 = (__bfloat162float(ph[2*e])   + __bfloat162float(pl[2*e]))   * px[2*e];
                    float q1 = (__bfloat162float(ph[2*e+1]) + __bfloat162float(pl[2*e+1])) * px[2*e+1];
                    bf16 H0, L0, H1, L1;
                    fsplit(q0, H0, L0); fsplit(q1, H1, L1);
                    oh[e] = pack2(H0, H1);
                    ol[e] = pack2(L0, L1);
                }
                ((uint4*)dh)[0] = *(uint4*)&oh[0]; ((uint4*)dh)[1] = *(uint4*)&oh[4];
                ((uint4*)dl)[0] = *(uint4*)&ol[0]; ((uint4*)dl)[1] = *(uint4*)&ol[4];
            } else {
                const uint4* sh = (const uint4*)(Ahi + (size_t)(bm + crow) * astr + k0 + chalf * 16);
                const uint4* sl = (const uint4*)(Alo + (size_t)(bm + crow) * astr + k0 + chalf * 16);
                ((uint4*)dh)[0] = sh[0]; ((uint4*)dh)[1] = sh[1];
                ((uint4*)dl)[0] = sl[0]; ((uint4*)dl)[1] = sl[1];
            }
        }
        {
            const uint4* sh = (const uint4*)(Bhi + (size_t)(bn + crow) * K + k0 + chalf * 16);
            const uint4* sl = (const uint4*)(Blo + (size_t)(bn + crow) * K + k0 + chalf * 16);
            char* dh = smem + HOF_BH + crow * RSTRIDE + chalf * 32;
            char* dl = smem + HOF_BL + crow * RSTRIDE + chalf * 32;
            ((uint4*)dh)[0] = sh[0]; ((uint4*)dh)[1] = sh[1];
            ((uint4*)dl)[0] = sl[0]; ((uint4*)dl)[1] = sl[1];
        }
        __syncthreads();

        #pragma unroll
        for (int ks = 0; ks < 2; ks++) {
            uint32_t ahi[2][4], alo[2][4], bfrag[8][2];
            int arowi = lane & 15;
            int akoff = (ks * 16 + ((lane >> 4) & 1) * 8) * 2;
            #pragma unroll
            for (int mt = 0; mt < 2; mt++) {
                uint32_t ad = sb + HOF_AH + (wm * 32 + mt * 16 + arowi) * RSTRIDE + akoff;
                LDSM_X4(ahi[mt][0], ahi[mt][1], ahi[mt][2], ahi[mt][3], ad);
                ad += (HOF_AL - HOF_AH);
                LDSM_X4(alo[mt][0], alo[mt][1], alo[mt][2], alo[mt][3], ad);
            }
            int bnrow = (lane & 7) + ((lane >> 4) << 3);
            int bkoff = (ks * 16 + ((lane >> 3) & 1) * 8) * 2;
            #pragma unroll
            for (int nq = 0; nq < 4; nq++) {
                uint32_t bd = sb + HOF_BH + (wn * 64 + nq * 16 + bnrow) * RSTRIDE + bkoff;
                LDSM_X4(bfrag[2 * nq][0], bfrag[2 * nq][1],
                        bfrag[2 * nq + 1][0], bfrag[2 * nq + 1][1], bd);
            }
            #pragma unroll
            for (int mt = 0; mt < 2; mt++)
                #pragma unroll
                for (int nb = 0; nb < 8; nb++)
                    mma_bf16(acc[mt][nb], ahi[mt], bfrag[nb]);
            #pragma unroll
            for (int mt = 0; mt < 2; mt++)
                #pragma unroll
                for (int nb = 0; nb < 8; nb++)
                    mma_bf16(acc[mt][nb], alo[mt], bfrag[nb]);
            #pragma unroll
            for (int nq = 0; nq < 4; nq++) {
                uint32_t bd = sb + HOF_BL + (wn * 64 + nq * 16 + bnrow) * RSTRIDE + bkoff;
                LDSM_X4(bfrag[2 * nq][0], bfrag[2 * nq][1],
                        bfrag[2 * nq + 1][0], bfrag[2 * nq + 1][1], bd);
            }
            #pragma unroll
            for (int mt = 0; mt < 2; mt++)
                #pragma unroll
                for (int nb = 0; nb < 8; nb++)
                    mma_bf16(acc[mt][nb], ahi[mt], bfrag[nb]);
        }
        __syncthreads();
    }

    #pragma unroll
    for (int mt = 0; mt < 2; mt++) {
        #pragma unroll
        for (int nb = 0; nb < 8; nb++) {
            int row0 = wm * 32 + mt * 16 + (lane >> 2);
            int col = bn + wn * 64 + nb * 8 + (lane & 3) * 2;
            #pragma unroll
            for (int h = 0; h < 2; h++) {
                int r = bm + row0 + h * 8;
                if (r >= M) continue;
                float v0 = acc[mt][nb][2 * h];
                float v1 = acc[mt][nb][2 * h + 1];
                if (epi == 1) {
                    v0 += bias[col];
                    v1 += bias[col + 1];
                    v0 = v0 > 0.f ? v0 : expm1f(v0);
                    v1 = v1 > 0.f ? v1 : expm1f(v1);
                }
                C[(size_t)r * N + col]     = v0;
                C[(size_t)r * N + col + 1] = v1;
            }
        }
    }
}

__global__ __launch_bounds__(256, 2) void hgemm_kernel(
    const bf16* __restrict__ Ahi, const bf16* __restrict__ Alo,
    const bf16* __restrict__ Bhi, const bf16* __restrict__ Blo,
    float* __restrict__ C, int M, int N, int K,
    const float* __restrict__ bias, int epi, const float* __restrict__ exF)
{
    extern __shared__ char smem[];
    hgemm_body(smem, Ahi, Alo, Bhi, Blo, C, M, N, K, bias, epi, exF,
               blockIdx.x, blockIdx.y);
}

// ---------------- attention body: single fp16 product, split-K, cp.async ----------------
#define AOF_B    0
#define AOF_BSZ  20480
#define AOF_A    40960
#define AOF_ASZ  5120
#define AOF_AE   51200
#define AOF_CE   51456
#define AOF_RS   51712
#define AOF_RSF  52736
#define SMEM_ATTN 53248

static __device__ __forceinline__ void cp_b_chunk(uint32_t sbB, int c, int tid)
{
    const __half* sh = g_kcWhT + ((size_t)c * 256 + tid) * KC;
    uint32_t dh = sbB + tid * RSTRIDE;
    #pragma unroll
    for (int t = 0; t < 4; t++)
        CP_ASYNC16(dh + t * 16, (const char*)sh + t * 16);
    CP_COMMIT();
}

static __device__ __forceinline__ void attn_body(char* smem, int tile, int half,
    const int* __restrict__ adj)
{
    uint32_t sb = smem_u32(smem);
    float* Aes = (float*)(smem + AOF_AE);
    float* Ces = (float*)(smem + AOF_CE);

    int tid = threadIdx.x, lane = tid & 31, wid = tid >> 5;
    int i0 = tile * MT;
    int c0 = half ? 32 : 0;
    int c1 = half ? NCHUNK_RUN : 32;

    cp_b_chunk(sb + AOF_B, c0, tid);

    if (tid < MT) {
        int gi = i0 + tid;
        bool v = gi < N_E;
        Aes[tid] = v ? g_Ae[gi] : 0.f;
        Ces[tid] = v ? g_Ce[gi] : 0.f;
    }
    __syncthreads();

    int r = tid >> 2, jl0 = (tid & 3) * 8;
    int gi_r = i0 + r;
    const int* arow = adj + (size_t)(gi_r < N_E ? gi_r : 0) * N_KC;
    float Ai = Aes[r], Ci = Ces[r];
    float srow = 0.f;

    int wm = wid & 1, wn = wid >> 1;
    float acc[2][8][4];
    #pragma unroll
    for (int mt = 0; mt < 2; mt++)
        #pragma unroll
        for (int nb = 0; nb < 8; nb++)
            #pragma unroll
            for (int k = 0; k < 4; k++) acc[mt][nb][k] = 0.f;

    for (int c = c0; c < c1; c++) {
        int buf = (c - c0) & 1;
        int j0 = c * KC;
        uint32_t aBase = sb + AOF_A + buf * AOF_ASZ;

        // ---- P-gen (single fp16)
        {
            float p[8];
            if (j0 + KC <= N_KC) {
                const int4* ap = (const int4*)(arow + j0 + jl0);
                int4 a0 = ap[0], a1 = ap[1];
                int am[8] = {a0.x, a0.y, a0.z, a0.w, a1.x, a1.y, a1.z, a1.w};
                #pragma unroll
                for (int e = 0; e < 8; e++) {
                    float2 t = __ldg(&g_tab[j0 + jl0 + e]);
                    float pv = Ai * t.x;
                    float v = (pv > 1.f) ? pv : Ci * t.y;
                    p[e] = (am[e] > 0) ? v : 0.f;
                }
            } else {
                #pragma unroll
                for (int e = 0; e < 8; e++) {
                    int j = j0 + jl0 + e;
                    int m = (j < N_KC) ? arow[j] : 0;
                    float2 t = __ldg(&g_tab[(j < N_KC) ? j : 0]);
                    float pv = Ai * t.x;
                    float v = (pv > 1.f) ? pv : Ci * t.y;
                    p[e] = (m > 0) ? v : 0.f;
                }
            }
            #pragma unroll
            for (int e = 0; e < 8; e++) srow += p[e];
            __half2 q0 = __floats2half2_rn(p[0], p[1]);
            __half2 q1 = __floats2half2_rn(p[2], p[3]);
            __half2 q2 = __floats2half2_rn(p[4], p[5]);
            __half2 q3 = __floats2half2_rn(p[6], p[7]);
            uint4 w = make_uint4(*(uint32_t*)&q0, *(uint32_t*)&q1,
                                 *(uint32_t*)&q2, *(uint32_t*)&q3);
            *(uint4*)(smem + AOF_A + buf * AOF_ASZ + r * RSTRIDE + jl0 * 2) = w;
        }

        CP_WAIT0();
        __syncthreads();

        if (c + 1 < c1)
            cp_b_chunk(sb + AOF_B + (buf ^ 1) * AOF_BSZ, c + 1, tid);

        // ---- MMA: single fp16 product
        uint32_t bBase = sb + AOF_B + buf * AOF_BSZ;
        #pragma unroll
        for (int ks = 0; ks < 2; ks++) {
            uint32_t af[2][4], bfrag[8][2];
            int arowi = lane & 15;
            int akoff = (ks * 16 + ((lane >> 4) & 1) * 8) * 2;
            #pragma unroll
            for (int mt = 0; mt < 2; mt++) {
                uint32_t ad = aBase + (wm * 32 + mt * 16 + arowi) * RSTRIDE + akoff;
                LDSM_X4(af[mt][0], af[mt][1], af[mt][2], af[mt][3], ad);
            }
            int bnrow = (lane & 7) + ((lane >> 4) << 3);
            int bkoff = (ks * 16 + ((lane >> 3) & 1) * 8) * 2;
            #pragma unroll
            for (int nq = 0; nq < 4; nq++) {
                uint32_t bd = bBase + (wn * 64 + nq * 16 + bnrow) * RSTRIDE + bkoff;
                LDSM_X4(bfrag[2 * nq][0], bfrag[2 * nq][1],
                        bfrag[2 * nq + 1][0], bfrag[2 * nq + 1][1], bd);
            }
            #pragma unroll
            for (int mt = 0; mt < 2; mt++)
                #pragma unroll
                for (int nb = 0; nb < 8; nb++)
                    mma_fp16(acc[mt][nb], af[mt], bfrag[nb]);
        }
    }

    // ---- per-row partial sums
    __syncthreads();
    ((float*)(smem + AOF_RS))[tid] = srow;
    __syncthreads();
    if (tid < MT) {
        const float* r4 = (const float*)(smem + AOF_RS) + tid * 4;
        ((float*)(smem + AOF_RSF))[tid] = (r4[0] + r4[1]) + (r4[2] + r4[3]);
    }
    __syncthreads();
    const float* rsF = (const float*)(smem + AOF_RSF);

    // ---- store partials
    #pragma unroll
    for (int mt = 0; mt < 2; mt++) {
        #pragma unroll
        for (int nb = 0; nb < 8; nb++) {
            int row0 = wm * 32 + mt * 16 + (lane >> 2);
            int col  = wn * 64 + nb * 8 + (lane & 3) * 2;
            #pragma unroll
            for (int h = 0; h < 2; h++) {
                int rr = row0 + h * 8;
                int gi = i0 + rr;
                if (gi >= N_E) continue;
                *(float2*)&g_pacc[half][(size_t)gi * OUT_F + col] =
                    make_float2(acc[mt][nb][2 * h], acc[mt][nb][2 * h + 1]);
            }
        }
    }
    if (tid < MT) g_psr[half][tile * MT + tid] = rsF[tid];
    __threadfence();
    __syncthreads();

    __shared__ int sLast;
    if (tid == 0) sLast = (atomicAdd(&g_cnt[tile], 1) == 1);
    __syncthreads();
    if (!sLast) return;

    // ---- combiner
    int other = half ^ 1;
    if (tid < MT)
        ((float*)(smem + AOF_RS))[tid] = rsF[tid] + g_psr[other][tile * MT + tid];
    __syncthreads();
    const float* rsC = (const float*)(smem + AOF_RS);

    #pragma unroll
    for (int mt = 0; mt < 2; mt++) {
        #pragma unroll
        for (int nb = 0; nb < 8; nb++) {
            int row0 = wm * 32 + mt * 16 + (lane >> 2);
            int col  = wn * 64 + nb * 8 + (lane & 3) * 2;
            #pragma unroll
            for (int h = 0; h < 2; h++) {
                int rr = row0 + h * 8;
                int gi = i0 + rr;
                if (gi >= N_E) continue;
                float2 po = *(const float2*)&g_pacc[other][(size_t)gi * OUT_F + col];
                float v0 = acc[mt][nb][2 * h]     + po.x;
                float v1 = acc[mt][nb][2 * h + 1] + po.y;
                float rs = rsC[rr];
                float nk0, nk1;
                if (rs > 0.f) {
                    float ri = 1.f / rs;
                    nk0 = v0 * ri;
                    nk1 = v1 * ri;
                } else {
                    nk0 = g_colmean[col];
                    nk1 = g_colmean[col + 1];
                }
                size_t fb = (size_t)gi * OUT_F + col;
                bf16 h0, l0, h1, l1;
                fsplit(nk0, h0, l0); fsplit(nk1, h1, l1);
                *(uint32_t*)(g_feathi + fb) = pack2(h0, h1);
                *(uint32_t*)(g_featlo + fb) = pack2(l0, l1);
            }
        }
    }
}

// ---------------- fused kernel ----------------
__global__ __launch_bounds__(256, 2) void attn_fused_kernel(const int* __restrict__ adj)
{
    extern __shared__ char smem[];
    if (blockIdx.x < NATTN2) {
        attn_body(smem, (int)(blockIdx.x >> 1), (int)(blockIdx.x & 1), adj);
    } else {
        int g = blockIdx.x - NATTN2;
        hgemm_body(smem, g_exhi, g_exlo, g_EThi, g_ETlo, (float*)g_exEh,
                   N_E, OUT_F, IN_F, nullptr, 0, nullptr, g & 1, g >> 1);
    }
}

// ---------------- launch ----------------
extern "C" void kernel_launch(void* const* d_in, const int* in_sizes, int n_in,
                              void* d_out, int out_size)
{
    const float* ex   = (const float*)d_in[0];
    const float* kc   = (const float*)d_in[1];
    const int*   adj  = (const int*)d_in[2];
    const float* W1   = (const float*)d_in[3];
    const float* E    = (const float*)d_in[4];
    const float* a    = (const float*)d_in[5];
    const float* rd_w = (const float*)d_in[6];
    const float* rd_b = (const float*)d_in[7];
    float* out = (float*)d_out;

    float *kcWh, *exEh;
    bf16 *kchi, *kclo, *W1Thi, *W1Tlo, *rdwhi, *rdwlo, *feathi, *featlo;
    cudaGetSymbolAddress((void**)&kcWh, g_kcWh);
    cudaGetSymbolAddress((void**)&exEh, g_exEh);
    cudaGetSymbolAddress((void**)&kchi, g_kchi);
    cudaGetSymbolAddress((void**)&kclo, g_kclo);
    cudaGetSymbolAddress((void**)&W1Thi, g_W1Thi);
    cudaGetSymbolAddress((void**)&W1Tlo, g_W1Tlo);
    cudaGetSymbolAddress((void**)&rdwhi, g_rdwhi);
    cudaGetSymbolAddress((void**)&rdwlo, g_rdwlo);
    cudaGetSymbolAddress((void**)&feathi, g_feathi);
    cudaGetSymbolAddress((void**)&featlo, g_featlo);

    cudaFuncSetAttribute(attn_fused_kernel,
                         cudaFuncAttributeMaxDynamicSharedMemorySize, SMEM_ATTN);
    cudaFuncSetAttribute(hgemm_kernel,
                         cudaFuncAttributeMaxDynamicSharedMemorySize, 40960);

    // 0. prep + splits + kc colsum partials + flag reset
    mega_kernel<<<MB_TOT, 256>>>(ex, kc, rd_w, W1, E, a);

    // 1. kc_Wh = kc @ W1   [2000,256]
    hgemm_kernel<<<dim3(OUT_F / 128, (N_KC + 127) / 128), 256, 40960>>>(
        kchi, kclo, W1Thi, W1Tlo, kcWh, N_KC, OUT_F, IN_F, nullptr, 0, nullptr);

    // 2. rowdots + exp tables + colmean + conv(kcWh -> single fp16)
    rowdot_both_kernel<<<RB_TOT, 256>>>(ex, kc, W1, kcWh);

    // 3. fused: attention split-K (314) + exEh GEMM (158)
    attn_fused_kernel<<<NATTN2 + NGEX, 256, SMEM_ATTN>>>(adj);

    // 4. out = elu([nk | nk*exEh] @ rd_w^T + rd_b)   [10000,256]
    hgemm_kernel<<<dim3(OUT_F / 128, (N_E + 127) / 128), 256, 40960>>>(
        feathi, featlo, rdwhi, rdwlo, out, N_E, OUT_F, 2 * OUT_F, rd_b, 1, exEh);
}

// round 14
// speedup vs baseline: 2.1833x; 1.0603x over previous
#include <cuda_runtime.h>
#include <cuda_bf16.h>
#include <cuda_fp16.h>
#include <math.h>
#include <stdint.h>

#define IN_F   256
#define OUT_F  256
#define N_E    10000
#define N_KC   2000
#define ALPHA  0.2f

#define MT      64
#define KC      32
#define NKC_PAD 2048
#define NCHUNK_RUN 63
#define RSTRIDE 80

#define NGEX    158
#define NATTN   157
#define NATTN2  (2 * NATTN)

typedef __nv_bfloat16 bf16;

// ---------------- scratch ----------------
__device__ float g_exEh[N_E * OUT_F];
__device__ float g_v1[IN_F];
__device__ float g_v2[IN_F];
__device__ __half g_kcWhT[OUT_F * NKC_PAD];   // fp16, chunk-blocked transposed
__device__ float g_colmean[OUT_F];
__device__ float g_mkcp[8][IN_F];
__device__ float g_Ae[N_E];
__device__ float g_Ce[N_E];
__device__ float2 g_tab[NKC_PAD];
__device__ __half g_exh[N_E * IN_F];          // fp16 ex
__device__ __half g_ETh[OUT_F * IN_F];        // fp16 E^T [n][k]
__device__ bf16 g_kchi[N_KC * IN_F];
__device__ bf16 g_kclo[N_KC * IN_F];
__device__ bf16 g_W1Thi[OUT_F * IN_F];
__device__ bf16 g_W1Tlo[OUT_F * IN_F];
__device__ bf16 g_rdwhi[OUT_F * 2 * OUT_F];
__device__ bf16 g_rdwlo[OUT_F * 2 * OUT_F];
__device__ bf16 g_feathi[N_E * OUT_F];
__device__ bf16 g_featlo[N_E * OUT_F];
// split-K partials
__device__ float g_pacc[2][N_E * OUT_F];
__device__ float g_psr[2][NATTN * MT];
__device__ int   g_cnt[NATTN];

// ---------------- helpers ----------------
static __device__ __forceinline__ uint32_t smem_u32(const void* p) {
    uint32_t a;
    asm("{ .reg .u64 t; cvta.to.shared.u64 t, %1; cvt.u32.u64 %0, t; }" : "=r"(a) : "l"(p));
    return a;
}
#define LDSM_X4(R0,R1,R2,R3,ADDR) \
    asm volatile("ldmatrix.sync.aligned.m8n8.x4.shared.b16 {%0,%1,%2,%3}, [%4];" \
                 : "=r"(R0),"=r"(R1),"=r"(R2),"=r"(R3) : "r"(ADDR))
#define CP_ASYNC16(dst, src) \
    asm volatile("cp.async.ca.shared.global [%0], [%1], 16;" :: "r"(dst), "l"(src))
#define CP_COMMIT() asm volatile("cp.async.commit_group;" ::: "memory")
#define CP_WAIT0()  asm volatile("cp.async.wait_group 0;" ::: "memory")

static __device__ __forceinline__ void mma_bf16(float* c, const uint32_t* a, const uint32_t* b) {
    asm volatile(
        "mma.sync.aligned.m16n8k16.row.col.f32.bf16.bf16.f32 "
        "{%0,%1,%2,%3}, {%4,%5,%6,%7}, {%8,%9}, {%0,%1,%2,%3};"
        : "+f"(c[0]), "+f"(c[1]), "+f"(c[2]), "+f"(c[3])
        : "r"(a[0]), "r"(a[1]), "r"(a[2]), "r"(a[3]), "r"(b[0]), "r"(b[1]));
}
static __device__ __forceinline__ void mma_fp16(float* c, const uint32_t* a, const uint32_t* b) {
    asm volatile(
        "mma.sync.aligned.m16n8k16.row.col.f32.f16.f16.f32 "
        "{%0,%1,%2,%3}, {%4,%5,%6,%7}, {%8,%9}, {%0,%1,%2,%3};"
        : "+f"(c[0]), "+f"(c[1]), "+f"(c[2]), "+f"(c[3])
        : "r"(a[0]), "r"(a[1]), "r"(a[2]), "r"(a[3]), "r"(b[0]), "r"(b[1]));
}
static __device__ __forceinline__ void fsplit(float v, bf16& h, bf16& l) {
    h = __float2bfloat16(v);
    l = __float2bfloat16(v - __bfloat162float(h));
}
static __device__ __forceinline__ uint32_t pack2(bf16 a, bf16 b) {
    __nv_bfloat162 t = __halves2bfloat162(a, b);
    return *(uint32_t*)&t;
}
static __device__ __forceinline__ void split4_store(const float4 v, bf16* hi, bf16* lo) {
    bf16 h0, l0, h1, l1, h2, l2, h3, l3;
    fsplit(v.x, h0, l0); fsplit(v.y, h1, l1);
    fsplit(v.z, h2, l2); fsplit(v.w, h3, l3);
    *(uint32_t*)(hi)     = pack2(h0, h1);
    *(uint32_t*)(hi + 2) = pack2(h2, h3);
    *(uint32_t*)(lo)     = pack2(l0, l1);
    *(uint32_t*)(lo + 2) = pack2(l2, l3);
}

// ---------------- mega kernel ----------------
#define MB_EX   1
#define MB_KC   2501
#define MB_RDW  3001
#define MB_TW1  3129
#define MB_TE   3193
#define MB_MKC  3257
#define MB_TOT  3265
__global__ void mega_kernel(const float* __restrict__ ex, const float* __restrict__ kc,
                            const float* __restrict__ rdw, const float* __restrict__ W1,
                            const float* __restrict__ E, const float* __restrict__ a)
{
    int b = blockIdx.x, tid = threadIdx.x;
    if (b < MB_EX) {
        int k = tid;
        float s1 = 0.f, s2 = 0.f;
        #pragma unroll 8
        for (int j = 0; j < OUT_F; j++) {
            float w = W1[k * OUT_F + j];
            s1 += w * a[j];
            s2 += w * a[OUT_F + j];
        }
        g_v1[k] = s1;
        g_v2[k] = s2;
        if (tid < NATTN) g_cnt[tid] = 0;
    } else if (b < MB_KC) {
        size_t i = ((size_t)(b - MB_EX) * 256 + tid) * 4;
        float4 v = *(const float4*)(ex + i);
        __half2 a0 = __floats2half2_rn(v.x, v.y);
        __half2 a1 = __floats2half2_rn(v.z, v.w);
        *(uint32_t*)(g_exh + i)     = *(uint32_t*)&a0;
        *(uint32_t*)(g_exh + i + 2) = *(uint32_t*)&a1;
    } else if (b < MB_RDW) {
        size_t i = ((size_t)(b - MB_KC) * 256 + tid) * 4;
        split4_store(*(const float4*)(kc + i), g_kchi + i, g_kclo + i);
    } else if (b < MB_TW1) {
        size_t i = ((size_t)(b - MB_RDW) * 256 + tid) * 4;
        split4_store(*(const float4*)(rdw + i), g_rdwhi + i, g_rdwlo + i);
    } else if (b < MB_TE) {
        // W1 transpose hi/lo
        int bb = b - MB_TW1;
        __shared__ float t[32][33];
        int kb = (bb & 7) * 32, nb = (bb >> 3) * 32;
        int tx = tid & 31, ty = tid >> 5;
        #pragma unroll
        for (int rr = 0; rr < 32; rr += 8)
            t[ty + rr][tx] = W1[(size_t)(kb + ty + rr) * OUT_F + nb + tx];
        __syncthreads();
        #pragma unroll
        for (int rr = 0; rr < 32; rr += 8) {
            int n = nb + ty + rr;
            bf16 h, l;
            fsplit(t[tx][ty + rr], h, l);
            g_W1Thi[(size_t)n * IN_F + kb + tx] = h;
            g_W1Tlo[(size_t)n * IN_F + kb + tx] = l;
        }
    } else if (b < MB_MKC) {
        // E transpose fp16
        int bb = b - MB_TE;
        __shared__ float t[32][33];
        int kb = (bb & 7) * 32, nb = (bb >> 3) * 32;
        int tx = tid & 31, ty = tid >> 5;
        #pragma unroll
        for (int rr = 0; rr < 32; rr += 8)
            t[ty + rr][tx] = E[(size_t)(kb + ty + rr) * OUT_F + nb + tx];
        __syncthreads();
        #pragma unroll
        for (int rr = 0; rr < 32; rr += 8) {
            int n = nb + ty + rr;
            g_ETh[(size_t)n * IN_F + kb + tx] = __float2half_rn(t[tx][ty + rr]);
        }
    } else {
        int p = b - MB_MKC;
        float s = 0.f;
        for (int j = p * 250; j < (p + 1) * 250; j++)
            s += kc[(size_t)j * IN_F + tid];
        g_mkcp[p][tid] = s;
    }
}

// ---------------- hgemm body ----------------
// use16==0: bf16 hi/lo 3-product. use16==1: fp16 single product (Ahi/Bhi raw fp16 bits).
// epi: 0 plain C write; 1 elu(C+bias) with virtual concat A; 2 write g_kcWhT fp16 transposed.
#define HOF_AH 0
#define HOF_AL 10240
#define HOF_BH 20480
#define HOF_BL 30720
static __device__ __forceinline__ void hgemm_body(char* smem,
    const bf16* __restrict__ Ahi, const bf16* __restrict__ Alo,
    const bf16* __restrict__ Bhi, const bf16* __restrict__ Blo,
    float* __restrict__ C, int M, int N, int K,
    const float* __restrict__ bias, int epi, const float* __restrict__ exF,
    int bx, int by, int use16)
{
    uint32_t sb = smem_u32(smem);
    int tid = threadIdx.x, lane = tid & 31, wid = tid >> 5;
    int bm = by * 128, bn = bx * 128;
    int wm = wid >> 1, wn = wid & 1;
    size_t astr = (epi == 1) ? 256 : (size_t)K;

    float acc[2][8][4];
    #pragma unroll
    for (int mt = 0; mt < 2; mt++)
        #pragma unroll
        for (int nb = 0; nb < 8; nb++)
            #pragma unroll
            for (int k = 0; k < 4; k++) acc[mt][nb][k] = 0.f;

    int crow = tid >> 1, chalf = tid & 1;
    bool arow_ok = (bm + crow) < M;
    const uint4 zero4 = make_uint4(0, 0, 0, 0);

    for (int k0 = 0; k0 < K; k0 += 32) {
        {
            char* dh = smem + HOF_AH + crow * RSTRIDE + chalf * 32;
            char* dl = smem + HOF_AL + crow * RSTRIDE + chalf * 32;
            if (!arow_ok) {
                ((uint4*)dh)[0] = zero4; ((uint4*)dh)[1] = zero4;
                if (!use16) { ((uint4*)dl)[0] = zero4; ((uint4*)dl)[1] = zero4; }
            } else if (epi == 1 && k0 >= 256) {
                size_t rb = (size_t)(bm + crow) * 256 + (k0 - 256) + chalf * 16;
                uint4 vh[2], vl[2];
                float4 vx[4];
                vh[0] = *(const uint4*)(Ahi + rb); vh[1] = *(const uint4*)(Ahi + rb + 8);
                vl[0] = *(const uint4*)(Alo + rb); vl[1] = *(const uint4*)(Alo + rb + 8);
                vx[0] = *(const float4*)(exF + rb);      vx[1] = *(const float4*)(exF + rb + 4);
                vx[2] = *(const float4*)(exF + rb + 8);  vx[3] = *(const float4*)(exF + rb + 12);
                const bf16* ph = (const bf16*)vh;
                const bf16* pl = (const bf16*)vl;
                const float* px = (const float*)vx;
                uint32_t oh[8], ol[8];
                #pragma unroll
                for (int e = 0; e < 8; e++) {
                    float q0 = (__bfloat162float(ph[2*e])   + __bfloat162float(pl[2*e]))   * px[2*e];
                    float q1 = (__bfloat162float(ph[2*e+1]) + __bfloat162float(pl[2*e+1])) * px[2*e+1];
                    bf16 H0, L0, H1, L1;
                    fsplit(q0, H0, L0); fsplit(q1, H1, L1);
                    oh[e] = pack2(H0, H1);
                    ol[e] = pack2(L0, L1);
                }
                ((uint4*)dh)[0] = *(uint4*)&oh[0]; ((uint4*)dh)[1] = *(uint4*)&oh[4];
                ((uint4*)dl)[0] = *(uint4*)&ol[0]; ((uint4*)dl)[1] = *(uint4*)&ol[4];
            } else {
                const uint4* sh = (const uint4*)(Ahi + (size_t)(bm + crow) * astr + k0 + chalf * 16);
                ((uint4*)dh)[0] = sh[0]; ((uint4*)dh)[1] = sh[1];
                if (!use16) {
                    const uint4* sl = (const uint4*)(Alo + (size_t)(bm + crow) * astr + k0 + chalf * 16);
                    ((uint4*)dl)[0] = sl[0]; ((uint4*)dl)[1] = sl[1];
                }
            }
        }
        {
            const uint4* sh = (const uint4*)(Bhi + (size_t)(bn + crow) * K + k0 + chalf * 16);
            char* dh = smem + HOF_BH + crow * RSTRIDE + chalf * 32;
            ((uint4*)dh)[0] = sh[0]; ((uint4*)dh)[1] = sh[1];
            if (!use16) {
                const uint4* sl = (const uint4*)(Blo + (size_t)(bn + crow) * K + k0 + chalf * 16);
                char* dl = smem + HOF_BL + crow * RSTRIDE + chalf * 32;
                ((uint4*)dl)[0] = sl[0]; ((uint4*)dl)[1] = sl[1];
            }
        }
        __syncthreads();

        #pragma unroll
        for (int ks = 0; ks < 2; ks++) {
            uint32_t ahi[2][4], alo[2][4], bfrag[8][2];
            int arowi = lane & 15;
            int akoff = (ks * 16 + ((lane >> 4) & 1) * 8) * 2;
            #pragma unroll
            for (int mt = 0; mt < 2; mt++) {
                uint32_t ad = sb + HOF_AH + (wm * 32 + mt * 16 + arowi) * RSTRIDE + akoff;
                LDSM_X4(ahi[mt][0], ahi[mt][1], ahi[mt][2], ahi[mt][3], ad);
                if (!use16) {
                    ad += (HOF_AL - HOF_AH);
                    LDSM_X4(alo[mt][0], alo[mt][1], alo[mt][2], alo[mt][3], ad);
                }
            }
            int bnrow = (lane & 7) + ((lane >> 4) << 3);
            int bkoff = (ks * 16 + ((lane >> 3) & 1) * 8) * 2;
            #pragma unroll
            for (int nq = 0; nq < 4; nq++) {
                uint32_t bd = sb + HOF_BH + (wn * 64 + nq * 16 + bnrow) * RSTRIDE + bkoff;
                LDSM_X4(bfrag[2 * nq][0], bfrag[2 * nq][1],
                        bfrag[2 * nq + 1][0], bfrag[2 * nq + 1][1], bd);
            }
            if (use16) {
                #pragma unroll
                for (int mt = 0; mt < 2; mt++)
                    #pragma unroll
                    for (int nb = 0; nb < 8; nb++)
                        mma_fp16(acc[mt][nb], ahi[mt], bfrag[nb]);
            } else {
                #pragma unroll
                for (int mt = 0; mt < 2; mt++)
                    #pragma unroll
                    for (int nb = 0; nb < 8; nb++)
                        mma_bf16(acc[mt][nb], ahi[mt], bfrag[nb]);
                #pragma unroll
                for (int mt = 0; mt < 2; mt++)
                    #pragma unroll
                    for (int nb = 0; nb < 8; nb++)
                        mma_bf16(acc[mt][nb], alo[mt], bfrag[nb]);
                #pragma unroll
                for (int nq = 0; nq < 4; nq++) {
                    uint32_t bd = sb + HOF_BL + (wn * 64 + nq * 16 + bnrow) * RSTRIDE + bkoff;
                    LDSM_X4(bfrag[2 * nq][0], bfrag[2 * nq][1],
                            bfrag[2 * nq + 1][0], bfrag[2 * nq + 1][1], bd);
                }
                #pragma unroll
                for (int mt = 0; mt < 2; mt++)
                    #pragma unroll
                    for (int nb = 0; nb < 8; nb++)
                        mma_bf16(acc[mt][nb], ahi[mt], bfrag[nb]);
            }
        }
        __syncthreads();
    }

    #pragma unroll
    for (int mt = 0; mt < 2; mt++) {
        #pragma unroll
        for (int nb = 0; nb < 8; nb++) {
            int row0 = wm * 32 + mt * 16 + (lane >> 2);
            int col = bn + wn * 64 + nb * 8 + (lane & 3) * 2;
            #pragma unroll
            for (int h = 0; h < 2; h++) {
                int r = bm + row0 + h * 8;
                float v0 = acc[mt][nb][2 * h];
                float v1 = acc[mt][nb][2 * h + 1];
                if (epi == 2) {
                    // transposed chunk-blocked fp16 write (r = j, zero-padded rows OK)
                    size_t base = ((size_t)(r >> 5) * 256);
                    g_kcWhT[(base + col)     * KC + (r & 31)] = __float2half_rn(v0);
                    g_kcWhT[(base + col + 1) * KC + (r & 31)] = __float2half_rn(v1);
                    continue;
                }
                if (r >= M) continue;
                if (epi == 1) {
                    v0 += bias[col];
                    v1 += bias[col + 1];
                    v0 = v0 > 0.f ? v0 : expm1f(v0);
                    v1 = v1 > 0.f ? v1 : expm1f(v1);
                }
                C[(size_t)r * N + col]     = v0;
                C[(size_t)r * N + col + 1] = v1;
            }
        }
    }
}

__global__ __launch_bounds__(256, 2) void hgemm_kernel(
    const bf16* __restrict__ Ahi, const bf16* __restrict__ Alo,
    const bf16* __restrict__ Bhi, const bf16* __restrict__ Blo,
    float* __restrict__ C, int M, int N, int K,
    const float* __restrict__ bias, int epi, const float* __restrict__ exF)
{
    extern __shared__ char smem[];
    hgemm_body(smem, Ahi, Alo, Bhi, Blo, C, M, N, K, bias, epi, exF,
               blockIdx.x, blockIdx.y, 0);
}

// ---------------- prep2: kcWh gemm (-> g_kcWhT) + rowdots + colmean ----------------
#define P2_GEMM 32
#define P2_E2   1282
#define P2_CM   1538
#define P2_TOT  1539
__global__ __launch_bounds__(256, 2) void prep2_kernel(
    const float* __restrict__ ex, const float* __restrict__ kc,
    const float* __restrict__ W1)
{
    extern __shared__ char smem[];
    int b = blockIdx.x, tid = threadIdx.x;
    int lane = tid & 31, warp = tid >> 5;
    if (b < P2_GEMM) {
        hgemm_body(smem, g_kchi, g_kclo, g_W1Thi, g_W1Tlo, nullptr,
                   N_KC, OUT_F, IN_F, nullptr, 2, nullptr, b & 1, b >> 1, 0);
    } else if (b < P2_E2) {
        int i = (b - P2_GEMM) * 8 + warp;
        if (i >= N_E) return;
        const float* row = ex + (size_t)i * IN_F;
        float s = 0.f;
        #pragma unroll
        for (int k = lane; k < IN_F; k += 32) s += row[k] * g_v1[k];
        #pragma unroll
        for (int o = 16; o; o >>= 1) s += __shfl_xor_sync(0xFFFFFFFFu, s, o);
        if (lane == 0) {
            g_Ae[i] = __expf(s);
            g_Ce[i] = __expf(ALPHA * s);
        }
    } else if (b < P2_CM) {
        int j = (b - P2_E2) * 8 + warp;
        if (j >= NKC_PAD) return;
        if (j < N_KC) {
            const float* row = kc + (size_t)j * IN_F;
            float s = 0.f;
            #pragma unroll
            for (int k = lane; k < IN_F; k += 32) s += row[k] * g_v2[k];
            #pragma unroll
            for (int o = 16; o; o >>= 1) s += __shfl_xor_sync(0xFFFFFFFFu, s, o);
            if (lane == 0)
                g_tab[j] = make_float2(__expf(s), __expf(ALPHA * s));
        } else if (lane == 0) {
            g_tab[j] = make_float2(0.f, 0.f);
        }
    } else {
        __shared__ float S[IN_F];
        float s = 0.f;
        #pragma unroll
        for (int p = 0; p < 8; p++) s += g_mkcp[p][tid];
        S[tid] = s;
        __syncthreads();
        float c = 0.f;
        #pragma unroll 8
        for (int k = 0; k < IN_F; k++)
            c += S[k] * W1[(size_t)k * OUT_F + tid];
        g_colmean[tid] = c * (1.0f / N_KC);
    }
}

// ---------------- attention body: single fp16 product, split-K, cp.async ----------------
#define AOF_B    0
#define AOF_BSZ  20480
#define AOF_A    40960
#define AOF_ASZ  5120
#define AOF_AE   51200
#define AOF_CE   51456
#define AOF_RS   51712
#define AOF_RSF  52736
#define SMEM_ATTN 53248

static __device__ __forceinline__ void cp_b_chunk(uint32_t sbB, int c, int tid)
{
    const __half* sh = g_kcWhT + ((size_t)c * 256 + tid) * KC;
    uint32_t dh = sbB + tid * RSTRIDE;
    #pragma unroll
    for (int t = 0; t < 4; t++)
        CP_ASYNC16(dh + t * 16, (const char*)sh + t * 16);
    CP_COMMIT();
}

static __device__ __forceinline__ void attn_body(char* smem, int tile, int half,
    const int* __restrict__ adj)
{
    uint32_t sb = smem_u32(smem);
    float* Aes = (float*)(smem + AOF_AE);
    float* Ces = (float*)(smem + AOF_CE);

    int tid = threadIdx.x, lane = tid & 31, wid = tid >> 5;
    int i0 = tile * MT;
    int c0 = half ? 32 : 0;
    int c1 = half ? NCHUNK_RUN : 32;

    cp_b_chunk(sb + AOF_B, c0, tid);

    if (tid < MT) {
        int gi = i0 + tid;
        bool v = gi < N_E;
        Aes[tid] = v ? g_Ae[gi] : 0.f;
        Ces[tid] = v ? g_Ce[gi] : 0.f;
    }
    __syncthreads();

    int r = tid >> 2, jl0 = (tid & 3) * 8;
    int gi_r = i0 + r;
    const int* arow = adj + (size_t)(gi_r < N_E ? gi_r : 0) * N_KC;
    float Ai = Aes[r], Ci = Ces[r];
    float srow = 0.f;

    int wm = wid & 1, wn = wid >> 1;
    float acc[2][8][4];
    #pragma unroll
    for (int mt = 0; mt < 2; mt++)
        #pragma unroll
        for (int nb = 0; nb < 8; nb++)
            #pragma unroll
            for (int k = 0; k < 4; k++) acc[mt][nb][k] = 0.f;

    for (int c = c0; c < c1; c++) {
        int buf = (c - c0) & 1;
        int j0 = c * KC;
        uint32_t aBase = sb + AOF_A + buf * AOF_ASZ;

        {
            float p[8];
            if (j0 + KC <= N_KC) {
                const int4* ap = (const int4*)(arow + j0 + jl0);
                int4 a0 = ap[0], a1 = ap[1];
                int am[8] = {a0.x, a0.y, a0.z, a0.w, a1.x, a1.y, a1.z, a1.w};
                #pragma unroll
                for (int e = 0; e < 8; e++) {
                    float2 t = __ldg(&g_tab[j0 + jl0 + e]);
                    float pv = Ai * t.x;
                    float v = (pv > 1.f) ? pv : Ci * t.y;
                    p[e] = (am[e] > 0) ? v : 0.f;
                }
            } else {
                #pragma unroll
                for (int e = 0; e < 8; e++) {
                    int j = j0 + jl0 + e;
                    int m = (j < N_KC) ? arow[j] : 0;
                    float2 t = __ldg(&g_tab[(j < N_KC) ? j : 0]);
                    float pv = Ai * t.x;
                    float v = (pv > 1.f) ? pv : Ci * t.y;
                    p[e] = (m > 0) ? v : 0.f;
                }
            }
            #pragma unroll
            for (int e = 0; e < 8; e++) srow += p[e];
            __half2 q0 = __floats2half2_rn(p[0], p[1]);
            __half2 q1 = __floats2half2_rn(p[2], p[3]);
            __half2 q2 = __floats2half2_rn(p[4], p[5]);
            __half2 q3 = __floats2half2_rn(p[6], p[7]);
            uint4 w = make_uint4(*(uint32_t*)&q0, *(uint32_t*)&q1,
                                 *(uint32_t*)&q2, *(uint32_t*)&q3);
            *(uint4*)(smem + AOF_A + buf * AOF_ASZ + r * RSTRIDE + jl0 * 2) = w;
        }

        CP_WAIT0();
        __syncthreads();

        if (c + 1 < c1)
            cp_b_chunk(sb + AOF_B + (buf ^ 1) * AOF_BSZ, c + 1, tid);

        uint32_t bBase = sb + AOF_B + buf * AOF_BSZ;
        #pragma unroll
        for (int ks = 0; ks < 2; ks++) {
            uint32_t af[2][4], bfrag[8][2];
            int arowi = lane & 15;
            int akoff = (ks * 16 + ((lane >> 4) & 1) * 8) * 2;
            #pragma unroll
            for (int mt = 0; mt < 2; mt++) {
                uint32_t ad = aBase + (wm * 32 + mt * 16 + arowi) * RSTRIDE + akoff;
                LDSM_X4(af[mt][0], af[mt][1], af[mt][2], af[mt][3], ad);
            }
            int bnrow = (lane & 7) + ((lane >> 4) << 3);
            int bkoff = (ks * 16 + ((lane >> 3) & 1) * 8) * 2;
            #pragma unroll
            for (int nq = 0; nq < 4; nq++) {
                uint32_t bd = bBase + (wn * 64 + nq * 16 + bnrow) * RSTRIDE + bkoff;
                LDSM_X4(bfrag[2 * nq][0], bfrag[2 * nq][1],
                        bfrag[2 * nq + 1][0], bfrag[2 * nq + 1][1], bd);
            }
            #pragma unroll
            for (int mt = 0; mt < 2; mt++)
                #pragma unroll
                for (int nb = 0; nb < 8; nb++)
                    mma_fp16(acc[mt][nb], af[mt], bfrag[nb]);
        }
    }

    __syncthreads();
    ((float*)(smem + AOF_RS))[tid] = srow;
    __syncthreads();
    if (tid < MT) {
        const float* r4 = (const float*)(smem + AOF_RS) + tid * 4;
        ((float*)(smem + AOF_RSF))[tid] = (r4[0] + r4[1]) + (r4[2] + r4[3]);
    }
    __syncthreads();
    const float* rsF = (const float*)(smem + AOF_RSF);

    #pragma unroll
    for (int mt = 0; mt < 2; mt++) {
        #pragma unroll
        for (int nb = 0; nb < 8; nb++) {
            int row0 = wm * 32 + mt * 16 + (lane >> 2);
            int col  = wn * 64 + nb * 8 + (lane & 3) * 2;
            #pragma unroll
            for (int h = 0; h < 2; h++) {
                int rr = row0 + h * 8;
                int gi = i0 + rr;
                if (gi >= N_E) continue;
                *(float2*)&g_pacc[half][(size_t)gi * OUT_F + col] =
                    make_float2(acc[mt][nb][2 * h], acc[mt][nb][2 * h + 1]);
            }
        }
    }
    if (tid < MT) g_psr[half][tile * MT + tid] = rsF[tid];
    __threadfence();
    __syncthreads();

    __shared__ int sLast;
    if (tid == 0) sLast = (atomicAdd(&g_cnt[tile], 1) == 1);
    __syncthreads();
    if (!sLast) return;

    int other = half ^ 1;
    if (tid < MT)
        ((float*)(smem + AOF_RS))[tid] = rsF[tid] + g_psr[other][tile * MT + tid];
    __syncthreads();
    const float* rsC = (const float*)(smem + AOF_RS);

    #pragma unroll
    for (int mt = 0; mt < 2; mt++) {
        #pragma unroll
        for (int nb = 0; nb < 8; nb++) {
            int row0 = wm * 32 + mt * 16 + (lane >> 2);
            int col  = wn * 64 + nb * 8 + (lane & 3) * 2;
            #pragma unroll
            for (int h = 0; h < 2; h++) {
                int rr = row0 + h * 8;
                int gi = i0 + rr;
                if (gi >= N_E) continue;
                float2 po = *(const float2*)&g_pacc[other][(size_t)gi * OUT_F + col];
                float v0 = acc[mt][nb][2 * h]     + po.x;
                float v1 = acc[mt][nb][2 * h + 1] + po.y;
                float rs = rsC[rr];
                float nk0, nk1;
                if (rs > 0.f) {
                    float ri = 1.f / rs;
                    nk0 = v0 * ri;
                    nk1 = v1 * ri;
                } else {
                    nk0 = g_colmean[col];
                    nk1 = g_colmean[col + 1];
                }
                size_t fb = (size_t)gi * OUT_F + col;
                bf16 h0, l0, h1, l1;
                fsplit(nk0, h0, l0); fsplit(nk1, h1, l1);
                *(uint32_t*)(g_feathi + fb) = pack2(h0, h1);
                *(uint32_t*)(g_featlo + fb) = pack2(l0, l1);
            }
        }
    }
}

// ---------------- fused kernel: attention split-K + exEh fp16 GEMM tail ----------------
__global__ __launch_bounds__(256, 2) void attn_fused_kernel(const int* __restrict__ adj)
{
    extern __shared__ char smem[];
    if (blockIdx.x < NATTN2) {
        attn_body(smem, (int)(blockIdx.x >> 1), (int)(blockIdx.x & 1), adj);
    } else {
        int g = blockIdx.x - NATTN2;
        hgemm_body(smem, (const bf16*)g_exh, nullptr, (const bf16*)g_ETh, nullptr,
                   (float*)g_exEh, N_E, OUT_F, IN_F, nullptr, 0, nullptr,
                   g & 1, g >> 1, 1);
    }
}

// ---------------- launch ----------------
extern "C" void kernel_launch(void* const* d_in, const int* in_sizes, int n_in,
                              void* d_out, int out_size)
{
    const float* ex   = (const float*)d_in[0];
    const float* kc   = (const float*)d_in[1];
    const int*   adj  = (const int*)d_in[2];
    const float* W1   = (const float*)d_in[3];
    const float* E    = (const float*)d_in[4];
    const float* a    = (const float*)d_in[5];
    const float* rd_w = (const float*)d_in[6];
    const float* rd_b = (const float*)d_in[7];
    float* out = (float*)d_out;

    float* exEh;
    bf16 *rdwhi, *rdwlo, *feathi, *featlo;
    cudaGetSymbolAddress((void**)&exEh, g_exEh);
    cudaGetSymbolAddress((void**)&rdwhi, g_rdwhi);
    cudaGetSymbolAddress((void**)&rdwlo, g_rdwlo);
    cudaGetSymbolAddress((void**)&feathi, g_feathi);
    cudaGetSymbolAddress((void**)&featlo, g_featlo);

    cudaFuncSetAttribute(attn_fused_kernel,
                         cudaFuncAttributeMaxDynamicSharedMemorySize, SMEM_ATTN);
    cudaFuncSetAttribute(hgemm_kernel,
                         cudaFuncAttributeMaxDynamicSharedMemorySize, 40960);
    cudaFuncSetAttribute(prep2_kernel,
                         cudaFuncAttributeMaxDynamicSharedMemorySize, 40960);

    // 0. prep + splits + kc colsum partials + flag reset
    mega_kernel<<<MB_TOT, 256>>>(ex, kc, rd_w, W1, E, a);

    // 1. kcWh gemm (-> g_kcWhT fp16 direct) + rowdots + exp tables + colmean
    prep2_kernel<<<P2_TOT, 256, 40960>>>(ex, kc, W1);

    // 2. fused: attention split-K (314) + exEh fp16 GEMM (158)
    attn_fused_kernel<<<NATTN2 + NGEX, 256, SMEM_ATTN>>>(adj);

    // 3. out = elu([nk | nk*exEh] @ rd_w^T + rd_b)   [10000,256]
    hgemm_kernel<<<dim3(OUT_F / 128, (N_E + 127) / 128), 256, 40960>>>(
        feathi, featlo, rdwhi, rdwlo, out, N_E, OUT_F, 2 * OUT_F, rd_b, 1, exEh);
}

// round 15
// speedup vs baseline: 2.4364x; 1.1159x over previous
#include <cuda_runtime.h>
#include <cuda_bf16.h>
#include <cuda_fp16.h>
#include <math.h>
#include <stdint.h>

#define IN_F   256
#define OUT_F  256
#define N_E    10000
#define N_KC   2000
#define ALPHA  0.2f

#define MT      64
#define KC      32
#define NKC_PAD 2048
#define NCHUNK_RUN 63
#define RSTRIDE 80

#define NGEX    158
#define NATTN   157
#define NATTN2  (2 * NATTN)

typedef __nv_bfloat16 bf16;

// ---------------- scratch ----------------
__device__ float g_exEh[N_E * OUT_F];
__device__ float g_v1[IN_F];
__device__ float g_v2[IN_F];
__device__ __half g_kcWhT[OUT_F * NKC_PAD];   // fp16, chunk-blocked transposed
__device__ float g_colmean[OUT_F];
__device__ float g_mkcp[8][IN_F];
__device__ float g_Ae[N_E];
__device__ float g_Ce[N_E];
__device__ float2 g_tab[NKC_PAD];
__device__ __half g_exh[N_E * IN_F];          // fp16 ex
__device__ __half g_ETh[OUT_F * IN_F];        // fp16 E^T [n][k]
__device__ bf16 g_kchi[N_KC * IN_F];
__device__ bf16 g_kclo[N_KC * IN_F];
__device__ bf16 g_W1Thi[OUT_F * IN_F];
__device__ bf16 g_W1Tlo[OUT_F * IN_F];
__device__ __half g_rdwh[OUT_F * 2 * OUT_F];  // fp16 rd_w [n=256][k=512]
__device__ __half g_feath[N_E * OUT_F];       // fp16 new_kc
// split-K partials
__device__ float g_pacc[2][N_E * OUT_F];
__device__ float g_psr[2][NATTN * MT];
__device__ int   g_cnt[NATTN];

// ---------------- helpers ----------------
static __device__ __forceinline__ uint32_t smem_u32(const void* p) {
    uint32_t a;
    asm("{ .reg .u64 t; cvta.to.shared.u64 t, %1; cvt.u32.u64 %0, t; }" : "=r"(a) : "l"(p));
    return a;
}
#define LDSM_X4(R0,R1,R2,R3,ADDR) \
    asm volatile("ldmatrix.sync.aligned.m8n8.x4.shared.b16 {%0,%1,%2,%3}, [%4];" \
                 : "=r"(R0),"=r"(R1),"=r"(R2),"=r"(R3) : "r"(ADDR))
#define CP_ASYNC16(dst, src) \
    asm volatile("cp.async.ca.shared.global [%0], [%1], 16;" :: "r"(dst), "l"(src))
#define CP_COMMIT() asm volatile("cp.async.commit_group;" ::: "memory")
#define CP_WAIT0()  asm volatile("cp.async.wait_group 0;" ::: "memory")

static __device__ __forceinline__ void mma_bf16(float* c, const uint32_t* a, const uint32_t* b) {
    asm volatile(
        "mma.sync.aligned.m16n8k16.row.col.f32.bf16.bf16.f32 "
        "{%0,%1,%2,%3}, {%4,%5,%6,%7}, {%8,%9}, {%0,%1,%2,%3};"
        : "+f"(c[0]), "+f"(c[1]), "+f"(c[2]), "+f"(c[3])
        : "r"(a[0]), "r"(a[1]), "r"(a[2]), "r"(a[3]), "r"(b[0]), "r"(b[1]));
}
static __device__ __forceinline__ void mma_fp16(float* c, const uint32_t* a, const uint32_t* b) {
    asm volatile(
        "mma.sync.aligned.m16n8k16.row.col.f32.f16.f16.f32 "
        "{%0,%1,%2,%3}, {%4,%5,%6,%7}, {%8,%9}, {%0,%1,%2,%3};"
        : "+f"(c[0]), "+f"(c[1]), "+f"(c[2]), "+f"(c[3])
        : "r"(a[0]), "r"(a[1]), "r"(a[2]), "r"(a[3]), "r"(b[0]), "r"(b[1]));
}
static __device__ __forceinline__ void fsplit(float v, bf16& h, bf16& l) {
    h = __float2bfloat16(v);
    l = __float2bfloat16(v - __bfloat162float(h));
}
static __device__ __forceinline__ uint32_t pack2(bf16 a, bf16 b) {
    __nv_bfloat162 t = __halves2bfloat162(a, b);
    return *(uint32_t*)&t;
}
static __device__ __forceinline__ void split4_store(const float4 v, bf16* hi, bf16* lo) {
    bf16 h0, l0, h1, l1, h2, l2, h3, l3;
    fsplit(v.x, h0, l0); fsplit(v.y, h1, l1);
    fsplit(v.z, h2, l2); fsplit(v.w, h3, l3);
    *(uint32_t*)(hi)     = pack2(h0, h1);
    *(uint32_t*)(hi + 2) = pack2(h2, h3);
    *(uint32_t*)(lo)     = pack2(l0, l1);
    *(uint32_t*)(lo + 2) = pack2(l2, l3);
}
static __device__ __forceinline__ void half4_store(const float4 v, __half* dst) {
    __half2 a0 = __floats2half2_rn(v.x, v.y);
    __half2 a1 = __floats2half2_rn(v.z, v.w);
    *(uint32_t*)(dst)     = *(uint32_t*)&a0;
    *(uint32_t*)(dst + 2) = *(uint32_t*)&a1;
}

// ---------------- mega kernel ----------------
#define MB_EX   1
#define MB_KC   2501
#define MB_RDW  3001
#define MB_TW1  3129
#define MB_TE   3193
#define MB_MKC  3257
#define MB_TOT  3265
__global__ void mega_kernel(const float* __restrict__ ex, const float* __restrict__ kc,
                            const float* __restrict__ rdw, const float* __restrict__ W1,
                            const float* __restrict__ E, const float* __restrict__ a)
{
    int b = blockIdx.x, tid = threadIdx.x;
    if (b < MB_EX) {
        int k = tid;
        float s1 = 0.f, s2 = 0.f;
        #pragma unroll 8
        for (int j = 0; j < OUT_F; j++) {
            float w = W1[k * OUT_F + j];
            s1 += w * a[j];
            s2 += w * a[OUT_F + j];
        }
        g_v1[k] = s1;
        g_v2[k] = s2;
        if (tid < NATTN) g_cnt[tid] = 0;
    } else if (b < MB_KC) {
        size_t i = ((size_t)(b - MB_EX) * 256 + tid) * 4;
        half4_store(*(const float4*)(ex + i), g_exh + i);
    } else if (b < MB_RDW) {
        size_t i = ((size_t)(b - MB_KC) * 256 + tid) * 4;
        split4_store(*(const float4*)(kc + i), g_kchi + i, g_kclo + i);
    } else if (b < MB_TW1) {
        size_t i = ((size_t)(b - MB_RDW) * 256 + tid) * 4;
        half4_store(*(const float4*)(rdw + i), g_rdwh + i);
    } else if (b < MB_TE) {
        // W1 transpose hi/lo
        int bb = b - MB_TW1;
        __shared__ float t[32][33];
        int kb = (bb & 7) * 32, nb = (bb >> 3) * 32;
        int tx = tid & 31, ty = tid >> 5;
        #pragma unroll
        for (int rr = 0; rr < 32; rr += 8)
            t[ty + rr][tx] = W1[(size_t)(kb + ty + rr) * OUT_F + nb + tx];
        __syncthreads();
        #pragma unroll
        for (int rr = 0; rr < 32; rr += 8) {
            int n = nb + ty + rr;
            bf16 h, l;
            fsplit(t[tx][ty + rr], h, l);
            g_W1Thi[(size_t)n * IN_F + kb + tx] = h;
            g_W1Tlo[(size_t)n * IN_F + kb + tx] = l;
        }
    } else if (b < MB_MKC) {
        // E transpose fp16
        int bb = b - MB_TE;
        __shared__ float t[32][33];
        int kb = (bb & 7) * 32, nb = (bb >> 3) * 32;
        int tx = tid & 31, ty = tid >> 5;
        #pragma unroll
        for (int rr = 0; rr < 32; rr += 8)
            t[ty + rr][tx] = E[(size_t)(kb + ty + rr) * OUT_F + nb + tx];
        __syncthreads();
        #pragma unroll
        for (int rr = 0; rr < 32; rr += 8) {
            int n = nb + ty + rr;
            g_ETh[(size_t)n * IN_F + kb + tx] = __float2half_rn(t[tx][ty + rr]);
        }
    } else {
        int p = b - MB_MKC;
        float s = 0.f;
        for (int j = p * 250; j < (p + 1) * 250; j++)
            s += kc[(size_t)j * IN_F + tid];
        g_mkcp[p][tid] = s;
    }
}

// ---------------- hgemm body ----------------
// use16==0: bf16 hi/lo 3-product. use16==1: fp16 single product.
// epi: 0 plain; 1 elu(C+bias), fp16 virtual concat A = [nk | nk*exEh]; 2 -> g_kcWhT.
#define HOF_AH 0
#define HOF_AL 10240
#define HOF_BH 20480
#define HOF_BL 30720
static __device__ __forceinline__ void hgemm_body(char* smem,
    const bf16* __restrict__ Ahi, const bf16* __restrict__ Alo,
    const bf16* __restrict__ Bhi, const bf16* __restrict__ Blo,
    float* __restrict__ C, int M, int N, int K,
    const float* __restrict__ bias, int epi, const float* __restrict__ exF,
    int bx, int by, int use16)
{
    uint32_t sb = smem_u32(smem);
    int tid = threadIdx.x, lane = tid & 31, wid = tid >> 5;
    int bm = by * 128, bn = bx * 128;
    int wm = wid >> 1, wn = wid & 1;
    size_t astr = (epi == 1) ? 256 : (size_t)K;

    float acc[2][8][4];
    #pragma unroll
    for (int mt = 0; mt < 2; mt++)
        #pragma unroll
        for (int nb = 0; nb < 8; nb++)
            #pragma unroll
            for (int k = 0; k < 4; k++) acc[mt][nb][k] = 0.f;

    int crow = tid >> 1, chalf = tid & 1;
    bool arow_ok = (bm + crow) < M;
    const uint4 zero4 = make_uint4(0, 0, 0, 0);

    for (int k0 = 0; k0 < K; k0 += 32) {
        {
            char* dh = smem + HOF_AH + crow * RSTRIDE + chalf * 32;
            char* dl = smem + HOF_AL + crow * RSTRIDE + chalf * 32;
            if (!arow_ok) {
                ((uint4*)dh)[0] = zero4; ((uint4*)dh)[1] = zero4;
                if (!use16) { ((uint4*)dl)[0] = zero4; ((uint4*)dl)[1] = zero4; }
            } else if (epi == 1 && k0 >= 256) {
                // virtual A (fp16): nk * exEh, 16 halves per thread-half
                size_t rb = (size_t)(bm + crow) * 256 + (k0 - 256) + chalf * 16;
                uint4 vh[2];
                float4 vx[4];
                vh[0] = *(const uint4*)((const __half*)Ahi + rb);
                vh[1] = *(const uint4*)((const __half*)Ahi + rb + 8);
                vx[0] = *(const float4*)(exF + rb);      vx[1] = *(const float4*)(exF + rb + 4);
                vx[2] = *(const float4*)(exF + rb + 8);  vx[3] = *(const float4*)(exF + rb + 12);
                const __half* ph = (const __half*)vh;
                const float* px = (const float*)vx;
                uint32_t oh[8];
                #pragma unroll
                for (int e = 0; e < 8; e++) {
                    float q0 = __half2float(ph[2*e])   * px[2*e];
                    float q1 = __half2float(ph[2*e+1]) * px[2*e+1];
                    __half2 t = __floats2half2_rn(q0, q1);
                    oh[e] = *(uint32_t*)&t;
                }
                ((uint4*)dh)[0] = *(uint4*)&oh[0]; ((uint4*)dh)[1] = *(uint4*)&oh[4];
            } else {
                const uint4* sh = (const uint4*)(Ahi + (size_t)(bm + crow) * astr + k0 + chalf * 16);
                ((uint4*)dh)[0] = sh[0]; ((uint4*)dh)[1] = sh[1];
                if (!use16) {
                    const uint4* sl = (const uint4*)(Alo + (size_t)(bm + crow) * astr + k0 + chalf * 16);
                    ((uint4*)dl)[0] = sl[0]; ((uint4*)dl)[1] = sl[1];
                }
            }
        }
        {
            const uint4* sh = (const uint4*)(Bhi + (size_t)(bn + crow) * K + k0 + chalf * 16);
            char* dh = smem + HOF_BH + crow * RSTRIDE + chalf * 32;
            ((uint4*)dh)[0] = sh[0]; ((uint4*)dh)[1] = sh[1];
            if (!use16) {
                const uint4* sl = (const uint4*)(Blo + (size_t)(bn + crow) * K + k0 + chalf * 16);
                char* dl = smem + HOF_BL + crow * RSTRIDE + chalf * 32;
                ((uint4*)dl)[0] = sl[0]; ((uint4*)dl)[1] = sl[1];
            }
        }
        __syncthreads();

        #pragma unroll
        for (int ks = 0; ks < 2; ks++) {
            uint32_t ahi[2][4], alo[2][4], bfrag[8][2];
            int arowi = lane & 15;
            int akoff = (ks * 16 + ((lane >> 4) & 1) * 8) * 2;
            #pragma unroll
            for (int mt = 0; mt < 2; mt++) {
                uint32_t ad = sb + HOF_AH + (wm * 32 + mt * 16 + arowi) * RSTRIDE + akoff;
                LDSM_X4(ahi[mt][0], ahi[mt][1], ahi[mt][2], ahi[mt][3], ad);
                if (!use16) {
                    ad += (HOF_AL - HOF_AH);
                    LDSM_X4(alo[mt][0], alo[mt][1], alo[mt][2], alo[mt][3], ad);
                }
            }
            int bnrow = (lane & 7) + ((lane >> 4) << 3);
            int bkoff = (ks * 16 + ((lane >> 3) & 1) * 8) * 2;
            #pragma unroll
            for (int nq = 0; nq < 4; nq++) {
                uint32_t bd = sb + HOF_BH + (wn * 64 + nq * 16 + bnrow) * RSTRIDE + bkoff;
                LDSM_X4(bfrag[2 * nq][0], bfrag[2 * nq][1],
                        bfrag[2 * nq + 1][0], bfrag[2 * nq + 1][1], bd);
            }
            if (use16) {
                #pragma unroll
                for (int mt = 0; mt < 2; mt++)
                    #pragma unroll
                    for (int nb = 0; nb < 8; nb++)
                        mma_fp16(acc[mt][nb], ahi[mt], bfrag[nb]);
            } else {
                #pragma unroll
                for (int mt = 0; mt < 2; mt++)
                    #pragma unroll
                    for (int nb = 0; nb < 8; nb++)
                        mma_bf16(acc[mt][nb], ahi[mt], bfrag[nb]);
                #pragma unroll
                for (int mt = 0; mt < 2; mt++)
                    #pragma unroll
                    for (int nb = 0; nb < 8; nb++)
                        mma_bf16(acc[mt][nb], alo[mt], bfrag[nb]);
                #pragma unroll
                for (int nq = 0; nq < 4; nq++) {
                    uint32_t bd = sb + HOF_BL + (wn * 64 + nq * 16 + bnrow) * RSTRIDE + bkoff;
                    LDSM_X4(bfrag[2 * nq][0], bfrag[2 * nq][1],
                            bfrag[2 * nq + 1][0], bfrag[2 * nq + 1][1], bd);
                }
                #pragma unroll
                for (int mt = 0; mt < 2; mt++)
                    #pragma unroll
                    for (int nb = 0; nb < 8; nb++)
                        mma_bf16(acc[mt][nb], ahi[mt], bfrag[nb]);
            }
        }
        __syncthreads();
    }

    #pragma unroll
    for (int mt = 0; mt < 2; mt++) {
        #pragma unroll
        for (int nb = 0; nb < 8; nb++) {
            int row0 = wm * 32 + mt * 16 + (lane >> 2);
            int col = bn + wn * 64 + nb * 8 + (lane & 3) * 2;
            #pragma unroll
            for (int h = 0; h < 2; h++) {
                int r = bm + row0 + h * 8;
                float v0 = acc[mt][nb][2 * h];
                float v1 = acc[mt][nb][2 * h + 1];
                if (epi == 2) {
                    size_t base = ((size_t)(r >> 5) * 256);
                    g_kcWhT[(base + col)     * KC + (r & 31)] = __float2half_rn(v0);
                    g_kcWhT[(base + col + 1) * KC + (r & 31)] = __float2half_rn(v1);
                    continue;
                }
                if (r >= M) continue;
                if (epi == 1) {
                    v0 += bias[col];
                    v1 += bias[col + 1];
                    v0 = v0 > 0.f ? v0 : expm1f(v0);
                    v1 = v1 > 0.f ? v1 : expm1f(v1);
                }
                C[(size_t)r * N + col]     = v0;
                C[(size_t)r * N + col + 1] = v1;
            }
        }
    }
}

__global__ __launch_bounds__(256, 2) void hgemm_kernel(
    const bf16* __restrict__ Ahi, const bf16* __restrict__ Alo,
    const bf16* __restrict__ Bhi, const bf16* __restrict__ Blo,
    float* __restrict__ C, int M, int N, int K,
    const float* __restrict__ bias, int epi, const float* __restrict__ exF, int use16)
{
    extern __shared__ char smem[];
    hgemm_body(smem, Ahi, Alo, Bhi, Blo, C, M, N, K, bias, epi, exF,
               blockIdx.x, blockIdx.y, use16);
}

// ---------------- prep2: kcWh gemm (-> g_kcWhT) + rowdots + colmean ----------------
#define P2_GEMM 32
#define P2_E2   1282
#define P2_CM   1538
#define P2_TOT  1539
__global__ __launch_bounds__(256, 2) void prep2_kernel(
    const float* __restrict__ ex, const float* __restrict__ kc,
    const float* __restrict__ W1)
{
    extern __shared__ char smem[];
    int b = blockIdx.x, tid = threadIdx.x;
    int lane = tid & 31, warp = tid >> 5;
    if (b < P2_GEMM) {
        hgemm_body(smem, g_kchi, g_kclo, g_W1Thi, g_W1Tlo, nullptr,
                   N_KC, OUT_F, IN_F, nullptr, 2, nullptr, b & 1, b >> 1, 0);
    } else if (b < P2_E2) {
        int i = (b - P2_GEMM) * 8 + warp;
        if (i >= N_E) return;
        const float* row = ex + (size_t)i * IN_F;
        float s = 0.f;
        #pragma unroll
        for (int k = lane; k < IN_F; k += 32) s += row[k] * g_v1[k];
        #pragma unroll
        for (int o = 16; o; o >>= 1) s += __shfl_xor_sync(0xFFFFFFFFu, s, o);
        if (lane == 0) {
            g_Ae[i] = __expf(s);
            g_Ce[i] = __expf(ALPHA * s);
        }
    } else if (b < P2_CM) {
        int j = (b - P2_E2) * 8 + warp;
        if (j >= NKC_PAD) return;
        if (j < N_KC) {
            const float* row = kc + (size_t)j * IN_F;
            float s = 0.f;
            #pragma unroll
            for (int k = lane; k < IN_F; k += 32) s += row[k] * g_v2[k];
            #pragma unroll
            for (int o = 16; o; o >>= 1) s += __shfl_xor_sync(0xFFFFFFFFu, s, o);
            if (lane == 0)
                g_tab[j] = make_float2(__expf(s), __expf(ALPHA * s));
        } else if (lane == 0) {
            g_tab[j] = make_float2(0.f, 0.f);
        }
    } else {
        __shared__ float S[IN_F];
        float s = 0.f;
        #pragma unroll
        for (int p = 0; p < 8; p++) s += g_mkcp[p][tid];
        S[tid] = s;
        __syncthreads();
        float c = 0.f;
        #pragma unroll 8
        for (int k = 0; k < IN_F; k++)
            c += S[k] * W1[(size_t)k * OUT_F + tid];
        g_colmean[tid] = c * (1.0f / N_KC);
    }
}

// ---------------- attention body: single fp16 product, split-K, cp.async ----------------
#define AOF_B    0
#define AOF_BSZ  20480
#define AOF_A    40960
#define AOF_ASZ  5120
#define AOF_AE   51200
#define AOF_CE   51456
#define AOF_RS   51712
#define AOF_RSF  52736
#define SMEM_ATTN 53248

static __device__ __forceinline__ void cp_b_chunk(uint32_t sbB, int c, int tid)
{
    const __half* sh = g_kcWhT + ((size_t)c * 256 + tid) * KC;
    uint32_t dh = sbB + tid * RSTRIDE;
    #pragma unroll
    for (int t = 0; t < 4; t++)
        CP_ASYNC16(dh + t * 16, (const char*)sh + t * 16);
    CP_COMMIT();
}

static __device__ __forceinline__ void attn_body(char* smem, int tile, int half,
    const int* __restrict__ adj)
{
    uint32_t sb = smem_u32(smem);
    float* Aes = (float*)(smem + AOF_AE);
    float* Ces = (float*)(smem + AOF_CE);

    int tid = threadIdx.x, lane = tid & 31, wid = tid >> 5;
    int i0 = tile * MT;
    int c0 = half ? 32 : 0;
    int c1 = half ? NCHUNK_RUN : 32;

    cp_b_chunk(sb + AOF_B, c0, tid);

    if (tid < MT) {
        int gi = i0 + tid;
        bool v = gi < N_E;
        Aes[tid] = v ? g_Ae[gi] : 0.f;
        Ces[tid] = v ? g_Ce[gi] : 0.f;
    }
    __syncthreads();

    int r = tid >> 2, jl0 = (tid & 3) * 8;
    int gi_r = i0 + r;
    const int* arow = adj + (size_t)(gi_r < N_E ? gi_r : 0) * N_KC;
    float Ai = Aes[r], Ci = Ces[r];
    float srow = 0.f;

    int wm = wid & 1, wn = wid >> 1;
    float acc[2][8][4];
    #pragma unroll
    for (int mt = 0; mt < 2; mt++)
        #pragma unroll
        for (int nb = 0; nb < 8; nb++)
            #pragma unroll
            for (int k = 0; k < 4; k++) acc[mt][nb][k] = 0.f;

    for (int c = c0; c < c1; c++) {
        int buf = (c - c0) & 1;
        int j0 = c * KC;
        uint32_t aBase = sb + AOF_A + buf * AOF_ASZ;

        {
            float p[8];
            if (j0 + KC <= N_KC) {
                const int4* ap = (const int4*)(arow + j0 + jl0);
                int4 a0 = ap[0], a1 = ap[1];
                int am[8] = {a0.x, a0.y, a0.z, a0.w, a1.x, a1.y, a1.z, a1.w};
                #pragma unroll
                for (int e = 0; e < 8; e++) {
                    float2 t = __ldg(&g_tab[j0 + jl0 + e]);
                    float pv = Ai * t.x;
                    float v = (pv > 1.f) ? pv : Ci * t.y;
                    p[e] = (am[e] > 0) ? v : 0.f;
                }
            } else {
                #pragma unroll
                for (int e = 0; e < 8; e++) {
                    int j = j0 + jl0 + e;
                    int m = (j < N_KC) ? arow[j] : 0;
                    float2 t = __ldg(&g_tab[(j < N_KC) ? j : 0]);
                    float pv = Ai * t.x;
                    float v = (pv > 1.f) ? pv : Ci * t.y;
                    p[e] = (m > 0) ? v : 0.f;
                }
            }
            #pragma unroll
            for (int e = 0; e < 8; e++) srow += p[e];
            __half2 q0 = __floats2half2_rn(p[0], p[1]);
            __half2 q1 = __floats2half2_rn(p[2], p[3]);
            __half2 q2 = __floats2half2_rn(p[4], p[5]);
            __half2 q3 = __floats2half2_rn(p[6], p[7]);
            uint4 w = make_uint4(*(uint32_t*)&q0, *(uint32_t*)&q1,
                                 *(uint32_t*)&q2, *(uint32_t*)&q3);
            *(uint4*)(smem + AOF_A + buf * AOF_ASZ + r * RSTRIDE + jl0 * 2) = w;
        }

        CP_WAIT0();
        __syncthreads();

        if (c + 1 < c1)
            cp_b_chunk(sb + AOF_B + (buf ^ 1) * AOF_BSZ, c + 1, tid);

        uint32_t bBase = sb + AOF_B + buf * AOF_BSZ;
        #pragma unroll
        for (int ks = 0; ks < 2; ks++) {
            uint32_t af[2][4], bfrag[8][2];
            int arowi = lane & 15;
            int akoff = (ks * 16 + ((lane >> 4) & 1) * 8) * 2;
            #pragma unroll
            for (int mt = 0; mt < 2; mt++) {
                uint32_t ad = aBase + (wm * 32 + mt * 16 + arowi) * RSTRIDE + akoff;
                LDSM_X4(af[mt][0], af[mt][1], af[mt][2], af[mt][3], ad);
            }
            int bnrow = (lane & 7) + ((lane >> 4) << 3);
            int bkoff = (ks * 16 + ((lane >> 3) & 1) * 8) * 2;
            #pragma unroll
            for (int nq = 0; nq < 4; nq++) {
                uint32_t bd = bBase + (wn * 64 + nq * 16 + bnrow) * RSTRIDE + bkoff;
                LDSM_X4(bfrag[2 * nq][0], bfrag[2 * nq][1],
                        bfrag[2 * nq + 1][0], bfrag[2 * nq + 1][1], bd);
            }
            #pragma unroll
            for (int mt = 0; mt < 2; mt++)
                #pragma unroll
                for (int nb = 0; nb < 8; nb++)
                    mma_fp16(acc[mt][nb], af[mt], bfrag[nb]);
        }
    }

    __syncthreads();
    ((float*)(smem + AOF_RS))[tid] = srow;
    __syncthreads();
    if (tid < MT) {
        const float* r4 = (const float*)(smem + AOF_RS) + tid * 4;
        ((float*)(smem + AOF_RSF))[tid] = (r4[0] + r4[1]) + (r4[2] + r4[3]);
    }
    __syncthreads();
    const float* rsF = (const float*)(smem + AOF_RSF);

    #pragma unroll
    for (int mt = 0; mt < 2; mt++) {
        #pragma unroll
        for (int nb = 0; nb < 8; nb++) {
            int row0 = wm * 32 + mt * 16 + (lane >> 2);
            int col  = wn * 64 + nb * 8 + (lane & 3) * 2;
            #pragma unroll
            for (int h = 0; h < 2; h++) {
                int rr = row0 + h * 8;
                int gi = i0 + rr;
                if (gi >= N_E) continue;
                *(float2*)&g_pacc[half][(size_t)gi * OUT_F + col] =
                    make_float2(acc[mt][nb][2 * h], acc[mt][nb][2 * h + 1]);
            }
        }
    }
    if (tid < MT) g_psr[half][tile * MT + tid] = rsF[tid];
    __threadfence();
    __syncthreads();

    __shared__ int sLast;
    if (tid == 0) sLast = (atomicAdd(&g_cnt[tile], 1) == 1);
    __syncthreads();
    if (!sLast) return;

    int other = half ^ 1;
    if (tid < MT)
        ((float*)(smem + AOF_RS))[tid] = rsF[tid] + g_psr[other][tile * MT + tid];
    __syncthreads();
    const float* rsC = (const float*)(smem + AOF_RS);

    #pragma unroll
    for (int mt = 0; mt < 2; mt++) {
        #pragma unroll
        for (int nb = 0; nb < 8; nb++) {
            int row0 = wm * 32 + mt * 16 + (lane >> 2);
            int col  = wn * 64 + nb * 8 + (lane & 3) * 2;
            #pragma unroll
            for (int h = 0; h < 2; h++) {
                int rr = row0 + h * 8;
                int gi = i0 + rr;
                if (gi >= N_E) continue;
                float2 po = *(const float2*)&g_pacc[other][(size_t)gi * OUT_F + col];
                float v0 = acc[mt][nb][2 * h]     + po.x;
                float v1 = acc[mt][nb][2 * h + 1] + po.y;
                float rs = rsC[rr];
                float nk0, nk1;
                if (rs > 0.f) {
                    float ri = 1.f / rs;
                    nk0 = v0 * ri;
                    nk1 = v1 * ri;
                } else {
                    nk0 = g_colmean[col];
                    nk1 = g_colmean[col + 1];
                }
                __half2 t = __floats2half2_rn(nk0, nk1);
                *(uint32_t*)(g_feath + (size_t)gi * OUT_F + col) = *(uint32_t*)&t;
            }
        }
    }
}

// ---------------- fused kernel: attention split-K + exEh fp16 GEMM tail ----------------
__global__ __launch_bounds__(256, 2) void attn_fused_kernel(const int* __restrict__ adj)
{
    extern __shared__ char smem[];
    if (blockIdx.x < NATTN2) {
        attn_body(smem, (int)(blockIdx.x >> 1), (int)(blockIdx.x & 1), adj);
    } else {
        int g = blockIdx.x - NATTN2;
        hgemm_body(smem, (const bf16*)g_exh, nullptr, (const bf16*)g_ETh, nullptr,
                   (float*)g_exEh, N_E, OUT_F, IN_F, nullptr, 0, nullptr,
                   g & 1, g >> 1, 1);
    }
}

// ---------------- launch ----------------
extern "C" void kernel_launch(void* const* d_in, const int* in_sizes, int n_in,
                              void* d_out, int out_size)
{
    const float* ex   = (const float*)d_in[0];
    const float* kc   = (const float*)d_in[1];
    const int*   adj  = (const int*)d_in[2];
    const float* W1   = (const float*)d_in[3];
    const float* E    = (const float*)d_in[4];
    const float* a    = (const float*)d_in[5];
    const float* rd_w = (const float*)d_in[6];
    const float* rd_b = (const float*)d_in[7];
    float* out = (float*)d_out;

    float* exEh;
    __half *rdwh, *feath;
    cudaGetSymbolAddress((void**)&exEh, g_exEh);
    cudaGetSymbolAddress((void**)&rdwh, g_rdwh);
    cudaGetSymbolAddress((void**)&feath, g_feath);

    cudaFuncSetAttribute(attn_fused_kernel,
                         cudaFuncAttributeMaxDynamicSharedMemorySize, SMEM_ATTN);
    cudaFuncSetAttribute(hgemm_kernel,
                         cudaFuncAttributeMaxDynamicSharedMemorySize, 40960);
    cudaFuncSetAttribute(prep2_kernel,
                         cudaFuncAttributeMaxDynamicSharedMemorySize, 40960);

    // 0. prep + conversions + kc colsum partials + flag reset
    mega_kernel<<<MB_TOT, 256>>>(ex, kc, rd_w, W1, E, a);

    // 1. kcWh gemm (-> g_kcWhT fp16 direct) + rowdots + exp tables + colmean
    prep2_kernel<<<P2_TOT, 256, 40960>>>(ex, kc, W1);

    // 2. fused: attention split-K (314) + exEh fp16 GEMM (158)
    attn_fused_kernel<<<NATTN2 + NGEX, 256, SMEM_ATTN>>>(adj);

    // 3. out = elu([nk | nk*exEh] @ rd_w^T + rd_b), all-fp16 single product
    hgemm_kernel<<<dim3(OUT_F / 128, (N_E + 127) / 128), 256, 40960>>>(
        (const bf16*)feath, nullptr, (const bf16*)rdwh, nullptr,
        out, N_E, OUT_F, 2 * OUT_F, rd_b, 1, exEh, 1);
}

// round 16
// speedup vs baseline: 2.5936x; 1.0645x over previous
#include <cuda_runtime.h>
#include <cuda_bf16.h>
#include <cuda_fp16.h>
#include <math.h>
#include <stdint.h>

#define IN_F   256
#define OUT_F  256
#define N_E    10000
#define N_KC   2000
#define ALPHA  0.2f

#define MT      64
#define KC      32
#define NKC_PAD 2048
#define NCHUNK_RUN 63
#define RSTRIDE 80

#define NGEX    158
#define NATTN   157
#define NATTN2  (2 * NATTN)

typedef __nv_bfloat16 bf16;

// ---------------- scratch ----------------
__device__ __half g_exEhh[N_E * OUT_F];       // fp16 exEh
__device__ float g_v1[IN_F];
__device__ float g_v2[IN_F];
__device__ __half g_kcWhT[OUT_F * NKC_PAD];   // fp16, chunk-blocked transposed
__device__ float g_colmean[OUT_F];
__device__ float g_mkcp[8][IN_F];
__device__ float g_Ae[N_E];
__device__ float g_Ce[N_E];
__device__ float2 g_tab[NKC_PAD];
__device__ __half g_exh[N_E * IN_F];          // fp16 ex
__device__ __half g_ETh[OUT_F * IN_F];        // fp16 E^T [n][k]
__device__ bf16 g_kchi[N_KC * IN_F];
__device__ bf16 g_kclo[N_KC * IN_F];
__device__ bf16 g_W1Thi[OUT_F * IN_F];
__device__ bf16 g_W1Tlo[OUT_F * IN_F];
__device__ __half g_rdwh[OUT_F * 2 * OUT_F];  // fp16 rd_w [n=256][k=512]
__device__ __half g_feath[N_E * OUT_F];       // fp16 new_kc
// split-K partials
__device__ float g_pacc[2][N_E * OUT_F];
__device__ float g_psr[2][NATTN * MT];
__device__ int   g_cnt[NATTN];

// ---------------- helpers ----------------
static __device__ __forceinline__ uint32_t smem_u32(const void* p) {
    uint32_t a;
    asm("{ .reg .u64 t; cvta.to.shared.u64 t, %1; cvt.u32.u64 %0, t; }" : "=r"(a) : "l"(p));
    return a;
}
#define LDSM_X4(R0,R1,R2,R3,ADDR) \
    asm volatile("ldmatrix.sync.aligned.m8n8.x4.shared.b16 {%0,%1,%2,%3}, [%4];" \
                 : "=r"(R0),"=r"(R1),"=r"(R2),"=r"(R3) : "r"(ADDR))
#define CP_ASYNC16(dst, src) \
    asm volatile("cp.async.ca.shared.global [%0], [%1], 16;" :: "r"(dst), "l"(src))
#define CP_COMMIT() asm volatile("cp.async.commit_group;" ::: "memory")
#define CP_WAIT0()  asm volatile("cp.async.wait_group 0;" ::: "memory")

static __device__ __forceinline__ void mma_bf16(float* c, const uint32_t* a, const uint32_t* b) {
    asm volatile(
        "mma.sync.aligned.m16n8k16.row.col.f32.bf16.bf16.f32 "
        "{%0,%1,%2,%3}, {%4,%5,%6,%7}, {%8,%9}, {%0,%1,%2,%3};"
        : "+f"(c[0]), "+f"(c[1]), "+f"(c[2]), "+f"(c[3])
        : "r"(a[0]), "r"(a[1]), "r"(a[2]), "r"(a[3]), "r"(b[0]), "r"(b[1]));
}
static __device__ __forceinline__ void mma_fp16(float* c, const uint32_t* a, const uint32_t* b) {
    asm volatile(
        "mma.sync.aligned.m16n8k16.row.col.f32.f16.f16.f32 "
        "{%0,%1,%2,%3}, {%4,%5,%6,%7}, {%8,%9}, {%0,%1,%2,%3};"
        : "+f"(c[0]), "+f"(c[1]), "+f"(c[2]), "+f"(c[3])
        : "r"(a[0]), "r"(a[1]), "r"(a[2]), "r"(a[3]), "r"(b[0]), "r"(b[1]));
}
static __device__ __forceinline__ void fsplit(float v, bf16& h, bf16& l) {
    h = __float2bfloat16(v);
    l = __float2bfloat16(v - __bfloat162float(h));
}
static __device__ __forceinline__ uint32_t pack2(bf16 a, bf16 b) {
    __nv_bfloat162 t = __halves2bfloat162(a, b);
    return *(uint32_t*)&t;
}
static __device__ __forceinline__ void split4_store(const float4 v, bf16* hi, bf16* lo) {
    bf16 h0, l0, h1, l1, h2, l2, h3, l3;
    fsplit(v.x, h0, l0); fsplit(v.y, h1, l1);
    fsplit(v.z, h2, l2); fsplit(v.w, h3, l3);
    *(uint32_t*)(hi)     = pack2(h0, h1);
    *(uint32_t*)(hi + 2) = pack2(h2, h3);
    *(uint32_t*)(lo)     = pack2(l0, l1);
    *(uint32_t*)(lo + 2) = pack2(l2, l3);
}
static __device__ __forceinline__ void half4_store(const float4 v, __half* dst) {
    __half2 a0 = __floats2half2_rn(v.x, v.y);
    __half2 a1 = __floats2half2_rn(v.z, v.w);
    *(uint32_t*)(dst)     = *(uint32_t*)&a0;
    *(uint32_t*)(dst + 2) = *(uint32_t*)&a1;
}

// ---------------- mega kernel ----------------
#define MB_EX   1
#define MB_KC   2501
#define MB_RDW  3001
#define MB_TW1  3129
#define MB_TE   3193
#define MB_MKC  3257
#define MB_TOT  3265
__global__ void mega_kernel(const float* __restrict__ ex, const float* __restrict__ kc,
                            const float* __restrict__ rdw, const float* __restrict__ W1,
                            const float* __restrict__ E, const float* __restrict__ a)
{
    int b = blockIdx.x, tid = threadIdx.x;
    if (b < MB_EX) {
        int k = tid;
        float s1 = 0.f, s2 = 0.f;
        #pragma unroll 8
        for (int j = 0; j < OUT_F; j++) {
            float w = W1[k * OUT_F + j];
            s1 += w * a[j];
            s2 += w * a[OUT_F + j];
        }
        g_v1[k] = s1;
        g_v2[k] = s2;
        if (tid < NATTN) g_cnt[tid] = 0;
    } else if (b < MB_KC) {
        size_t i = ((size_t)(b - MB_EX) * 256 + tid) * 4;
        half4_store(*(const float4*)(ex + i), g_exh + i);
    } else if (b < MB_RDW) {
        size_t i = ((size_t)(b - MB_KC) * 256 + tid) * 4;
        split4_store(*(const float4*)(kc + i), g_kchi + i, g_kclo + i);
    } else if (b < MB_TW1) {
        size_t i = ((size_t)(b - MB_RDW) * 256 + tid) * 4;
        half4_store(*(const float4*)(rdw + i), g_rdwh + i);
    } else if (b < MB_TE) {
        int bb = b - MB_TW1;
        __shared__ float t[32][33];
        int kb = (bb & 7) * 32, nb = (bb >> 3) * 32;
        int tx = tid & 31, ty = tid >> 5;
        #pragma unroll
        for (int rr = 0; rr < 32; rr += 8)
            t[ty + rr][tx] = W1[(size_t)(kb + ty + rr) * OUT_F + nb + tx];
        __syncthreads();
        #pragma unroll
        for (int rr = 0; rr < 32; rr += 8) {
            int n = nb + ty + rr;
            bf16 h, l;
            fsplit(t[tx][ty + rr], h, l);
            g_W1Thi[(size_t)n * IN_F + kb + tx] = h;
            g_W1Tlo[(size_t)n * IN_F + kb + tx] = l;
        }
    } else if (b < MB_MKC) {
        int bb = b - MB_TE;
        __shared__ float t[32][33];
        int kb = (bb & 7) * 32, nb = (bb >> 3) * 32;
        int tx = tid & 31, ty = tid >> 5;
        #pragma unroll
        for (int rr = 0; rr < 32; rr += 8)
            t[ty + rr][tx] = E[(size_t)(kb + ty + rr) * OUT_F + nb + tx];
        __syncthreads();
        #pragma unroll
        for (int rr = 0; rr < 32; rr += 8) {
            int n = nb + ty + rr;
            g_ETh[(size_t)n * IN_F + kb + tx] = __float2half_rn(t[tx][ty + rr]);
        }
    } else {
        int p = b - MB_MKC;
        float s = 0.f;
        for (int j = p * 250; j < (p + 1) * 250; j++)
            s += kc[(size_t)j * IN_F + tid];
        g_mkcp[p][tid] = s;
    }
}

// ---------------- hgemm body ----------------
// use16==0: bf16 hi/lo 3-product. use16==1: fp16 single product.
// epi: 0 plain fp32; 2 -> g_kcWhT transposed fp16; 3 -> fp16 C write.
#define HOF_AH 0
#define HOF_AL 10240
#define HOF_BH 20480
#define HOF_BL 30720
static __device__ __forceinline__ void hgemm_body(char* smem,
    const bf16* __restrict__ Ahi, const bf16* __restrict__ Alo,
    const bf16* __restrict__ Bhi, const bf16* __restrict__ Blo,
    float* __restrict__ C, int M, int N, int K,
    int epi, int bx, int by, int use16)
{
    uint32_t sb = smem_u32(smem);
    int tid = threadIdx.x, lane = tid & 31, wid = tid >> 5;
    int bm = by * 128, bn = bx * 128;
    int wm = wid >> 1, wn = wid & 1;

    float acc[2][8][4];
    #pragma unroll
    for (int mt = 0; mt < 2; mt++)
        #pragma unroll
        for (int nb = 0; nb < 8; nb++)
            #pragma unroll
            for (int k = 0; k < 4; k++) acc[mt][nb][k] = 0.f;

    int crow = tid >> 1, chalf = tid & 1;
    bool arow_ok = (bm + crow) < M;
    const uint4 zero4 = make_uint4(0, 0, 0, 0);

    for (int k0 = 0; k0 < K; k0 += 32) {
        {
            char* dh = smem + HOF_AH + crow * RSTRIDE + chalf * 32;
            char* dl = smem + HOF_AL + crow * RSTRIDE + chalf * 32;
            if (!arow_ok) {
                ((uint4*)dh)[0] = zero4; ((uint4*)dh)[1] = zero4;
                if (!use16) { ((uint4*)dl)[0] = zero4; ((uint4*)dl)[1] = zero4; }
            } else {
                const uint4* sh = (const uint4*)(Ahi + (size_t)(bm + crow) * K + k0 + chalf * 16);
                ((uint4*)dh)[0] = sh[0]; ((uint4*)dh)[1] = sh[1];
                if (!use16) {
                    const uint4* sl = (const uint4*)(Alo + (size_t)(bm + crow) * K + k0 + chalf * 16);
                    ((uint4*)dl)[0] = sl[0]; ((uint4*)dl)[1] = sl[1];
                }
            }
        }
        {
            const uint4* sh = (const uint4*)(Bhi + (size_t)(bn + crow) * K + k0 + chalf * 16);
            char* dh = smem + HOF_BH + crow * RSTRIDE + chalf * 32;
            ((uint4*)dh)[0] = sh[0]; ((uint4*)dh)[1] = sh[1];
            if (!use16) {
                const uint4* sl = (const uint4*)(Blo + (size_t)(bn + crow) * K + k0 + chalf * 16);
                char* dl = smem + HOF_BL + crow * RSTRIDE + chalf * 32;
                ((uint4*)dl)[0] = sl[0]; ((uint4*)dl)[1] = sl[1];
            }
        }
        __syncthreads();

        #pragma unroll
        for (int ks = 0; ks < 2; ks++) {
            uint32_t ahi[2][4], alo[2][4], bfrag[8][2];
            int arowi = lane & 15;
            int akoff = (ks * 16 + ((lane >> 4) & 1) * 8) * 2;
            #pragma unroll
            for (int mt = 0; mt < 2; mt++) {
                uint32_t ad = sb + HOF_AH + (wm * 32 + mt * 16 + arowi) * RSTRIDE + akoff;
                LDSM_X4(ahi[mt][0], ahi[mt][1], ahi[mt][2], ahi[mt][3], ad);
                if (!use16) {
                    ad += (HOF_AL - HOF_AH);
                    LDSM_X4(alo[mt][0], alo[mt][1], alo[mt][2], alo[mt][3], ad);
                }
            }
            int bnrow = (lane & 7) + ((lane >> 4) << 3);
            int bkoff = (ks * 16 + ((lane >> 3) & 1) * 8) * 2;
            #pragma unroll
            for (int nq = 0; nq < 4; nq++) {
                uint32_t bd = sb + HOF_BH + (wn * 64 + nq * 16 + bnrow) * RSTRIDE + bkoff;
                LDSM_X4(bfrag[2 * nq][0], bfrag[2 * nq][1],
                        bfrag[2 * nq + 1][0], bfrag[2 * nq + 1][1], bd);
            }
            if (use16) {
                #pragma unroll
                for (int mt = 0; mt < 2; mt++)
                    #pragma unroll
                    for (int nb = 0; nb < 8; nb++)
                        mma_fp16(acc[mt][nb], ahi[mt], bfrag[nb]);
            } else {
                #pragma unroll
                for (int mt = 0; mt < 2; mt++)
                    #pragma unroll
                    for (int nb = 0; nb < 8; nb++)
                        mma_bf16(acc[mt][nb], ahi[mt], bfrag[nb]);
                #pragma unroll
                for (int mt = 0; mt < 2; mt++)
                    #pragma unroll
                    for (int nb = 0; nb < 8; nb++)
                        mma_bf16(acc[mt][nb], alo[mt], bfrag[nb]);
                #pragma unroll
                for (int nq = 0; nq < 4; nq++) {
                    uint32_t bd = sb + HOF_BL + (wn * 64 + nq * 16 + bnrow) * RSTRIDE + bkoff;
                    LDSM_X4(bfrag[2 * nq][0], bfrag[2 * nq][1],
                            bfrag[2 * nq + 1][0], bfrag[2 * nq + 1][1], bd);
                }
                #pragma unroll
                for (int mt = 0; mt < 2; mt++)
                    #pragma unroll
                    for (int nb = 0; nb < 8; nb++)
                        mma_bf16(acc[mt][nb], ahi[mt], bfrag[nb]);
            }
        }
        __syncthreads();
    }

    #pragma unroll
    for (int mt = 0; mt < 2; mt++) {
        #pragma unroll
        for (int nb = 0; nb < 8; nb++) {
            int row0 = wm * 32 + mt * 16 + (lane >> 2);
            int col = bn + wn * 64 + nb * 8 + (lane & 3) * 2;
            #pragma unroll
            for (int h = 0; h < 2; h++) {
                int r = bm + row0 + h * 8;
                float v0 = acc[mt][nb][2 * h];
                float v1 = acc[mt][nb][2 * h + 1];
                if (epi == 2) {
                    size_t base = ((size_t)(r >> 5) * 256);
                    g_kcWhT[(base + col)     * KC + (r & 31)] = __float2half_rn(v0);
                    g_kcWhT[(base + col + 1) * KC + (r & 31)] = __float2half_rn(v1);
                    continue;
                }
                if (r >= M) continue;
                if (epi == 3) {
                    __half2 t = __floats2half2_rn(v0, v1);
                    *(uint32_t*)((__half*)C + (size_t)r * N + col) = *(uint32_t*)&t;
                } else {
                    C[(size_t)r * N + col]     = v0;
                    C[(size_t)r * N + col + 1] = v1;
                }
            }
        }
    }
}

// ---------------- fgemm64: final GEMM, 64x128 tiles, fp16 single product ----------------
// out = elu([nk | nk*exEh] @ rd_w^T + rd_b). A virtual: k<256 -> feath; k>=256 -> feath*exEhh.
#define G64_A 0
#define G64_B 5120
#define G64_SMEM 15360
__global__ __launch_bounds__(256, 3) void fgemm64_kernel(const float* __restrict__ bias,
                                                         float* __restrict__ out)
{
    __shared__ char smem[G64_SMEM];
    uint32_t sb = smem_u32(smem);
    int tid = threadIdx.x, lane = tid & 31, wid = tid >> 5;
    int bm = blockIdx.y * 64, bn = blockIdx.x * 128;
    int wm = wid & 1, wn = wid >> 1;

    float acc[2][4][4];
    #pragma unroll
    for (int mt = 0; mt < 2; mt++)
        #pragma unroll
        for (int nb = 0; nb < 4; nb++)
            #pragma unroll
            for (int k = 0; k < 4; k++) acc[mt][nb][k] = 0.f;

    int arow_c = tid >> 2, aq = tid & 3;   // A: 4 threads/row x 16B
    int brow_c = tid >> 1, bq = tid & 1;   // B: 2 threads/row x 32B
    bool arow_ok = (bm + arow_c) < N_E;
    const uint4 zero4 = make_uint4(0, 0, 0, 0);

    for (int k0 = 0; k0 < 2 * OUT_F; k0 += 32) {
        {
            char* d = smem + G64_A + arow_c * RSTRIDE + aq * 16;
            if (!arow_ok) {
                *(uint4*)d = zero4;
            } else if (k0 < 256) {
                *(uint4*)d = *(const uint4*)(g_feath + (size_t)(bm + arow_c) * 256 + k0 + aq * 8);
            } else {
                size_t rb = (size_t)(bm + arow_c) * 256 + (k0 - 256) + aq * 8;
                uint4 vh = *(const uint4*)(g_feath + rb);
                uint4 vx = *(const uint4*)(g_exEhh + rb);
                const __half* ph = (const __half*)&vh;
                const __half* px = (const __half*)&vx;
                uint32_t o[4];
                #pragma unroll
                for (int e = 0; e < 4; e++) {
                    float q0 = __half2float(ph[2*e])   * __half2float(px[2*e]);
                    float q1 = __half2float(ph[2*e+1]) * __half2float(px[2*e+1]);
                    __half2 t = __floats2half2_rn(q0, q1);
                    o[e] = *(uint32_t*)&t;
                }
                *(uint4*)d = *(uint4*)o;
            }
        }
        {
            const uint4* s4 = (const uint4*)(g_rdwh + (size_t)(bn + brow_c) * (2 * OUT_F) + k0 + bq * 16);
            char* d = smem + G64_B + brow_c * RSTRIDE + bq * 32;
            ((uint4*)d)[0] = s4[0];
            ((uint4*)d)[1] = s4[1];
        }
        __syncthreads();

        #pragma unroll
        for (int ks = 0; ks < 2; ks++) {
            uint32_t af[2][4], bfrag[4][2];
            int arowi = lane & 15;
            int akoff = (ks * 16 + ((lane >> 4) & 1) * 8) * 2;
            #pragma unroll
            for (int mt = 0; mt < 2; mt++) {
                uint32_t ad = sb + G64_A + (wm * 32 + mt * 16 + arowi) * RSTRIDE + akoff;
                LDSM_X4(af[mt][0], af[mt][1], af[mt][2], af[mt][3], ad);
            }
            int bnrow = (lane & 7) + ((lane >> 4) << 3);
            int bkoff = (ks * 16 + ((lane >> 3) & 1) * 8) * 2;
            #pragma unroll
            for (int nq = 0; nq < 2; nq++) {
                uint32_t bd = sb + G64_B + (wn * 32 + nq * 16 + bnrow) * RSTRIDE + bkoff;
                LDSM_X4(bfrag[2 * nq][0], bfrag[2 * nq][1],
                        bfrag[2 * nq + 1][0], bfrag[2 * nq + 1][1], bd);
            }
            #pragma unroll
            for (int mt = 0; mt < 2; mt++)
                #pragma unroll
                for (int nb = 0; nb < 4; nb++)
                    mma_fp16(acc[mt][nb], af[mt], bfrag[nb]);
        }
        __syncthreads();
    }

    #pragma unroll
    for (int mt = 0; mt < 2; mt++) {
        #pragma unroll
        for (int nb = 0; nb < 4; nb++) {
            int row0 = wm * 32 + mt * 16 + (lane >> 2);
            int col = bn + wn * 32 + nb * 8 + (lane & 3) * 2;
            #pragma unroll
            for (int h = 0; h < 2; h++) {
                int r = bm + row0 + h * 8;
                if (r >= N_E) continue;
                float v0 = acc[mt][nb][2 * h] + bias[col];
                float v1 = acc[mt][nb][2 * h + 1] + bias[col + 1];
                v0 = v0 > 0.f ? v0 : expm1f(v0);
                v1 = v1 > 0.f ? v1 : expm1f(v1);
                out[(size_t)r * OUT_F + col]     = v0;
                out[(size_t)r * OUT_F + col + 1] = v1;
            }
        }
    }
}

// ---------------- prep2: kcWh gemm (-> g_kcWhT) + rowdots + colmean ----------------
#define P2_GEMM 32
#define P2_E2   1282
#define P2_CM   1538
#define P2_TOT  1539
__global__ __launch_bounds__(256, 2) void prep2_kernel(
    const float* __restrict__ ex, const float* __restrict__ kc,
    const float* __restrict__ W1)
{
    extern __shared__ char smem[];
    int b = blockIdx.x, tid = threadIdx.x;
    int lane = tid & 31, warp = tid >> 5;
    if (b < P2_GEMM) {
        hgemm_body(smem, g_kchi, g_kclo, g_W1Thi, g_W1Tlo, nullptr,
                   N_KC, OUT_F, IN_F, 2, b & 1, b >> 1, 0);
    } else if (b < P2_E2) {
        int i = (b - P2_GEMM) * 8 + warp;
        if (i >= N_E) return;
        const float* row = ex + (size_t)i * IN_F;
        float s = 0.f;
        #pragma unroll
        for (int k = lane; k < IN_F; k += 32) s += row[k] * g_v1[k];
        #pragma unroll
        for (int o = 16; o; o >>= 1) s += __shfl_xor_sync(0xFFFFFFFFu, s, o);
        if (lane == 0) {
            g_Ae[i] = __expf(s);
            g_Ce[i] = __expf(ALPHA * s);
        }
    } else if (b < P2_CM) {
        int j = (b - P2_E2) * 8 + warp;
        if (j >= NKC_PAD) return;
        if (j < N_KC) {
            const float* row = kc + (size_t)j * IN_F;
            float s = 0.f;
            #pragma unroll
            for (int k = lane; k < IN_F; k += 32) s += row[k] * g_v2[k];
            #pragma unroll
            for (int o = 16; o; o >>= 1) s += __shfl_xor_sync(0xFFFFFFFFu, s, o);
            if (lane == 0)
                g_tab[j] = make_float2(__expf(s), __expf(ALPHA * s));
        } else if (lane == 0) {
            g_tab[j] = make_float2(0.f, 0.f);
        }
    } else {
        __shared__ float S[IN_F];
        float s = 0.f;
        #pragma unroll
        for (int p = 0; p < 8; p++) s += g_mkcp[p][tid];
        S[tid] = s;
        __syncthreads();
        float c = 0.f;
        #pragma unroll 8
        for (int k = 0; k < IN_F; k++)
            c += S[k] * W1[(size_t)k * OUT_F + tid];
        g_colmean[tid] = c * (1.0f / N_KC);
    }
}

// ---------------- attention body: single fp16 product, split-K, cp.async ----------------
#define AOF_B    0
#define AOF_BSZ  20480
#define AOF_A    40960
#define AOF_ASZ  5120
#define AOF_AE   51200
#define AOF_CE   51456
#define AOF_RS   51712
#define AOF_RSF  52736
#define SMEM_ATTN 53248

static __device__ __forceinline__ void cp_b_chunk(uint32_t sbB, int c, int tid)
{
    const __half* sh = g_kcWhT + ((size_t)c * 256 + tid) * KC;
    uint32_t dh = sbB + tid * RSTRIDE;
    #pragma unroll
    for (int t = 0; t < 4; t++)
        CP_ASYNC16(dh + t * 16, (const char*)sh + t * 16);
    CP_COMMIT();
}

static __device__ __forceinline__ void attn_body(char* smem, int tile, int half,
    const int* __restrict__ adj)
{
    uint32_t sb = smem_u32(smem);
    float* Aes = (float*)(smem + AOF_AE);
    float* Ces = (float*)(smem + AOF_CE);

    int tid = threadIdx.x, lane = tid & 31, wid = tid >> 5;
    int i0 = tile * MT;
    int c0 = half ? 32 : 0;
    int c1 = half ? NCHUNK_RUN : 32;

    cp_b_chunk(sb + AOF_B, c0, tid);

    if (tid < MT) {
        int gi = i0 + tid;
        bool v = gi < N_E;
        Aes[tid] = v ? g_Ae[gi] : 0.f;
        Ces[tid] = v ? g_Ce[gi] : 0.f;
    }
    __syncthreads();

    int r = tid >> 2, jl0 = (tid & 3) * 8;
    int gi_r = i0 + r;
    const int* arow = adj + (size_t)(gi_r < N_E ? gi_r : 0) * N_KC;
    float Ai = Aes[r], Ci = Ces[r];
    float srow = 0.f;

    int wm = wid & 1, wn = wid >> 1;
    float acc[2][8][4];
    #pragma unroll
    for (int mt = 0; mt < 2; mt++)
        #pragma unroll
        for (int nb = 0; nb < 8; nb++)
            #pragma unroll
            for (int k = 0; k < 4; k++) acc[mt][nb][k] = 0.f;

    for (int c = c0; c < c1; c++) {
        int buf = (c - c0) & 1;
        int j0 = c * KC;
        uint32_t aBase = sb + AOF_A + buf * AOF_ASZ;

        {
            float p[8];
            if (j0 + KC <= N_KC) {
                const int4* ap = (const int4*)(arow + j0 + jl0);
                int4 a0 = ap[0], a1 = ap[1];
                int am[8] = {a0.x, a0.y, a0.z, a0.w, a1.x, a1.y, a1.z, a1.w};
                #pragma unroll
                for (int e = 0; e < 8; e++) {
                    float2 t = __ldg(&g_tab[j0 + jl0 + e]);
                    float pv = Ai * t.x;
                    float v = (pv > 1.f) ? pv : Ci * t.y;
                    p[e] = (am[e] > 0) ? v : 0.f;
                }
            } else {
                #pragma unroll
                for (int e = 0; e < 8; e++) {
                    int j = j0 + jl0 + e;
                    int m = (j < N_KC) ? arow[j] : 0;
                    float2 t = __ldg(&g_tab[(j < N_KC) ? j : 0]);
                    float pv = Ai * t.x;
                    float v = (pv > 1.f) ? pv : Ci * t.y;
                    p[e] = (m > 0) ? v : 0.f;
                }
            }
            #pragma unroll
            for (int e = 0; e < 8; e++) srow += p[e];
            __half2 q0 = __floats2half2_rn(p[0], p[1]);
            __half2 q1 = __floats2half2_rn(p[2], p[3]);
            __half2 q2 = __floats2half2_rn(p[4], p[5]);
            __half2 q3 = __floats2half2_rn(p[6], p[7]);
            uint4 w = make_uint4(*(uint32_t*)&q0, *(uint32_t*)&q1,
                                 *(uint32_t*)&q2, *(uint32_t*)&q3);
            *(uint4*)(smem + AOF_A + buf * AOF_ASZ + r * RSTRIDE + jl0 * 2) = w;
        }

        CP_WAIT0();
        __syncthreads();

        if (c + 1 < c1)
            cp_b_chunk(sb + AOF_B + (buf ^ 1) * AOF_BSZ, c + 1, tid);

        uint32_t bBase = sb + AOF_B + buf * AOF_BSZ;
        #pragma unroll
        for (int ks = 0; ks < 2; ks++) {
            uint32_t af[2][4], bfrag[8][2];
            int arowi = lane & 15;
            int akoff = (ks * 16 + ((lane >> 4) & 1) * 8) * 2;
            #pragma unroll
            for (int mt = 0; mt < 2; mt++) {
                uint32_t ad = aBase + (wm * 32 + mt * 16 + arowi) * RSTRIDE + akoff;
                LDSM_X4(af[mt][0], af[mt][1], af[mt][2], af[mt][3], ad);
            }
            int bnrow = (lane & 7) + ((lane >> 4) << 3);
            int bkoff = (ks * 16 + ((lane >> 3) & 1) * 8) * 2;
            #pragma unroll
            for (int nq = 0; nq < 4; nq++) {
                uint32_t bd = bBase + (wn * 64 + nq * 16 + bnrow) * RSTRIDE + bkoff;
                LDSM_X4(bfrag[2 * nq][0], bfrag[2 * nq][1],
                        bfrag[2 * nq + 1][0], bfrag[2 * nq + 1][1], bd);
            }
            #pragma unroll
            for (int mt = 0; mt < 2; mt++)
                #pragma unroll
                for (int nb = 0; nb < 8; nb++)
                    mma_fp16(acc[mt][nb], af[mt], bfrag[nb]);
        }
    }

    __syncthreads();
    ((float*)(smem + AOF_RS))[tid] = srow;
    __syncthreads();
    if (tid < MT) {
        const float* r4 = (const float*)(smem + AOF_RS) + tid * 4;
        ((float*)(smem + AOF_RSF))[tid] = (r4[0] + r4[1]) + (r4[2] + r4[3]);
    }
    __syncthreads();
    const float* rsF = (const float*)(smem + AOF_RSF);

    #pragma unroll
    for (int mt = 0; mt < 2; mt++) {
        #pragma unroll
        for (int nb = 0; nb < 8; nb++) {
            int row0 = wm * 32 + mt * 16 + (lane >> 2);
            int col  = wn * 64 + nb * 8 + (lane & 3) * 2;
            #pragma unroll
            for (int h = 0; h < 2; h++) {
                int rr = row0 + h * 8;
                int gi = i0 + rr;
                if (gi >= N_E) continue;
                *(float2*)&g_pacc[half][(size_t)gi * OUT_F + col] =
                    make_float2(acc[mt][nb][2 * h], acc[mt][nb][2 * h + 1]);
            }
        }
    }
    if (tid < MT) g_psr[half][tile * MT + tid] = rsF[tid];
    __threadfence();
    __syncthreads();

    __shared__ int sLast;
    if (tid == 0) sLast = (atomicAdd(&g_cnt[tile], 1) == 1);
    __syncthreads();
    if (!sLast) return;

    int other = half ^ 1;
    if (tid < MT)
        ((float*)(smem + AOF_RS))[tid] = rsF[tid] + g_psr[other][tile * MT + tid];
    __syncthreads();
    const float* rsC = (const float*)(smem + AOF_RS);

    #pragma unroll
    for (int mt = 0; mt < 2; mt++) {
        #pragma unroll
        for (int nb = 0; nb < 8; nb++) {
            int row0 = wm * 32 + mt * 16 + (lane >> 2);
            int col  = wn * 64 + nb * 8 + (lane & 3) * 2;
            #pragma unroll
            for (int h = 0; h < 2; h++) {
                int rr = row0 + h * 8;
                int gi = i0 + rr;
                if (gi >= N_E) continue;
                float2 po = *(const float2*)&g_pacc[other][(size_t)gi * OUT_F + col];
                float v0 = acc[mt][nb][2 * h]     + po.x;
                float v1 = acc[mt][nb][2 * h + 1] + po.y;
                float rs = rsC[rr];
                float nk0, nk1;
                if (rs > 0.f) {
                    float ri = 1.f / rs;
                    nk0 = v0 * ri;
                    nk1 = v1 * ri;
                } else {
                    nk0 = g_colmean[col];
                    nk1 = g_colmean[col + 1];
                }
                __half2 t = __floats2half2_rn(nk0, nk1);
                *(uint32_t*)(g_feath + (size_t)gi * OUT_F + col) = *(uint32_t*)&t;
            }
        }
    }
}

// ---------------- fused kernel: attention split-K + exEh fp16 GEMM tail ----------------
__global__ __launch_bounds__(256, 2) void attn_fused_kernel(const int* __restrict__ adj)
{
    extern __shared__ char smem[];
    if (blockIdx.x < NATTN2) {
        attn_body(smem, (int)(blockIdx.x >> 1), (int)(blockIdx.x & 1), adj);
    } else {
        int g = blockIdx.x - NATTN2;
        hgemm_body(smem, (const bf16*)g_exh, nullptr, (const bf16*)g_ETh, nullptr,
                   (float*)g_exEhh, N_E, OUT_F, IN_F, 3, g & 1, g >> 1, 1);
    }
}

// ---------------- launch ----------------
extern "C" void kernel_launch(void* const* d_in, const int* in_sizes, int n_in,
                              void* d_out, int out_size)
{
    const float* ex   = (const float*)d_in[0];
    const float* kc   = (const float*)d_in[1];
    const int*   adj  = (const int*)d_in[2];
    const float* W1   = (const float*)d_in[3];
    const float* E    = (const float*)d_in[4];
    const float* a    = (const float*)d_in[5];
    const float* rd_w = (const float*)d_in[6];
    const float* rd_b = (const float*)d_in[7];
    float* out = (float*)d_out;

    cudaFuncSetAttribute(attn_fused_kernel,
                         cudaFuncAttributeMaxDynamicSharedMemorySize, SMEM_ATTN);
    cudaFuncSetAttribute(prep2_kernel,
                         cudaFuncAttributeMaxDynamicSharedMemorySize, 40960);

    // 0. prep + conversions + kc colsum partials + flag reset
    mega_kernel<<<MB_TOT, 256>>>(ex, kc, rd_w, W1, E, a);

    // 1. kcWh gemm (-> g_kcWhT fp16 direct) + rowdots + exp tables + colmean
    prep2_kernel<<<P2_TOT, 256, 40960>>>(ex, kc, W1);

    // 2. fused: attention split-K (314) + exEh fp16 GEMM (158)
    attn_fused_kernel<<<NATTN2 + NGEX, 256, SMEM_ATTN>>>(adj);

    // 3. out = elu([nk | nk*exEh] @ rd_w^T + rd_b), 64x128 tiles, fp16
    fgemm64_kernel<<<dim3(2, (N_E + 63) / 64), 256>>>(rd_b, out);
}